// round 8
// baseline (speedup 1.0000x reference)
#include <cuda_runtime.h>
#include <cuda_bf16.h>
#include <math.h>
#include <stdint.h>

#define SEQ     2048
#define HIDDEN  1024
#define NH      16
#define HD      64
#define NL      8
#define VOCABSZ 50272
#define FFN     4096
#define EPSV    1e-5f

// weight element offsets (int8 planes)
#define OFF_WQKV 0ULL
#define OFF_WO   25165824ULL
#define OFF_W1   33554432ULL
#define OFF_W2   67108864ULL
#define OFF_LM   100663296ULL
#define W_TOTAL  152141824ULL
// weight scale row offsets
#define SOFF_QKV 0
#define SOFF_WO  24576
#define SOFF_W1  32768
#define SOFF_W2  65536
#define SOFF_LM  73728
#define S_TOTAL  124000

// ---------------- scratch ----------------
__device__ float g_x  [(size_t)SEQ * HIDDEN];
__device__ float g_qkv[(size_t)SEQ * 3 * HIDDEN];
__device__ float g_att[(size_t)SEQ * HIDDEN];
__device__ float g_mid[(size_t)SEQ * FFN];
__device__ float g_cos[(size_t)SEQ * (HD / 2)];
__device__ float g_sin[(size_t)SEQ * (HD / 2)];
__device__ __nv_bfloat16 g_sh[(size_t)SEQ * 3 * HIDDEN], g_sl[(size_t)SEQ * 3 * HIDDEN];
__device__ int8_t g_w1p[W_TOTAL];
__device__ int8_t g_w2p[W_TOTAL];
__device__ float  g_swt[S_TOTAL];
__device__ int8_t g_aq1[(size_t)SEQ * FFN];
__device__ int8_t g_aq2[(size_t)SEQ * FFN];
__device__ float  g_sa[SEQ];

// ---------------- helpers ----------------
__device__ __forceinline__ uint32_t smem_u32(const void* p) {
    uint32_t a;
    asm("{ .reg .u64 t; cvta.to.shared.u64 t, %1; cvt.u32.u64 %0, t; }" : "=r"(a) : "l"(p));
    return a;
}
__device__ __forceinline__ float warpSum(float v) {
    #pragma unroll
    for (int o = 16; o; o >>= 1) v += __shfl_xor_sync(0xffffffffu, v, o);
    return v;
}
__device__ __forceinline__ float warpMax(float v) {
    #pragma unroll
    for (int o = 16; o; o >>= 1) v = fmaxf(v, __shfl_xor_sync(0xffffffffu, v, o));
    return v;
}
__device__ __forceinline__ float blockReduceSum(float v, float* red) {
    int lane = threadIdx.x & 31, w = threadIdx.x >> 5;
    v = warpSum(v);
    if (lane == 0) red[w] = v;
    __syncthreads();
    if (w == 0) {
        float r = (lane < (int)(blockDim.x >> 5)) ? red[lane] : 0.0f;
        r = warpSum(r);
        if (lane == 0) red[0] = r;
    }
    __syncthreads();
    float out = red[0];
    __syncthreads();
    return out;
}
__device__ __forceinline__ float blockReduceMax(float v, float* red) {
    int lane = threadIdx.x & 31, w = threadIdx.x >> 5;
    v = warpMax(v);
    if (lane == 0) red[w] = v;
    __syncthreads();
    if (w == 0) {
        float r = (lane < (int)(blockDim.x >> 5)) ? red[lane] : 0.0f;
        r = warpMax(r);
        if (lane == 0) red[0] = r;
    }
    __syncthreads();
    float out = red[0];
    __syncthreads();
    return out;
}
__device__ __forceinline__ void mma_bf16(float* c, const uint32_t* a, const uint32_t* b) {
    asm volatile(
        "mma.sync.aligned.m16n8k16.row.col.f32.bf16.bf16.f32 "
        "{%0,%1,%2,%3}, {%4,%5,%6,%7}, {%8,%9}, {%0,%1,%2,%3};"
        : "+f"(c[0]), "+f"(c[1]), "+f"(c[2]), "+f"(c[3])
        : "r"(a[0]), "r"(a[1]), "r"(a[2]), "r"(a[3]), "r"(b[0]), "r"(b[1]));
}
__device__ __forceinline__ void mma_s8(int* c, const uint32_t* a, uint32_t b0, uint32_t b1) {
    asm volatile(
        "mma.sync.aligned.m16n8k32.row.col.s32.s8.s8.s32 "
        "{%0,%1,%2,%3}, {%4,%5,%6,%7}, {%8,%9}, {%0,%1,%2,%3};"
        : "+r"(c[0]), "+r"(c[1]), "+r"(c[2]), "+r"(c[3])
        : "r"(a[0]), "r"(a[1]), "r"(a[2]), "r"(a[3]), "r"(b0), "r"(b1));
}
__device__ __forceinline__ void ldmx4(uint32_t* d, uint32_t addr) {
    asm volatile("ldmatrix.sync.aligned.m8n8.x4.shared.b16 {%0,%1,%2,%3}, [%4];"
                 : "=r"(d[0]), "=r"(d[1]), "=r"(d[2]), "=r"(d[3]) : "r"(addr));
}
__device__ __forceinline__ void ldmx4t(uint32_t* d, uint32_t addr) {
    asm volatile("ldmatrix.sync.aligned.m8n8.x4.trans.shared.b16 {%0,%1,%2,%3}, [%4];"
                 : "=r"(d[0]), "=r"(d[1]), "=r"(d[2]), "=r"(d[3]) : "r"(addr));
}
__device__ __forceinline__ void cpa16(uint32_t s, const void* g, int srcsz) {
    asm volatile("cp.async.cg.shared.global [%0], [%1], 16, %2;"
                 :: "r"(s), "l"(g), "r"(srcsz) : "memory");
}
__device__ __forceinline__ void cpa_commit() {
    asm volatile("cp.async.commit_group;" ::: "memory");
}
__device__ __forceinline__ void cpa_wait0() {
    asm volatile("cp.async.wait_group 0;" ::: "memory");
}

// ---------------- row quantization: fp32 row -> 2x int8 planes + scale ----------------
// one block per row; K in {1024, 4096}
__global__ void quant_rows_kernel(const float* __restrict__ src, int8_t* __restrict__ q1,
                                  int8_t* __restrict__ q2, float* __restrict__ sc, int K) {
    __shared__ float red[32];
    int row = blockIdx.x, tid = threadIdx.x;
    const float4* s4 = (const float4*)(src + (size_t)row * K);
    int n4 = K >> 2;
    int ng = n4 >> 8;                       // groups of 256 float4
    float4 buf[4];
    float vm = 0.0f;
    #pragma unroll
    for (int g = 0; g < 4; g++) {
        if (g < ng) {
            buf[g] = s4[tid + g * 256];
            vm = fmaxf(vm, fmaxf(fmaxf(fabsf(buf[g].x), fabsf(buf[g].y)),
                                 fmaxf(fabsf(buf[g].z), fabsf(buf[g].w))));
        }
    }
    vm = blockReduceMax(vm, red);
    float s = fmaxf(vm, 1e-30f) * (1.0f / 127.0f);
    float fs = 1.0f / s;
    #pragma unroll
    for (int g = 0; g < 4; g++) {
        if (g < ng) {
            float f[4] = {buf[g].x * fs, buf[g].y * fs, buf[g].z * fs, buf[g].w * fs};
            char4 c1, c2;
            int i0 = __float2int_rn(f[0]); c1.x = (char)i0; c2.x = (char)__float2int_rn(128.f * (f[0] - i0));
            int i1 = __float2int_rn(f[1]); c1.y = (char)i1; c2.y = (char)__float2int_rn(128.f * (f[1] - i1));
            int i2 = __float2int_rn(f[2]); c1.z = (char)i2; c2.z = (char)__float2int_rn(128.f * (f[2] - i2));
            int i3 = __float2int_rn(f[3]); c1.w = (char)i3; c2.w = (char)__float2int_rn(128.f * (f[3] - i3));
            ((char4*)q1)[(size_t)row * n4 + tid + g * 256] = c1;
            ((char4*)q2)[(size_t)row * n4 + tid + g * 256] = c2;
        }
    }
    if (tid == 0) sc[row] = s;
}

// ---------------- rmsnorm + quantize (K = 1024) ----------------
__global__ void rmsnorm_quant_kernel(const float* __restrict__ in, int8_t* __restrict__ q1,
                                     int8_t* __restrict__ q2, float* __restrict__ sc) {
    __shared__ float red[32];
    int t = blockIdx.x, tid = threadIdx.x;
    float4 v = ((const float4*)(in + (size_t)t * HIDDEN))[tid];
    float ss = v.x * v.x + v.y * v.y + v.z * v.z + v.w * v.w;
    float vm = fmaxf(fmaxf(fabsf(v.x), fabsf(v.y)), fmaxf(fabsf(v.z), fabsf(v.w)));
    ss = blockReduceSum(ss, red);
    vm = blockReduceMax(vm, red);
    float scn = rsqrtf(ss * (1.0f / HIDDEN) + EPSV);
    float s = fmaxf(vm * scn, 1e-30f) * (1.0f / 127.0f);
    float fs = scn / s;
    float f[4] = {v.x * fs, v.y * fs, v.z * fs, v.w * fs};
    char4 c1, c2;
    int i0 = __float2int_rn(f[0]); c1.x = (char)i0; c2.x = (char)__float2int_rn(128.f * (f[0] - i0));
    int i1 = __float2int_rn(f[1]); c1.y = (char)i1; c2.y = (char)__float2int_rn(128.f * (f[1] - i1));
    int i2 = __float2int_rn(f[2]); c1.z = (char)i2; c2.z = (char)__float2int_rn(128.f * (f[2] - i2));
    int i3 = __float2int_rn(f[3]); c1.w = (char)i3; c2.w = (char)__float2int_rn(128.f * (f[3] - i3));
    ((char4*)q1)[(size_t)t * 256 + tid] = c1;
    ((char4*)q2)[(size_t)t * 256 + tid] = c2;
    if (tid == 0) sc[t] = s;
}

// ---------------- embedding + rmsnorm ----------------
__global__ void embed_rmsnorm_kernel(const int* __restrict__ ids,
                                     const float* __restrict__ wte,
                                     float* __restrict__ out) {
    __shared__ float red[32];
    int t = blockIdx.x;
    const float* row = wte + (size_t)ids[t] * HIDDEN;
    float v[4]; float ss = 0.0f;
    #pragma unroll
    for (int i = 0; i < 4; i++) { v[i] = row[threadIdx.x + i * 256]; ss += v[i] * v[i]; }
    ss = blockReduceSum(ss, red);
    float sc = rsqrtf(ss * (1.0f / HIDDEN) + EPSV);
    #pragma unroll
    for (int i = 0; i < 4; i++)
        out[(size_t)t * HIDDEN + threadIdx.x + i * 256] = v[i] * sc;
}

// ---------------- rope tables ----------------
__global__ void rope_init_kernel(float* __restrict__ ctab, float* __restrict__ stab) {
    int t = blockIdx.x, i = threadIdx.x;
    float invf = (float)pow(10000.0, -(double)(2 * i) / (double)HD);
    float ang = (float)t * invf;
    float s, c;
    sincosf(ang, &s, &c);
    ctab[t * 32 + i] = c;
    stab[t * 32 + i] = s;
}

// ---------------- per-head rmsnorm + rope; split q,k,v to bf16 hi/lo ----------------
__global__ void qknorm_rope_split_kernel(const float* __restrict__ qkv,
                                         const float* __restrict__ ctab,
                                         const float* __restrict__ stab,
                                         __nv_bfloat16* __restrict__ oh,
                                         __nv_bfloat16* __restrict__ ol) {
    int t = blockIdx.x, h = blockIdx.y, w = blockIdx.z;
    size_t base = (size_t)t * (3 * HIDDEN) + (size_t)w * HIDDEN + h * HD;
    const float* p = qkv + base;
    int i = threadIdx.x;
    float x0 = p[2 * i], x1 = p[2 * i + 1];
    float y0, y1;
    if (w < 2) {
        float ss = warpSum(x0 * x0 + x1 * x1);
        float sc = rsqrtf(ss * (1.0f / HD) + EPSV);
        x0 *= sc; x1 *= sc;
        float c = ctab[t * 32 + i], s = stab[t * 32 + i];
        y0 = x1 * c - x0 * s;
        y1 = x1 * s + x0 * c;
    } else {
        y0 = x0; y1 = x1;
    }
    __nv_bfloat162 hh = __floats2bfloat162_rn(y0, y1);
    __nv_bfloat162 ll = __floats2bfloat162_rn(y0 - __bfloat162float(hh.x),
                                              y1 - __bfloat162float(hh.y));
    *(uint32_t*)((char*)oh + (base + 2 * i) * 2) = *(uint32_t*)&hh;
    *(uint32_t*)((char*)ol + (base + 2 * i) * 2) = *(uint32_t*)&ll;
}

// ================= fused flash attention (bf16-split HMMA), fp32 out =================
#define FRS       72
#define FT_BYTES  (64 * FRS * 2)
#define KV_STAGE  (4 * FT_BYTES)
#define FLASH_SMEM (2 * FT_BYTES + 2 * KV_STAGE)

__global__ void __launch_bounds__(128, 2)
flash_attn_kernel(const __nv_bfloat16* __restrict__ qh_g,
                  const __nv_bfloat16* __restrict__ ql_g,
                  float* __restrict__ out) {
    extern __shared__ char fsm[];
    uint32_t sb = smem_u32(fsm);
    uint32_t uQh = sb, uQl = sb + FT_BYTES;

    int tid = threadIdx.x, lane = tid & 31, wid = tid >> 5;
    int h = blockIdx.y;
    int qt = (int)gridDim.x - 1 - (int)blockIdx.x;
    int bm = qt * 64;

    int r = tid >> 1, c0 = (tid & 1) * 32;
    uint32_t soff = (uint32_t)(r * (FRS * 2) + c0 * 2);

    {
        const char* gQh = (const char*)(qh_g + (size_t)(bm + r) * (3 * HIDDEN) + h * HD + c0);
        const char* gQl = (const char*)(ql_g + (size_t)(bm + r) * (3 * HIDDEN) + h * HD + c0);
        #pragma unroll
        for (int g = 0; g < 4; g++) {
            cpa16(uQh + soff + g * 16, gQh + g * 16, 16);
            cpa16(uQl + soff + g * 16, gQl + g * 16, 16);
        }
        const char* gKh = (const char*)(qh_g + (size_t)r * (3 * HIDDEN) + HIDDEN + h * HD + c0);
        const char* gKl = (const char*)(ql_g + (size_t)r * (3 * HIDDEN) + HIDDEN + h * HD + c0);
        uint32_t st = sb + 2 * FT_BYTES;
        #pragma unroll
        for (int g = 0; g < 4; g++) {
            cpa16(st + soff + g * 16,                gKh + g * 16, 16);
            cpa16(st + FT_BYTES + soff + g * 16,     gKl + g * 16, 16);
            cpa16(st + 2 * FT_BYTES + soff + g * 16, gKh + HIDDEN * 2 + g * 16, 16);
            cpa16(st + 3 * FT_BYTES + soff + g * 16, gKl + HIDDEN * 2 + g * 16, 16);
        }
        cpa_commit();
    }

    uint32_t qh[4][4], ql[4][4];
    float o[8][4] = {};
    float m[2] = {-INFINITY, -INFINITY};
    float l[2] = {0.0f, 0.0f};

    for (int jt = 0; jt <= qt; jt++) {
        cpa_wait0();
        __syncthreads();

        if (jt == 0) {
            uint32_t qoff = (uint32_t)(((wid * 16 + (lane & 15)) * FRS + ((lane >> 4) & 1) * 8) * 2);
            #pragma unroll
            for (int ks = 0; ks < 4; ks++) {
                ldmx4(qh[ks], uQh + qoff + ks * 32);
                ldmx4(ql[ks], uQl + qoff + ks * 32);
            }
        }
        if (jt + 1 <= qt) {
            const char* gKh = (const char*)(qh_g + (size_t)((jt + 1) * 64 + r) * (3 * HIDDEN) + HIDDEN + h * HD + c0);
            const char* gKl = (const char*)(ql_g + (size_t)((jt + 1) * 64 + r) * (3 * HIDDEN) + HIDDEN + h * HD + c0);
            uint32_t st = sb + 2 * FT_BYTES + (uint32_t)((jt + 1) & 1) * KV_STAGE;
            #pragma unroll
            for (int g = 0; g < 4; g++) {
                cpa16(st + soff + g * 16,                gKh + g * 16, 16);
                cpa16(st + FT_BYTES + soff + g * 16,     gKl + g * 16, 16);
                cpa16(st + 2 * FT_BYTES + soff + g * 16, gKh + HIDDEN * 2 + g * 16, 16);
                cpa16(st + 3 * FT_BYTES + soff + g * 16, gKl + HIDDEN * 2 + g * 16, 16);
            }
            cpa_commit();
        }

        uint32_t stg = sb + 2 * FT_BYTES + (uint32_t)(jt & 1) * KV_STAGE;
        uint32_t uKh = stg, uKl = stg + FT_BYTES, uVh = stg + 2 * FT_BYTES, uVl = stg + 3 * FT_BYTES;

        float s[8][4] = {};
        uint32_t bbase = (uint32_t)(((((lane >> 4) & 1) * 8 + (lane & 7)) * FRS
                                     + ((lane >> 3) & 1) * 8) * 2);
        #pragma unroll
        for (int ks = 0; ks < 4; ks++) {
            #pragma unroll
            for (int nb = 0; nb < 4; nb++) {
                uint32_t kh[4], kl[4];
                uint32_t bo = bbase + (uint32_t)(nb * 16 * FRS * 2) + (uint32_t)(ks * 32);
                ldmx4(kh, uKh + bo);
                ldmx4(kl, uKl + bo);
                mma_bf16(s[nb * 2],     qh[ks], kh + 0);
                mma_bf16(s[nb * 2 + 1], qh[ks], kh + 2);
                mma_bf16(s[nb * 2],     qh[ks], kl + 0);
                mma_bf16(s[nb * 2 + 1], qh[ks], kl + 2);
                mma_bf16(s[nb * 2],     ql[ks], kh + 0);
                mma_bf16(s[nb * 2 + 1], ql[ks], kh + 2);
            }
        }
        #pragma unroll
        for (int nt = 0; nt < 8; nt++)
            #pragma unroll
            for (int c = 0; c < 4; c++) s[nt][c] *= 0.125f;

        if (jt == qt) {
            int q0 = wid * 16 + (lane >> 2);
            int q1 = q0 + 8;
            #pragma unroll
            for (int nt = 0; nt < 8; nt++) {
                int j0 = nt * 8 + (lane & 3) * 2;
                if (j0     > q0) s[nt][0] = -INFINITY;
                if (j0 + 1 > q0) s[nt][1] = -INFINITY;
                if (j0     > q1) s[nt][2] = -INFINITY;
                if (j0 + 1 > q1) s[nt][3] = -INFINITY;
            }
        }

        #pragma unroll
        for (int hh = 0; hh < 2; hh++) {
            float rm = -INFINITY;
            #pragma unroll
            for (int nt = 0; nt < 8; nt++)
                rm = fmaxf(rm, fmaxf(s[nt][2 * hh], s[nt][2 * hh + 1]));
            rm = fmaxf(rm, __shfl_xor_sync(0xffffffffu, rm, 1));
            rm = fmaxf(rm, __shfl_xor_sync(0xffffffffu, rm, 2));
            float mnew = fmaxf(m[hh], rm);
            float corr = __expf(m[hh] - mnew);
            float rs = 0.0f;
            #pragma unroll
            for (int nt = 0; nt < 8; nt++) {
                float p0 = __expf(s[nt][2 * hh]     - mnew);
                float p1 = __expf(s[nt][2 * hh + 1] - mnew);
                s[nt][2 * hh] = p0; s[nt][2 * hh + 1] = p1;
                rs += p0 + p1;
            }
            rs += __shfl_xor_sync(0xffffffffu, rs, 1);
            rs += __shfl_xor_sync(0xffffffffu, rs, 2);
            l[hh] = l[hh] * corr + rs;
            m[hh] = mnew;
            #pragma unroll
            for (int dt = 0; dt < 8; dt++) {
                o[dt][2 * hh] *= corr; o[dt][2 * hh + 1] *= corr;
            }
        }

        #pragma unroll
        for (int jks = 0; jks < 4; jks++) {
            float* ce = s[2 * jks];
            float* co = s[2 * jks + 1];
            uint32_t pa[4], pb[4];
            {
                __nv_bfloat162 h0 = __floats2bfloat162_rn(ce[0], ce[1]);
                __nv_bfloat162 h1 = __floats2bfloat162_rn(ce[2], ce[3]);
                __nv_bfloat162 h2 = __floats2bfloat162_rn(co[0], co[1]);
                __nv_bfloat162 h3 = __floats2bfloat162_rn(co[2], co[3]);
                pa[0] = *(uint32_t*)&h0; pa[1] = *(uint32_t*)&h1;
                pa[2] = *(uint32_t*)&h2; pa[3] = *(uint32_t*)&h3;
                __nv_bfloat162 e0 = __floats2bfloat162_rn(ce[0] - __bfloat162float(h0.x),
                                                          ce[1] - __bfloat162float(h0.y));
                __nv_bfloat162 e1 = __floats2bfloat162_rn(ce[2] - __bfloat162float(h1.x),
                                                          ce[3] - __bfloat162float(h1.y));
                __nv_bfloat162 e2 = __floats2bfloat162_rn(co[0] - __bfloat162float(h2.x),
                                                          co[1] - __bfloat162float(h2.y));
                __nv_bfloat162 e3 = __floats2bfloat162_rn(co[2] - __bfloat162float(h3.x),
                                                          co[3] - __bfloat162float(h3.y));
                pb[0] = *(uint32_t*)&e0; pb[1] = *(uint32_t*)&e1;
                pb[2] = *(uint32_t*)&e2; pb[3] = *(uint32_t*)&e3;
            }
            uint32_t vbase = (uint32_t)(((jks * 16 + (lane & 15)) * FRS
                                         + ((lane >> 4) & 1) * 8) * 2);
            #pragma unroll
            for (int db = 0; db < 4; db++) {
                uint32_t vh[4], vl[4];
                uint32_t vo = vbase + (uint32_t)(db * 32);
                ldmx4t(vh, uVh + vo);
                ldmx4t(vl, uVl + vo);
                mma_bf16(o[db * 2],     pa, vh + 0);
                mma_bf16(o[db * 2 + 1], pa, vh + 2);
                mma_bf16(o[db * 2],     pa, vl + 0);
                mma_bf16(o[db * 2 + 1], pa, vl + 2);
                mma_bf16(o[db * 2],     pb, vh + 0);
                mma_bf16(o[db * 2 + 1], pb, vh + 2);
            }
        }
    }

    float inv0 = 1.0f / l[0], inv1 = 1.0f / l[1];
    int row0 = bm + wid * 16 + (lane >> 2);
    #pragma unroll
    for (int dt = 0; dt < 8; dt++) {
        int col = h * HD + dt * 8 + (lane & 3) * 2;
        *(float2*)(out + (size_t)row0 * HIDDEN + col) =
            make_float2(o[dt][0] * inv0, o[dt][1] * inv0);
        *(float2*)(out + (size_t)(row0 + 8) * HIDDEN + col) =
            make_float2(o[dt][2] * inv1, o[dt][3] * inv1);
    }
}

// ================= int8 split GEMM (IMMA m16n8k32), cp.async double buffered =================
// C[M,N] = sa[m]*sb[n]*(A1B1 + (A1B2 + A2B1)/128).  BM=64, BN=128, BK=64 (int8).
// EPI 0: C = v    EPI 1: C = R + v    EPI 2: C = relu(v)^2
#define RSB   80                         // smem row stride bytes (64B data + pad)
#define ABYI  (64 * RSB)                 // 5120
#define BBYI  (128 * RSB)                // 10240
#define STGI  (2 * ABYI + 2 * BBYI)      // 30720
#define GSMEM_I8 (2 * STGI)              // 61440

template <int EPI>
__global__ void __launch_bounds__(256, 2)
gemm_i8_kernel(const int8_t* __restrict__ A1, const int8_t* __restrict__ A2,
               const int8_t* __restrict__ B1, const int8_t* __restrict__ B2,
               const float* __restrict__ sa, const float* __restrict__ sb,
               float* __restrict__ C, const float* __restrict__ R,
               int M, int N, int K) {
    extern __shared__ char gsm[];
    int tid = threadIdx.x, lane = tid & 31, wid = tid >> 5;
    int wm = wid >> 2, wn = wid & 3;
    int bm = blockIdx.y * 64, bn = blockIdx.x * 128;

    uint32_t sbse = smem_u32(gsm);

    // A loader: 64 rows x 4 segs of 16B
    int arow = tid >> 2, aseg = tid & 3;
    uint32_t soA = (uint32_t)(arow * RSB + aseg * 16);
    const char* gA1 = (const char*)(A1 + (size_t)(bm + arow) * K + aseg * 16);
    const char* gA2 = (const char*)(A2 + (size_t)(bm + arow) * K + aseg * 16);

    // B loader: 128 rows x 4 segs, two rows per thread
    int brow0 = tid >> 2, bseg = tid & 3;
    const char* gB1r[2]; const char* gB2r[2];
    uint32_t soB[2]; int bsz[2];
    #pragma unroll
    for (int rb = 0; rb < 2; rb++) {
        int br = brow0 + rb * 64;
        int gr = bn + br;
        bool ok = gr < N;
        int grc = ok ? gr : (N - 1);
        gB1r[rb] = (const char*)(B1 + (size_t)grc * K + bseg * 16);
        gB2r[rb] = (const char*)(B2 + (size_t)grc * K + bseg * 16);
        soB[rb] = (uint32_t)(br * RSB + bseg * 16);
        bsz[rb] = ok ? 16 : 0;
    }

    uint32_t aoff = (uint32_t)((wm * 32 + (lane & 15)) * RSB + ((lane >> 4) & 1) * 16);
    uint32_t boff0 = (uint32_t)((wn * 32 + ((lane >> 3) & 1) * 8 + (lane & 7)) * RSB
                                + ((lane >> 4) & 1) * 16);
    uint32_t boff1 = boff0 + 16 * RSB;

    int acc1[2][4][4] = {};
    int acc2[2][4][4] = {};
    int nCh = K >> 6;

    // issue chunk 0
    {
        uint32_t s0 = sbse;
        cpa16(s0 + soA,        gA1, 16);
        cpa16(s0 + ABYI + soA, gA2, 16);
        #pragma unroll
        for (int rb = 0; rb < 2; rb++) {
            cpa16(s0 + 2 * ABYI + soB[rb],        gB1r[rb], bsz[rb]);
            cpa16(s0 + 2 * ABYI + BBYI + soB[rb], gB2r[rb], bsz[rb]);
        }
        cpa_commit();
    }

    for (int s = 0; s < nCh; s++) {
        cpa_wait0();
        __syncthreads();

        if (s + 1 < nCh) {
            uint32_t s1 = sbse + (uint32_t)((s + 1) & 1) * STGI;
            int kb = (s + 1) * 64;
            cpa16(s1 + soA,        gA1 + kb, 16);
            cpa16(s1 + ABYI + soA, gA2 + kb, 16);
            #pragma unroll
            for (int rb = 0; rb < 2; rb++) {
                cpa16(s1 + 2 * ABYI + soB[rb],        gB1r[rb] + kb, bsz[rb]);
                cpa16(s1 + 2 * ABYI + BBYI + soB[rb], gB2r[rb] + kb, bsz[rb]);
            }
            cpa_commit();
        }

        uint32_t st = sbse + (uint32_t)(s & 1) * STGI;
        uint32_t uA1 = st, uA2 = st + ABYI, uB1 = st + 2 * ABYI, uB2 = st + 2 * ABYI + BBYI;
        #pragma unroll
        for (int ks = 0; ks < 2; ks++) {
            uint32_t k2 = (uint32_t)(ks * 32);
            uint32_t aH[2][4], aL[2][4], bH[2][4], bL[2][4];
            #pragma unroll
            for (int mt = 0; mt < 2; mt++) {
                ldmx4(aH[mt], uA1 + aoff + mt * (16 * RSB) + k2);
                ldmx4(aL[mt], uA2 + aoff + mt * (16 * RSB) + k2);
            }
            ldmx4(bH[0], uB1 + boff0 + k2);
            ldmx4(bH[1], uB1 + boff1 + k2);
            ldmx4(bL[0], uB2 + boff0 + k2);
            ldmx4(bL[1], uB2 + boff1 + k2);
            #pragma unroll
            for (int mt = 0; mt < 2; mt++) {
                #pragma unroll
                for (int np = 0; np < 2; np++) {
                    #pragma unroll
                    for (int hf = 0; hf < 2; hf++) {
                        int nt = np * 2 + hf;
                        mma_s8(acc1[mt][nt], aH[mt], bH[np][hf], bH[np][hf + 2]);
                        mma_s8(acc2[mt][nt], aH[mt], bL[np][hf], bL[np][hf + 2]);
                        mma_s8(acc2[mt][nt], aL[mt], bH[np][hf], bH[np][hf + 2]);
                    }
                }
            }
        }
    }

    const float inv128 = 0.0078125f;
    #pragma unroll
    for (int mt = 0; mt < 2; mt++) {
        int rw = bm + wm * 32 + mt * 16 + (lane >> 2);
        float a0 = sa[rw], a8 = sa[rw + 8];
        #pragma unroll
        for (int nt = 0; nt < 4; nt++) {
            int col = bn + wn * 32 + nt * 8 + (lane & 3) * 2;
            if (col < N) {
                float sb0 = sb[col], sb1 = sb[col + 1];
                int* c1 = acc1[mt][nt];
                int* c2 = acc2[mt][nt];
                float v0 = ((float)c1[0] + (float)c2[0] * inv128) * a0 * sb0;
                float v1 = ((float)c1[1] + (float)c2[1] * inv128) * a0 * sb1;
                float v2 = ((float)c1[2] + (float)c2[2] * inv128) * a8 * sb0;
                float v3 = ((float)c1[3] + (float)c2[3] * inv128) * a8 * sb1;
                if (EPI == 1) {
                    float2 r0 = *(const float2*)(R + (size_t)rw * N + col);
                    float2 r1 = *(const float2*)(R + (size_t)(rw + 8) * N + col);
                    v0 += r0.x; v1 += r0.y; v2 += r1.x; v3 += r1.y;
                }
                if (EPI == 2) {
                    v0 = fmaxf(v0, 0.f); v0 *= v0;
                    v1 = fmaxf(v1, 0.f); v1 *= v1;
                    v2 = fmaxf(v2, 0.f); v2 *= v2;
                    v3 = fmaxf(v3, 0.f); v3 *= v3;
                }
                *(float2*)(C + (size_t)rw * N + col) = make_float2(v0, v1);
                *(float2*)(C + (size_t)(rw + 8) * N + col) = make_float2(v2, v3);
            }
        }
    }
}

// ---------------- host launcher ----------------
extern "C" void kernel_launch(void* const* d_in, const int* in_sizes, int n_in,
                              void* d_out, int out_size) {
    const int*   ids  = (const int*)d_in[0];
    const float* wte  = (const float*)d_in[1];
    const float* wqkv = (const float*)d_in[2];
    const float* wo   = (const float*)d_in[3];
    const float* w1   = (const float*)d_in[4];
    const float* w2   = (const float*)d_in[5];
    const float* lm   = (const float*)d_in[6];
    float* out = (float*)d_out;

    float *px, *pqkv, *patt, *pmid, *pcos, *psin, *pswt, *psa;
    __nv_bfloat16 *psh, *psl;
    int8_t *pw1, *pw2, *paq1, *paq2;
    cudaGetSymbolAddress((void**)&px,   g_x);
    cudaGetSymbolAddress((void**)&pqkv, g_qkv);
    cudaGetSymbolAddress((void**)&patt, g_att);
    cudaGetSymbolAddress((void**)&pmid, g_mid);
    cudaGetSymbolAddress((void**)&pcos, g_cos);
    cudaGetSymbolAddress((void**)&psin, g_sin);
    cudaGetSymbolAddress((void**)&psh,  g_sh);
    cudaGetSymbolAddress((void**)&psl,  g_sl);
    cudaGetSymbolAddress((void**)&pw1,  g_w1p);
    cudaGetSymbolAddress((void**)&pw2,  g_w2p);
    cudaGetSymbolAddress((void**)&pswt, g_swt);
    cudaGetSymbolAddress((void**)&paq1, g_aq1);
    cudaGetSymbolAddress((void**)&paq2, g_aq2);
    cudaGetSymbolAddress((void**)&psa,  g_sa);

    cudaFuncSetAttribute(flash_attn_kernel,
                         cudaFuncAttributeMaxDynamicSharedMemorySize, FLASH_SMEM);
    cudaFuncSetAttribute(gemm_i8_kernel<0>,
                         cudaFuncAttributeMaxDynamicSharedMemorySize, GSMEM_I8);
    cudaFuncSetAttribute(gemm_i8_kernel<1>,
                         cudaFuncAttributeMaxDynamicSharedMemorySize, GSMEM_I8);
    cudaFuncSetAttribute(gemm_i8_kernel<2>,
                         cudaFuncAttributeMaxDynamicSharedMemorySize, GSMEM_I8);

    // ---- weight quantization (per launch) ----
    {
        struct { const float* s; size_t eoff; int soff, rows, K; } wt[5] = {
            {wqkv, OFF_WQKV, SOFF_QKV, 24576, 1024},
            {wo,   OFF_WO,   SOFF_WO,   8192, 1024},
            {w1,   OFF_W1,   SOFF_W1,  32768, 1024},
            {w2,   OFF_W2,   SOFF_W2,   8192, 4096},
            {lm,   OFF_LM,   SOFF_LM,  50272, 1024},
        };
        for (int i = 0; i < 5; i++)
            quant_rows_kernel<<<wt[i].rows, 256>>>(
                wt[i].s, pw1 + wt[i].eoff, pw2 + wt[i].eoff, pswt + wt[i].soff, wt[i].K);
    }

    rope_init_kernel<<<SEQ, 32>>>(pcos, psin);
    embed_rmsnorm_kernel<<<SEQ, 256>>>(ids, wte, px);

    for (int l = 0; l < NL; l++) {
        int8_t* wqkv1 = pw1 + OFF_WQKV + (size_t)l * 3145728;
        int8_t* wqkv2 = pw2 + OFF_WQKV + (size_t)l * 3145728;
        int8_t* wo1   = pw1 + OFF_WO + (size_t)l * 1048576;
        int8_t* wo2   = pw2 + OFF_WO + (size_t)l * 1048576;
        int8_t* w11   = pw1 + OFF_W1 + (size_t)l * 4194304;
        int8_t* w12   = pw2 + OFF_W1 + (size_t)l * 4194304;
        int8_t* w21   = pw1 + OFF_W2 + (size_t)l * 4194304;
        int8_t* w22   = pw2 + OFF_W2 + (size_t)l * 4194304;
        float* s_qkv = pswt + SOFF_QKV + l * 3072;
        float* s_wo  = pswt + SOFF_WO  + l * 1024;
        float* s_w1  = pswt + SOFF_W1  + l * 4096;
        float* s_w2  = pswt + SOFF_W2  + l * 1024;

        rmsnorm_quant_kernel<<<SEQ, 256>>>(px, paq1, paq2, psa);
        gemm_i8_kernel<0><<<dim3(24, 32), 256, GSMEM_I8>>>(
            paq1, paq2, wqkv1, wqkv2, psa, s_qkv, pqkv, nullptr, SEQ, 3 * HIDDEN, HIDDEN);
        qknorm_rope_split_kernel<<<dim3(SEQ, NH, 3), 32>>>(pqkv, pcos, psin, psh, psl);
        flash_attn_kernel<<<dim3(SEQ / 64, NH), 128, FLASH_SMEM>>>(psh, psl, patt);
        quant_rows_kernel<<<SEQ, 256>>>(patt, paq1, paq2, psa, HIDDEN);
        gemm_i8_kernel<1><<<dim3(8, 32), 256, GSMEM_I8>>>(
            paq1, paq2, wo1, wo2, psa, s_wo, px, px, SEQ, HIDDEN, HIDDEN);

        rmsnorm_quant_kernel<<<SEQ, 256>>>(px, paq1, paq2, psa);
        gemm_i8_kernel<2><<<dim3(32, 32), 256, GSMEM_I8>>>(
            paq1, paq2, w11, w12, psa, s_w1, pmid, nullptr, SEQ, FFN, HIDDEN);
        quant_rows_kernel<<<SEQ, 256>>>(pmid, paq1, paq2, psa, FFN);
        gemm_i8_kernel<1><<<dim3(8, 32), 256, GSMEM_I8>>>(
            paq1, paq2, w21, w22, psa, s_w2, px, px, SEQ, HIDDEN, FFN);
    }

    rmsnorm_quant_kernel<<<SEQ, 256>>>(px, paq1, paq2, psa);
    gemm_i8_kernel<0><<<dim3((VOCABSZ + 127) / 128, 32), 256, GSMEM_I8>>>(
        paq1, paq2, pw1 + OFF_LM, pw2 + OFF_LM, psa, pswt + SOFF_LM, out, nullptr,
        SEQ, VOCABSZ, HIDDEN);
}

// round 9
// speedup vs baseline: 2.3425x; 2.3425x over previous
#include <cuda_runtime.h>
#include <cuda_bf16.h>
#include <cuda_fp16.h>
#include <math.h>
#include <stdint.h>

#define SEQ     2048
#define HIDDEN  1024
#define NH      16
#define HD      64
#define NL      8
#define VOCABSZ 50272
#define FFN     4096
#define EPSV    1e-5f

#define OFF_WQKV 0ULL
#define OFF_WO   25165824ULL
#define OFF_W1   33554432ULL
#define OFF_W2   67108864ULL
#define OFF_LM   100663296ULL
#define W_TOTAL  152141824ULL

// ---------------- scratch ----------------
__device__ float g_x  [(size_t)SEQ * HIDDEN];
__device__ float g_qkv[(size_t)SEQ * 3 * HIDDEN];
__device__ float g_cos[(size_t)SEQ * (HD / 2)];
__device__ float g_sin[(size_t)SEQ * (HD / 2)];
__device__ __nv_bfloat16 g_wh[W_TOTAL];          // bf16-hi (wo,w1,w2) or fp16 (wqkv,lm)
__device__ __nv_bfloat16 g_wl[W_TOTAL];          // bf16-lo (wo,w1,w2)
__device__ __nv_bfloat16 g_sh[(size_t)SEQ * 3 * HIDDEN], g_sl[(size_t)SEQ * 3 * HIDDEN];
__device__ __nv_bfloat16 g_hh[(size_t)SEQ * HIDDEN], g_hl[(size_t)SEQ * HIDDEN];  // bf16 or fp16
__device__ __nv_bfloat16 g_ah[(size_t)SEQ * HIDDEN], g_al[(size_t)SEQ * HIDDEN];
__device__ __nv_bfloat16 g_mh[(size_t)SEQ * FFN],    g_ml[(size_t)SEQ * FFN];

// ---------------- helpers ----------------
__device__ __forceinline__ uint32_t smem_u32(const void* p) {
    uint32_t a;
    asm("{ .reg .u64 t; cvta.to.shared.u64 t, %1; cvt.u32.u64 %0, t; }" : "=r"(a) : "l"(p));
    return a;
}
__device__ __forceinline__ float warpSum(float v) {
    #pragma unroll
    for (int o = 16; o; o >>= 1) v += __shfl_xor_sync(0xffffffffu, v, o);
    return v;
}
__device__ __forceinline__ float blockReduceSum(float v, float* red) {
    int lane = threadIdx.x & 31, w = threadIdx.x >> 5;
    v = warpSum(v);
    if (lane == 0) red[w] = v;
    __syncthreads();
    if (w == 0) {
        float r = (lane < (int)(blockDim.x >> 5)) ? red[lane] : 0.0f;
        r = warpSum(r);
        if (lane == 0) red[0] = r;
    }
    __syncthreads();
    float out = red[0];
    __syncthreads();
    return out;
}
__device__ __forceinline__ void mma_bf16(float* c, const uint32_t* a, const uint32_t* b) {
    asm volatile(
        "mma.sync.aligned.m16n8k16.row.col.f32.bf16.bf16.f32 "
        "{%0,%1,%2,%3}, {%4,%5,%6,%7}, {%8,%9}, {%0,%1,%2,%3};"
        : "+f"(c[0]), "+f"(c[1]), "+f"(c[2]), "+f"(c[3])
        : "r"(a[0]), "r"(a[1]), "r"(a[2]), "r"(a[3]), "r"(b[0]), "r"(b[1]));
}
__device__ __forceinline__ void mma_f16(float* c, const uint32_t* a, const uint32_t* b) {
    asm volatile(
        "mma.sync.aligned.m16n8k16.row.col.f32.f16.f16.f32 "
        "{%0,%1,%2,%3}, {%4,%5,%6,%7}, {%8,%9}, {%0,%1,%2,%3};"
        : "+f"(c[0]), "+f"(c[1]), "+f"(c[2]), "+f"(c[3])
        : "r"(a[0]), "r"(a[1]), "r"(a[2]), "r"(a[3]), "r"(b[0]), "r"(b[1]));
}
__device__ __forceinline__ void ldmx4(uint32_t* d, uint32_t addr) {
    asm volatile("ldmatrix.sync.aligned.m8n8.x4.shared.b16 {%0,%1,%2,%3}, [%4];"
                 : "=r"(d[0]), "=r"(d[1]), "=r"(d[2]), "=r"(d[3]) : "r"(addr));
}
__device__ __forceinline__ void ldmx4t(uint32_t* d, uint32_t addr) {
    asm volatile("ldmatrix.sync.aligned.m8n8.x4.trans.shared.b16 {%0,%1,%2,%3}, [%4];"
                 : "=r"(d[0]), "=r"(d[1]), "=r"(d[2]), "=r"(d[3]) : "r"(addr));
}
__device__ __forceinline__ void split4(float4 f, uint2& h, uint2& l) {
    __nv_bfloat162 h0 = __floats2bfloat162_rn(f.x, f.y);
    __nv_bfloat162 h1 = __floats2bfloat162_rn(f.z, f.w);
    __nv_bfloat162 l0 = __floats2bfloat162_rn(f.x - __bfloat162float(h0.x),
                                              f.y - __bfloat162float(h0.y));
    __nv_bfloat162 l1 = __floats2bfloat162_rn(f.z - __bfloat162float(h1.x),
                                              f.w - __bfloat162float(h1.y));
    h.x = *(uint32_t*)&h0; h.y = *(uint32_t*)&h1;
    l.x = *(uint32_t*)&l0; l.y = *(uint32_t*)&l1;
}
__device__ __forceinline__ void cpa16(uint32_t s, const void* g, int srcsz) {
    asm volatile("cp.async.cg.shared.global [%0], [%1], 16, %2;"
                 :: "r"(s), "l"(g), "r"(srcsz) : "memory");
}
__device__ __forceinline__ void cpa_commit() {
    asm volatile("cp.async.commit_group;" ::: "memory");
}
__device__ __forceinline__ void cpa_wait0() {
    asm volatile("cp.async.wait_group 0;" ::: "memory");
}

// ---------------- weight prep ----------------
__global__ void wsplit_kernel(const float4* __restrict__ src, uint32_t* __restrict__ dh,
                              uint32_t* __restrict__ dl, size_t n4) {
    size_t i = (size_t)blockIdx.x * blockDim.x + threadIdx.x;
    if (i < n4) {
        uint2 h, l;
        split4(src[i], h, l);
        dh[2 * i] = h.x; dh[2 * i + 1] = h.y;
        dl[2 * i] = l.x; dl[2 * i + 1] = l.y;
    }
}
__global__ void wsplit_f16_kernel(const float4* __restrict__ src, uint32_t* __restrict__ d,
                                  size_t n4) {
    size_t i = (size_t)blockIdx.x * blockDim.x + threadIdx.x;
    if (i < n4) {
        float4 f = src[i];
        __half2 h0 = __floats2half2_rn(f.x, f.y);
        __half2 h1 = __floats2half2_rn(f.z, f.w);
        d[2 * i] = *(uint32_t*)&h0;
        d[2 * i + 1] = *(uint32_t*)&h1;
    }
}

// ---------------- embedding + rmsnorm ----------------
__global__ void embed_rmsnorm_kernel(const int* __restrict__ ids,
                                     const float* __restrict__ wte,
                                     float* __restrict__ out) {
    __shared__ float red[32];
    int t = blockIdx.x;
    const float* row = wte + (size_t)ids[t] * HIDDEN;
    float v[4]; float ss = 0.0f;
    #pragma unroll
    for (int i = 0; i < 4; i++) { v[i] = row[threadIdx.x + i * 256]; ss += v[i] * v[i]; }
    ss = blockReduceSum(ss, red);
    float sc = rsqrtf(ss * (1.0f / HIDDEN) + EPSV);
    #pragma unroll
    for (int i = 0; i < 4; i++)
        out[(size_t)t * HIDDEN + threadIdx.x + i * 256] = v[i] * sc;
}

// ---------------- rmsnorm: fp32 in -> split planes (bf16 or fp16) ----------------
template <int F16>
__global__ void rmsnorm_split_kernel(const float* __restrict__ in,
                                     __nv_bfloat16* __restrict__ oh,
                                     __nv_bfloat16* __restrict__ ol) {
    __shared__ float red[32];
    int t = blockIdx.x;
    const float* row = in + (size_t)t * HIDDEN;
    float v[4]; float ss = 0.0f;
    #pragma unroll
    for (int i = 0; i < 4; i++) {
        int idx = 2 * threadIdx.x + (i & 1) + (i >> 1) * 512;
        v[i] = row[idx];
        ss += v[i] * v[i];
    }
    ss = blockReduceSum(ss, red);
    float sc = rsqrtf(ss * (1.0f / HIDDEN) + EPSV);
    #pragma unroll
    for (int p = 0; p < 2; p++) {
        float a = v[2 * p] * sc, b = v[2 * p + 1] * sc;
        uint32_t uh, ul;
        if (F16) {
            __half2 hh = __floats2half2_rn(a, b);
            __half2 ll = __floats2half2_rn(a - __half2float(hh.x),
                                           b - __half2float(hh.y));
            uh = *(uint32_t*)&hh; ul = *(uint32_t*)&ll;
        } else {
            __nv_bfloat162 hh = __floats2bfloat162_rn(a, b);
            __nv_bfloat162 ll = __floats2bfloat162_rn(a - __bfloat162float(hh.x),
                                                      b - __bfloat162float(hh.y));
            uh = *(uint32_t*)&hh; ul = *(uint32_t*)&ll;
        }
        size_t off = (size_t)t * HIDDEN + 2 * threadIdx.x + p * 512;
        *(uint32_t*)((char*)oh + off * 2) = uh;
        *(uint32_t*)((char*)ol + off * 2) = ul;
    }
}

// ---------------- rope tables ----------------
__global__ void rope_init_kernel(float* __restrict__ ctab, float* __restrict__ stab) {
    int t = blockIdx.x, i = threadIdx.x;
    float invf = (float)pow(10000.0, -(double)(2 * i) / (double)HD);
    float ang = (float)t * invf;
    float s, c;
    sincosf(ang, &s, &c);
    ctab[t * 32 + i] = c;
    stab[t * 32 + i] = s;
}

// ---------------- per-token: qk rmsnorm+rope+split, v split. grid SEQ, 256 thr ----------------
__global__ void qknorm_rope_split_kernel(const float* __restrict__ qkv,
                                         const float* __restrict__ ctab,
                                         const float* __restrict__ stab,
                                         __nv_bfloat16* __restrict__ oh,
                                         __nv_bfloat16* __restrict__ ol) {
    int t = blockIdx.x, tid = threadIdx.x, lane = tid & 31, wid = tid >> 5;
    float cc = ctab[t * 32 + lane], ssn = stab[t * 32 + lane];
    #pragma unroll
    for (int task = wid; task < 32; task += 8) {
        int h = task & 15, wv = task >> 4;
        size_t base = (size_t)t * (3 * HIDDEN) + (size_t)wv * HIDDEN + h * HD;
        float2 x = *(const float2*)(qkv + base + 2 * lane);
        float ss = warpSum(x.x * x.x + x.y * x.y);
        float sc = rsqrtf(ss * (1.0f / HD) + EPSV);
        float x0 = x.x * sc, x1 = x.y * sc;
        float y0 = x1 * cc - x0 * ssn;
        float y1 = x1 * ssn + x0 * cc;
        __nv_bfloat162 hh = __floats2bfloat162_rn(y0, y1);
        __nv_bfloat162 ll = __floats2bfloat162_rn(y0 - __bfloat162float(hh.x),
                                                  y1 - __bfloat162float(hh.y));
        *(uint32_t*)((char*)oh + (base + 2 * lane) * 2) = *(uint32_t*)&hh;
        *(uint32_t*)((char*)ol + (base + 2 * lane) * 2) = *(uint32_t*)&ll;
    }
    // v: 1024 floats
    size_t vb = (size_t)t * (3 * HIDDEN) + 2 * HIDDEN;
    float4 v = *(const float4*)(qkv + vb + tid * 4);
    uint2 h, l;
    split4(v, h, l);
    *(uint2*)((char*)oh + (vb + tid * 4) * 2) = h;
    *(uint2*)((char*)ol + (vb + tid * 4) * 2) = l;
}

// ================= fused flash attention (pre-split bf16, cp.async pipelined) =================
#define FRS       72
#define FT_BYTES  (64 * FRS * 2)
#define KV_STAGE  (4 * FT_BYTES)
#define FLASH_SMEM (2 * FT_BYTES + 2 * KV_STAGE)

__global__ void __launch_bounds__(128, 2)
flash_attn_kernel(const __nv_bfloat16* __restrict__ qh_g,
                  const __nv_bfloat16* __restrict__ ql_g,
                  __nv_bfloat16* __restrict__ outh, __nv_bfloat16* __restrict__ outl) {
    extern __shared__ char fsm[];
    uint32_t sb = smem_u32(fsm);
    uint32_t uQh = sb, uQl = sb + FT_BYTES;

    int tid = threadIdx.x, lane = tid & 31, wid = tid >> 5;
    int h = blockIdx.y;
    int qt = (int)gridDim.x - 1 - (int)blockIdx.x;
    int bm = qt * 64;

    int r = tid >> 1, c0 = (tid & 1) * 32;
    uint32_t soff = (uint32_t)(r * (FRS * 2) + c0 * 2);

    {
        const char* gQh = (const char*)(qh_g + (size_t)(bm + r) * (3 * HIDDEN) + h * HD + c0);
        const char* gQl = (const char*)(ql_g + (size_t)(bm + r) * (3 * HIDDEN) + h * HD + c0);
        #pragma unroll
        for (int g = 0; g < 4; g++) {
            cpa16(uQh + soff + g * 16, gQh + g * 16, 16);
            cpa16(uQl + soff + g * 16, gQl + g * 16, 16);
        }
        const char* gKh = (const char*)(qh_g + (size_t)r * (3 * HIDDEN) + HIDDEN + h * HD + c0);
        const char* gKl = (const char*)(ql_g + (size_t)r * (3 * HIDDEN) + HIDDEN + h * HD + c0);
        uint32_t st = sb + 2 * FT_BYTES;
        #pragma unroll
        for (int g = 0; g < 4; g++) {
            cpa16(st + soff + g * 16,                gKh + g * 16, 16);
            cpa16(st + FT_BYTES + soff + g * 16,     gKl + g * 16, 16);
            cpa16(st + 2 * FT_BYTES + soff + g * 16, gKh + HIDDEN * 2 + g * 16, 16);
            cpa16(st + 3 * FT_BYTES + soff + g * 16, gKl + HIDDEN * 2 + g * 16, 16);
        }
        cpa_commit();
    }

    uint32_t qh[4][4], ql[4][4];
    float o[8][4] = {};
    float m[2] = {-INFINITY, -INFINITY};
    float l[2] = {0.0f, 0.0f};

    for (int jt = 0; jt <= qt; jt++) {
        cpa_wait0();
        __syncthreads();

        if (jt == 0) {
            uint32_t qoff = (uint32_t)(((wid * 16 + (lane & 15)) * FRS + ((lane >> 4) & 1) * 8) * 2);
            #pragma unroll
            for (int ks = 0; ks < 4; ks++) {
                ldmx4(qh[ks], uQh + qoff + ks * 32);
                ldmx4(ql[ks], uQl + qoff + ks * 32);
            }
        }
        if (jt + 1 <= qt) {
            const char* gKh = (const char*)(qh_g + (size_t)((jt + 1) * 64 + r) * (3 * HIDDEN) + HIDDEN + h * HD + c0);
            const char* gKl = (const char*)(ql_g + (size_t)((jt + 1) * 64 + r) * (3 * HIDDEN) + HIDDEN + h * HD + c0);
            uint32_t st = sb + 2 * FT_BYTES + (uint32_t)((jt + 1) & 1) * KV_STAGE;
            #pragma unroll
            for (int g = 0; g < 4; g++) {
                cpa16(st + soff + g * 16,                gKh + g * 16, 16);
                cpa16(st + FT_BYTES + soff + g * 16,     gKl + g * 16, 16);
                cpa16(st + 2 * FT_BYTES + soff + g * 16, gKh + HIDDEN * 2 + g * 16, 16);
                cpa16(st + 3 * FT_BYTES + soff + g * 16, gKl + HIDDEN * 2 + g * 16, 16);
            }
            cpa_commit();
        }

        uint32_t stg = sb + 2 * FT_BYTES + (uint32_t)(jt & 1) * KV_STAGE;
        uint32_t uKh = stg, uKl = stg + FT_BYTES, uVh = stg + 2 * FT_BYTES, uVl = stg + 3 * FT_BYTES;

        float s[8][4] = {};
        uint32_t bbase = (uint32_t)(((((lane >> 4) & 1) * 8 + (lane & 7)) * FRS
                                     + ((lane >> 3) & 1) * 8) * 2);
        #pragma unroll
        for (int ks = 0; ks < 4; ks++) {
            #pragma unroll
            for (int nb = 0; nb < 4; nb++) {
                uint32_t kh[4], kl[4];
                uint32_t bo = bbase + (uint32_t)(nb * 16 * FRS * 2) + (uint32_t)(ks * 32);
                ldmx4(kh, uKh + bo);
                ldmx4(kl, uKl + bo);
                mma_bf16(s[nb * 2],     qh[ks], kh + 0);
                mma_bf16(s[nb * 2 + 1], qh[ks], kh + 2);
                mma_bf16(s[nb * 2],     qh[ks], kl + 0);
                mma_bf16(s[nb * 2 + 1], qh[ks], kl + 2);
                mma_bf16(s[nb * 2],     ql[ks], kh + 0);
                mma_bf16(s[nb * 2 + 1], ql[ks], kh + 2);
            }
        }
        #pragma unroll
        for (int nt = 0; nt < 8; nt++)
            #pragma unroll
            for (int c = 0; c < 4; c++) s[nt][c] *= 0.125f;

        if (jt == qt) {
            int q0 = wid * 16 + (lane >> 2);
            int q1 = q0 + 8;
            #pragma unroll
            for (int nt = 0; nt < 8; nt++) {
                int j0 = nt * 8 + (lane & 3) * 2;
                if (j0     > q0) s[nt][0] = -INFINITY;
                if (j0 + 1 > q0) s[nt][1] = -INFINITY;
                if (j0     > q1) s[nt][2] = -INFINITY;
                if (j0 + 1 > q1) s[nt][3] = -INFINITY;
            }
        }

        #pragma unroll
        for (int hh = 0; hh < 2; hh++) {
            float rm = -INFINITY;
            #pragma unroll
            for (int nt = 0; nt < 8; nt++)
                rm = fmaxf(rm, fmaxf(s[nt][2 * hh], s[nt][2 * hh + 1]));
            rm = fmaxf(rm, __shfl_xor_sync(0xffffffffu, rm, 1));
            rm = fmaxf(rm, __shfl_xor_sync(0xffffffffu, rm, 2));
            float mnew = fmaxf(m[hh], rm);
            float corr = __expf(m[hh] - mnew);
            float rs = 0.0f;
            #pragma unroll
            for (int nt = 0; nt < 8; nt++) {
                float p0 = __expf(s[nt][2 * hh]     - mnew);
                float p1 = __expf(s[nt][2 * hh + 1] - mnew);
                s[nt][2 * hh] = p0; s[nt][2 * hh + 1] = p1;
                rs += p0 + p1;
            }
            rs += __shfl_xor_sync(0xffffffffu, rs, 1);
            rs += __shfl_xor_sync(0xffffffffu, rs, 2);
            l[hh] = l[hh] * corr + rs;
            m[hh] = mnew;
            #pragma unroll
            for (int dt = 0; dt < 8; dt++) {
                o[dt][2 * hh] *= corr; o[dt][2 * hh + 1] *= corr;
            }
        }

        #pragma unroll
        for (int jks = 0; jks < 4; jks++) {
            float* ce = s[2 * jks];
            float* co = s[2 * jks + 1];
            uint32_t pa[4], pb[4];
            {
                __nv_bfloat162 h0 = __floats2bfloat162_rn(ce[0], ce[1]);
                __nv_bfloat162 h1 = __floats2bfloat162_rn(ce[2], ce[3]);
                __nv_bfloat162 h2 = __floats2bfloat162_rn(co[0], co[1]);
                __nv_bfloat162 h3 = __floats2bfloat162_rn(co[2], co[3]);
                pa[0] = *(uint32_t*)&h0; pa[1] = *(uint32_t*)&h1;
                pa[2] = *(uint32_t*)&h2; pa[3] = *(uint32_t*)&h3;
                __nv_bfloat162 e0 = __floats2bfloat162_rn(ce[0] - __bfloat162float(h0.x),
                                                          ce[1] - __bfloat162float(h0.y));
                __nv_bfloat162 e1 = __floats2bfloat162_rn(ce[2] - __bfloat162float(h1.x),
                                                          ce[3] - __bfloat162float(h1.y));
                __nv_bfloat162 e2 = __floats2bfloat162_rn(co[0] - __bfloat162float(h2.x),
                                                          co[1] - __bfloat162float(h2.y));
                __nv_bfloat162 e3 = __floats2bfloat162_rn(co[2] - __bfloat162float(h3.x),
                                                          co[3] - __bfloat162float(h3.y));
                pb[0] = *(uint32_t*)&e0; pb[1] = *(uint32_t*)&e1;
                pb[2] = *(uint32_t*)&e2; pb[3] = *(uint32_t*)&e3;
            }
            uint32_t vbase = (uint32_t)(((jks * 16 + (lane & 15)) * FRS
                                         + ((lane >> 4) & 1) * 8) * 2);
            #pragma unroll
            for (int db = 0; db < 4; db++) {
                uint32_t vh[4], vl[4];
                uint32_t vo = vbase + (uint32_t)(db * 32);
                ldmx4t(vh, uVh + vo);
                ldmx4t(vl, uVl + vo);
                mma_bf16(o[db * 2],     pa, vh + 0);
                mma_bf16(o[db * 2 + 1], pa, vh + 2);
                mma_bf16(o[db * 2],     pa, vl + 0);
                mma_bf16(o[db * 2 + 1], pa, vl + 2);
                mma_bf16(o[db * 2],     pb, vh + 0);
                mma_bf16(o[db * 2 + 1], pb, vh + 2);
            }
        }
    }

    float inv0 = 1.0f / l[0], inv1 = 1.0f / l[1];
    int row0 = bm + wid * 16 + (lane >> 2);
    #pragma unroll
    for (int dt = 0; dt < 8; dt++) {
        int col = h * HD + dt * 8 + (lane & 3) * 2;
        float a0 = o[dt][0] * inv0, b0 = o[dt][1] * inv0;
        float a1 = o[dt][2] * inv1, b1 = o[dt][3] * inv1;
        __nv_bfloat162 hh0 = __floats2bfloat162_rn(a0, b0);
        __nv_bfloat162 ll0 = __floats2bfloat162_rn(a0 - __bfloat162float(hh0.x),
                                                   b0 - __bfloat162float(hh0.y));
        __nv_bfloat162 hh1 = __floats2bfloat162_rn(a1, b1);
        __nv_bfloat162 ll1 = __floats2bfloat162_rn(a1 - __bfloat162float(hh1.x),
                                                   b1 - __bfloat162float(hh1.y));
        size_t off0 = (size_t)row0 * HIDDEN + col;
        size_t off1 = (size_t)(row0 + 8) * HIDDEN + col;
        *(uint32_t*)((char*)outh + off0 * 2) = *(uint32_t*)&hh0;
        *(uint32_t*)((char*)outl + off0 * 2) = *(uint32_t*)&ll0;
        *(uint32_t*)((char*)outh + off1 * 2) = *(uint32_t*)&hh1;
        *(uint32_t*)((char*)outl + off1 * 2) = *(uint32_t*)&ll1;
    }
}

// ================= bf16-split 3-pass GEMM (R7, unchanged) =================
#define RS 40

template <int EPI, int BM>
__global__ void __launch_bounds__(256, 2)
gemm_bf16_kernel(const __nv_bfloat16* __restrict__ Ah, const __nv_bfloat16* __restrict__ Al,
                 const __nv_bfloat16* __restrict__ Bh, const __nv_bfloat16* __restrict__ Bl,
                 float* __restrict__ C, const float* __restrict__ R,
                 __nv_bfloat16* __restrict__ Oh, __nv_bfloat16* __restrict__ Ol,
                 int M, int N, int K) {
    constexpr int MT = (BM == 128) ? 4 : 2;
    constexpr int ABY = BM * RS * 2;
    constexpr int BBY = 128 * RS * 2;
    constexpr int STG = 2 * ABY + 2 * BBY;

    extern __shared__ char gsm[];
    int tid = threadIdx.x, lane = tid & 31, wid = tid >> 5;
    int wm = wid >> 2, wn = wid & 3;
    int bm = blockIdx.y * BM, bn = blockIdx.x * 128;

    uint32_t sb = smem_u32(gsm);

    int arow, acpa_n; uint32_t so_a; const char *gAh, *gAl;
    if (BM == 128) {
        arow = tid >> 1; int half = tid & 1; acpa_n = 2;
        so_a = (uint32_t)(arow * 80 + half * 32);
        gAh = (const char*)(Ah + (size_t)(bm + arow) * K + half * 16);
        gAl = (const char*)(Al + (size_t)(bm + arow) * K + half * 16);
    } else {
        arow = tid >> 2; int seg = tid & 3; acpa_n = 1;
        so_a = (uint32_t)(arow * 80 + seg * 16);
        gAh = (const char*)(Ah + (size_t)(bm + arow) * K + seg * 8);
        gAl = (const char*)(Al + (size_t)(bm + arow) * K + seg * 8);
    }
    int brow = tid >> 1, bhalf = tid & 1;
    int bgrow = bn + brow;
    bool bok = bgrow < N;
    int browc = bok ? bgrow : (N - 1);
    uint32_t so_b = (uint32_t)(brow * 80 + bhalf * 32);
    const char* gBh = (const char*)(Bh + (size_t)browc * K + bhalf * 16);
    const char* gBl = (const char*)(Bl + (size_t)browc * K + bhalf * 16);
    int bsz = bok ? 16 : 0;

    uint32_t aoff = (uint32_t)(((wm * (MT * 16) + (lane & 15)) * RS + ((lane >> 4) & 1) * 8) * 2);
    uint32_t boff = (uint32_t)(((wn * 32 + ((lane >> 4) & 1) * 8 + (lane & 7)) * RS
                                + ((lane >> 3) & 1) * 8) * 2);

    float acc[MT][4][4] = {};
    int nCh = K >> 5;

    {
        uint32_t s0 = sb;
        #pragma unroll
        for (int g = 0; g < 2; g++) {
            if (g < acpa_n) {
                cpa16(s0 + so_a + g * 16,       gAh + g * 16, 16);
                cpa16(s0 + ABY + so_a + g * 16, gAl + g * 16, 16);
            }
        }
        cpa16(s0 + 2 * ABY + so_b,            gBh, bsz);
        cpa16(s0 + 2 * ABY + so_b + 16,       gBh + 16, bsz);
        cpa16(s0 + 2 * ABY + BBY + so_b,      gBl, bsz);
        cpa16(s0 + 2 * ABY + BBY + so_b + 16, gBl + 16, bsz);
        cpa_commit();
    }

    for (int s = 0; s < nCh; s++) {
        cpa_wait0();
        __syncthreads();

        if (s + 1 < nCh) {
            uint32_t s1 = sb + (uint32_t)((s + 1) & 1) * STG;
            int kb = (s + 1) * 64;
            #pragma unroll
            for (int g = 0; g < 2; g++) {
                if (g < acpa_n) {
                    cpa16(s1 + so_a + g * 16,       gAh + kb + g * 16, 16);
                    cpa16(s1 + ABY + so_a + g * 16, gAl + kb + g * 16, 16);
                }
            }
            cpa16(s1 + 2 * ABY + so_b,            gBh + kb, bsz);
            cpa16(s1 + 2 * ABY + so_b + 16,       gBh + kb + 16, bsz);
            cpa16(s1 + 2 * ABY + BBY + so_b,      gBl + kb, bsz);
            cpa16(s1 + 2 * ABY + BBY + so_b + 16, gBl + kb + 16, bsz);
            cpa_commit();
        }

        uint32_t st = sb + (uint32_t)(s & 1) * STG;
        uint32_t uAh = st, uAl = st + ABY, uBh = st + 2 * ABY, uBl = st + 2 * ABY + BBY;
        #pragma unroll
        for (int ks = 0; ks < 2; ks++) {
            uint32_t k2 = (uint32_t)(ks * 32);
            uint32_t aH[MT][4], aL[MT][4], bH[2][4], bL[2][4];
            #pragma unroll
            for (int mt = 0; mt < MT; mt++) ldmx4(aH[mt], uAh + aoff + mt * (16 * RS * 2) + k2);
            #pragma unroll
            for (int np = 0; np < 2; np++) ldmx4(bH[np], uBh + boff + np * (16 * RS * 2) + k2);
            #pragma unroll
            for (int mt = 0; mt < MT; mt++)
                #pragma unroll
                for (int nt = 0; nt < 4; nt++)
                    mma_bf16(acc[mt][nt], aH[mt], &bH[nt >> 1][(nt & 1) * 2]);
            #pragma unroll
            for (int np = 0; np < 2; np++) ldmx4(bL[np], uBl + boff + np * (16 * RS * 2) + k2);
            #pragma unroll
            for (int mt = 0; mt < MT; mt++)
                #pragma unroll
                for (int nt = 0; nt < 4; nt++)
                    mma_bf16(acc[mt][nt], aH[mt], &bL[nt >> 1][(nt & 1) * 2]);
            #pragma unroll
            for (int mt = 0; mt < MT; mt++) ldmx4(aL[mt], uAl + aoff + mt * (16 * RS * 2) + k2);
            #pragma unroll
            for (int mt = 0; mt < MT; mt++)
                #pragma unroll
                for (int nt = 0; nt < 4; nt++)
                    mma_bf16(acc[mt][nt], aL[mt], &bH[nt >> 1][(nt & 1) * 2]);
        }
    }

    #pragma unroll
    for (int mt = 0; mt < MT; mt++) {
        int rw = bm + wm * (MT * 16) + mt * 16 + (lane >> 2);
        #pragma unroll
        for (int nt = 0; nt < 4; nt++) {
            int col = bn + wn * 32 + nt * 8 + (lane & 3) * 2;
            if (col < N) {
                float* c = acc[mt][nt];
                float v0 = c[0], v1 = c[1], v2 = c[2], v3 = c[3];
                if (EPI == 1) {
                    float2 r0 = *(const float2*)(R + (size_t)rw * N + col);
                    float2 r1 = *(const float2*)(R + (size_t)(rw + 8) * N + col);
                    v0 += r0.x; v1 += r0.y; v2 += r1.x; v3 += r1.y;
                }
                if (EPI == 2) {
                    v0 = fmaxf(v0, 0.f); v0 *= v0;
                    v1 = fmaxf(v1, 0.f); v1 *= v1;
                    v2 = fmaxf(v2, 0.f); v2 *= v2;
                    v3 = fmaxf(v3, 0.f); v3 *= v3;
                    __nv_bfloat162 hh0 = __floats2bfloat162_rn(v0, v1);
                    __nv_bfloat162 ll0 = __floats2bfloat162_rn(v0 - __bfloat162float(hh0.x),
                                                               v1 - __bfloat162float(hh0.y));
                    __nv_bfloat162 hh1 = __floats2bfloat162_rn(v2, v3);
                    __nv_bfloat162 ll1 = __floats2bfloat162_rn(v2 - __bfloat162float(hh1.x),
                                                               v3 - __bfloat162float(hh1.y));
                    size_t o0 = (size_t)rw * N + col;
                    size_t o1 = (size_t)(rw + 8) * N + col;
                    *(uint32_t*)((char*)Oh + o0 * 2) = *(uint32_t*)&hh0;
                    *(uint32_t*)((char*)Ol + o0 * 2) = *(uint32_t*)&ll0;
                    *(uint32_t*)((char*)Oh + o1 * 2) = *(uint32_t*)&hh1;
                    *(uint32_t*)((char*)Ol + o1 * 2) = *(uint32_t*)&ll1;
                } else {
                    *(float2*)(C + (size_t)rw * N + col) = make_float2(v0, v1);
                    *(float2*)(C + (size_t)(rw + 8) * N + col) = make_float2(v2, v3);
                }
            }
        }
    }
}

#define GSMEM_128 (2 * (2 * 128 * RS * 2 + 2 * 128 * RS * 2))
#define GSMEM_64  (2 * (2 * 64 * RS * 2 + 2 * 128 * RS * 2))

// ================= fp16 2-pass GEMM: C = (Ah+Al) @ B^T, B single fp16 plane =================
#define ABYF 10240
#define BBYF 10240
#define STGF (2 * ABYF + BBYF)
#define GSMEM_F16 (2 * STGF)

__global__ void __launch_bounds__(256, 2)
gemm_f16_2p_kernel(const __half* __restrict__ Ah, const __half* __restrict__ Al,
                   const __half* __restrict__ Bh, float* __restrict__ C,
                   int M, int N, int K) {
    extern __shared__ char gsm[];
    int tid = threadIdx.x, lane = tid & 31, wid = tid >> 5;
    int wm = wid >> 2, wn = wid & 3;
    int bm = blockIdx.y * 128, bn = blockIdx.x * 128;

    uint32_t sb = smem_u32(gsm);

    int arow = tid >> 1, ahalf = tid & 1;
    uint32_t so_a = (uint32_t)(arow * 80 + ahalf * 32);
    const char* gAh = (const char*)(Ah + (size_t)(bm + arow) * K + ahalf * 16);
    const char* gAl = (const char*)(Al + (size_t)(bm + arow) * K + ahalf * 16);

    int bgrow = bn + arow;
    bool bok = bgrow < N;
    int browc = bok ? bgrow : (N - 1);
    const char* gBh = (const char*)(Bh + (size_t)browc * K + ahalf * 16);
    int bsz = bok ? 16 : 0;

    uint32_t aoff = (uint32_t)(((wm * 64 + (lane & 15)) * RS + ((lane >> 4) & 1) * 8) * 2);
    uint32_t boff = (uint32_t)(((wn * 32 + ((lane >> 4) & 1) * 8 + (lane & 7)) * RS
                                + ((lane >> 3) & 1) * 8) * 2);

    float acc[4][4][4] = {};
    int nCh = K >> 5;

    {
        uint32_t s0 = sb;
        cpa16(s0 + so_a,               gAh, 16);
        cpa16(s0 + so_a + 16,          gAh + 16, 16);
        cpa16(s0 + ABYF + so_a,        gAl, 16);
        cpa16(s0 + ABYF + so_a + 16,   gAl + 16, 16);
        cpa16(s0 + 2 * ABYF + so_a,      gBh, bsz);
        cpa16(s0 + 2 * ABYF + so_a + 16, gBh + 16, bsz);
        cpa_commit();
    }

    for (int s = 0; s < nCh; s++) {
        cpa_wait0();
        __syncthreads();

        if (s + 1 < nCh) {
            uint32_t s1 = sb + (uint32_t)((s + 1) & 1) * STGF;
            int kb = (s + 1) * 64;
            cpa16(s1 + so_a,               gAh + kb, 16);
            cpa16(s1 + so_a + 16,          gAh + kb + 16, 16);
            cpa16(s1 + ABYF + so_a,        gAl + kb, 16);
            cpa16(s1 + ABYF + so_a + 16,   gAl + kb + 16, 16);
            cpa16(s1 + 2 * ABYF + so_a,      gBh + kb, bsz);
            cpa16(s1 + 2 * ABYF + so_a + 16, gBh + kb + 16, bsz);
            cpa_commit();
        }

        uint32_t st = sb + (uint32_t)(s & 1) * STGF;
        uint32_t uAh = st, uAl = st + ABYF, uB = st + 2 * ABYF;
        #pragma unroll
        for (int ks = 0; ks < 2; ks++) {
            uint32_t k2 = (uint32_t)(ks * 32);
            uint32_t aH[4][4], aL[4][4], bH[2][4];
            #pragma unroll
            for (int mt = 0; mt < 4; mt++) ldmx4(aH[mt], uAh + aoff + mt * (16 * RS * 2) + k2);
            #pragma unroll
            for (int np = 0; np < 2; np++) ldmx4(bH[np], uB + boff + np * (16 * RS * 2) + k2);
            #pragma unroll
            for (int mt = 0; mt < 4; mt++)
                #pragma unroll
                for (int nt = 0; nt < 4; nt++)
                    mma_f16(acc[mt][nt], aH[mt], &bH[nt >> 1][(nt & 1) * 2]);
            #pragma unroll
            for (int mt = 0; mt < 4; mt++) ldmx4(aL[mt], uAl + aoff + mt * (16 * RS * 2) + k2);
            #pragma unroll
            for (int mt = 0; mt < 4; mt++)
                #pragma unroll
                for (int nt = 0; nt < 4; nt++)
                    mma_f16(acc[mt][nt], aL[mt], &bH[nt >> 1][(nt & 1) * 2]);
        }
    }

    #pragma unroll
    for (int mt = 0; mt < 4; mt++) {
        int rw = bm + wm * 64 + mt * 16 + (lane >> 2);
        #pragma unroll
        for (int nt = 0; nt < 4; nt++) {
            int col = bn + wn * 32 + nt * 8 + (lane & 3) * 2;
            if (col < N) {
                float* c = acc[mt][nt];
                *(float2*)(C + (size_t)rw * N + col) = make_float2(c[0], c[1]);
                *(float2*)(C + (size_t)(rw + 8) * N + col) = make_float2(c[2], c[3]);
            }
        }
    }
}

// ---------------- host launcher ----------------
extern "C" void kernel_launch(void* const* d_in, const int* in_sizes, int n_in,
                              void* d_out, int out_size) {
    const int*   ids  = (const int*)d_in[0];
    const float* wte  = (const float*)d_in[1];
    const float* wqkv = (const float*)d_in[2];
    const float* wo   = (const float*)d_in[3];
    const float* w1   = (const float*)d_in[4];
    const float* w2   = (const float*)d_in[5];
    const float* lm   = (const float*)d_in[6];
    float* out = (float*)d_out;

    float *px, *pqkv, *pcos, *psin;
    __nv_bfloat16 *pwh, *pwl, *psh, *psl, *phh, *phl, *pah, *pal, *pmh, *pml;
    cudaGetSymbolAddress((void**)&px,   g_x);
    cudaGetSymbolAddress((void**)&pqkv, g_qkv);
    cudaGetSymbolAddress((void**)&pcos, g_cos);
    cudaGetSymbolAddress((void**)&psin, g_sin);
    cudaGetSymbolAddress((void**)&pwh,  g_wh);
    cudaGetSymbolAddress((void**)&pwl,  g_wl);
    cudaGetSymbolAddress((void**)&psh,  g_sh);
    cudaGetSymbolAddress((void**)&psl,  g_sl);
    cudaGetSymbolAddress((void**)&phh,  g_hh);
    cudaGetSymbolAddress((void**)&phl,  g_hl);
    cudaGetSymbolAddress((void**)&pah,  g_ah);
    cudaGetSymbolAddress((void**)&pal,  g_al);
    cudaGetSymbolAddress((void**)&pmh,  g_mh);
    cudaGetSymbolAddress((void**)&pml,  g_ml);

    cudaFuncSetAttribute(flash_attn_kernel,
                         cudaFuncAttributeMaxDynamicSharedMemorySize, FLASH_SMEM);
    cudaFuncSetAttribute(gemm_bf16_kernel<1, 64>,
                         cudaFuncAttributeMaxDynamicSharedMemorySize, GSMEM_64);
    cudaFuncSetAttribute(gemm_bf16_kernel<2, 128>,
                         cudaFuncAttributeMaxDynamicSharedMemorySize, GSMEM_128);
    cudaFuncSetAttribute(gemm_f16_2p_kernel,
                         cudaFuncAttributeMaxDynamicSharedMemorySize, GSMEM_F16);

    // ---- weight prep ----
    wsplit_f16_kernel<<<(unsigned)((25165824ULL / 4 + 255) / 256), 256>>>(
        (const float4*)wqkv, (uint32_t*)(pwh + OFF_WQKV), 25165824ULL / 4);
    wsplit_kernel<<<(unsigned)((8388608ULL / 4 + 255) / 256), 256>>>(
        (const float4*)wo, (uint32_t*)(pwh + OFF_WO), (uint32_t*)(pwl + OFF_WO), 8388608ULL / 4);
    wsplit_kernel<<<(unsigned)((33554432ULL / 4 + 255) / 256), 256>>>(
        (const float4*)w1, (uint32_t*)(pwh + OFF_W1), (uint32_t*)(pwl + OFF_W1), 33554432ULL / 4);
    wsplit_kernel<<<(unsigned)((33554432ULL / 4 + 255) / 256), 256>>>(
        (const float4*)w2, (uint32_t*)(pwh + OFF_W2), (uint32_t*)(pwl + OFF_W2), 33554432ULL / 4);
    wsplit_f16_kernel<<<(unsigned)((51478528ULL / 4 + 255) / 256), 256>>>(
        (const float4*)lm, (uint32_t*)(pwh + OFF_LM), 51478528ULL / 4);

    rope_init_kernel<<<SEQ, 32>>>(pcos, psin);
    embed_rmsnorm_kernel<<<SEQ, 256>>>(ids, wte, px);

    for (int l = 0; l < NL; l++) {
        __nv_bfloat16* wqkv_h = pwh + OFF_WQKV + (size_t)l * 3145728;   // fp16 plane
        __nv_bfloat16* wo_h = pwh + OFF_WO + (size_t)l * 1048576;
        __nv_bfloat16* wo_l2 = pwl + OFF_WO + (size_t)l * 1048576;
        __nv_bfloat16* w1_h = pwh + OFF_W1 + (size_t)l * 4194304;
        __nv_bfloat16* w1_l2 = pwl + OFF_W1 + (size_t)l * 4194304;
        __nv_bfloat16* w2_h = pwh + OFF_W2 + (size_t)l * 4194304;
        __nv_bfloat16* w2_l2 = pwl + OFF_W2 + (size_t)l * 4194304;

        rmsnorm_split_kernel<1><<<SEQ, 256>>>(px, phh, phl);   // fp16 planes
        gemm_f16_2p_kernel<<<dim3(24, 16), 256, GSMEM_F16>>>(
            (const __half*)phh, (const __half*)phl, (const __half*)wqkv_h,
            pqkv, SEQ, 3 * HIDDEN, HIDDEN);
        qknorm_rope_split_kernel<<<SEQ, 256>>>(pqkv, pcos, psin, psh, psl);
        flash_attn_kernel<<<dim3(SEQ / 64, NH), 128, FLASH_SMEM>>>(psh, psl, pah, pal);
        gemm_bf16_kernel<1, 64><<<dim3(8, 32), 256, GSMEM_64>>>(
            pah, pal, wo_h, wo_l2, px, px, nullptr, nullptr,
            SEQ, HIDDEN, HIDDEN);

        rmsnorm_split_kernel<0><<<SEQ, 256>>>(px, phh, phl);   // bf16 planes
        gemm_bf16_kernel<2, 128><<<dim3(32, 16), 256, GSMEM_128>>>(
            phh, phl, w1_h, w1_l2, nullptr, nullptr, pmh, pml,
            SEQ, FFN, HIDDEN);
        gemm_bf16_kernel<1, 64><<<dim3(8, 32), 256, GSMEM_64>>>(
            pmh, pml, w2_h, w2_l2, px, px, nullptr, nullptr,
            SEQ, HIDDEN, FFN);
    }

    rmsnorm_split_kernel<1><<<SEQ, 256>>>(px, phh, phl);       // fp16 planes
    gemm_f16_2p_kernel<<<dim3((VOCABSZ + 127) / 128, 16), 256, GSMEM_F16>>>(
        (const __half*)phh, (const __half*)phl, (const __half*)(pwh + OFF_LM),
        out, SEQ, VOCABSZ, HIDDEN);
}

// round 11
// speedup vs baseline: 2.7211x; 1.1616x over previous
#include <cuda_runtime.h>
#include <cuda_bf16.h>
#include <cuda_fp16.h>
#include <math.h>
#include <stdint.h>

#define SEQ     2048
#define HIDDEN  1024
#define NH      16
#define HD      64
#define NL      8
#define VOCABSZ 50272
#define FFN     4096
#define EPSV    1e-5f

#define OFF_WQKV 0ULL
#define OFF_WO   25165824ULL
#define OFF_W1   33554432ULL
#define OFF_W2   67108864ULL
#define OFF_LM   100663296ULL
#define W_TOTAL  152141824ULL

// ---------------- scratch ----------------
__device__ float g_x  [(size_t)SEQ * HIDDEN];
__device__ float g_qkv[(size_t)SEQ * 3 * HIDDEN];
__device__ float g_cos[(size_t)SEQ * (HD / 2)];
__device__ float g_sin[(size_t)SEQ * (HD / 2)];
__device__ __nv_bfloat16 g_wh[W_TOTAL];          // fp16 (wqkv,w1,w2,lm) or bf16-hi (wo)
__device__ __nv_bfloat16 g_wl[W_TOTAL];          // bf16-lo (wo only)
__device__ __nv_bfloat16 g_sh[(size_t)SEQ * 3 * HIDDEN], g_sl[(size_t)SEQ * 3 * HIDDEN];
__device__ __nv_bfloat16 g_hh[(size_t)SEQ * HIDDEN], g_hl[(size_t)SEQ * HIDDEN];  // fp16 planes
__device__ __nv_bfloat16 g_ah[(size_t)SEQ * HIDDEN], g_al[(size_t)SEQ * HIDDEN];  // bf16 planes
__device__ __nv_bfloat16 g_mh[(size_t)SEQ * FFN],    g_ml[(size_t)SEQ * FFN];     // fp16 planes

// ---------------- helpers ----------------
__device__ __forceinline__ uint32_t smem_u32(const void* p) {
    uint32_t a;
    asm("{ .reg .u64 t; cvta.to.shared.u64 t, %1; cvt.u32.u64 %0, t; }" : "=r"(a) : "l"(p));
    return a;
}
__device__ __forceinline__ float warpSum(float v) {
    #pragma unroll
    for (int o = 16; o; o >>= 1) v += __shfl_xor_sync(0xffffffffu, v, o);
    return v;
}
__device__ __forceinline__ float blockReduceSum(float v, float* red) {
    int lane = threadIdx.x & 31, w = threadIdx.x >> 5;
    v = warpSum(v);
    if (lane == 0) red[w] = v;
    __syncthreads();
    if (w == 0) {
        float r = (lane < (int)(blockDim.x >> 5)) ? red[lane] : 0.0f;
        r = warpSum(r);
        if (lane == 0) red[0] = r;
    }
    __syncthreads();
    float out = red[0];
    __syncthreads();
    return out;
}
__device__ __forceinline__ void mma_bf16(float* c, const uint32_t* a, const uint32_t* b) {
    asm volatile(
        "mma.sync.aligned.m16n8k16.row.col.f32.bf16.bf16.f32 "
        "{%0,%1,%2,%3}, {%4,%5,%6,%7}, {%8,%9}, {%0,%1,%2,%3};"
        : "+f"(c[0]), "+f"(c[1]), "+f"(c[2]), "+f"(c[3])
        : "r"(a[0]), "r"(a[1]), "r"(a[2]), "r"(a[3]), "r"(b[0]), "r"(b[1]));
}
__device__ __forceinline__ void mma_f16(float* c, const uint32_t* a, const uint32_t* b) {
    asm volatile(
        "mma.sync.aligned.m16n8k16.row.col.f32.f16.f16.f32 "
        "{%0,%1,%2,%3}, {%4,%5,%6,%7}, {%8,%9}, {%0,%1,%2,%3};"
        : "+f"(c[0]), "+f"(c[1]), "+f"(c[2]), "+f"(c[3])
        : "r"(a[0]), "r"(a[1]), "r"(a[2]), "r"(a[3]), "r"(b[0]), "r"(b[1]));
}
__device__ __forceinline__ void ldmx4(uint32_t* d, uint32_t addr) {
    asm volatile("ldmatrix.sync.aligned.m8n8.x4.shared.b16 {%0,%1,%2,%3}, [%4];"
                 : "=r"(d[0]), "=r"(d[1]), "=r"(d[2]), "=r"(d[3]) : "r"(addr));
}
__device__ __forceinline__ void ldmx4t(uint32_t* d, uint32_t addr) {
    asm volatile("ldmatrix.sync.aligned.m8n8.x4.trans.shared.b16 {%0,%1,%2,%3}, [%4];"
                 : "=r"(d[0]), "=r"(d[1]), "=r"(d[2]), "=r"(d[3]) : "r"(addr));
}
__device__ __forceinline__ void split4(float4 f, uint2& h, uint2& l) {
    __nv_bfloat162 h0 = __floats2bfloat162_rn(f.x, f.y);
    __nv_bfloat162 h1 = __floats2bfloat162_rn(f.z, f.w);
    __nv_bfloat162 l0 = __floats2bfloat162_rn(f.x - __bfloat162float(h0.x),
                                              f.y - __bfloat162float(h0.y));
    __nv_bfloat162 l1 = __floats2bfloat162_rn(f.z - __bfloat162float(h1.x),
                                              f.w - __bfloat162float(h1.y));
    h.x = *(uint32_t*)&h0; h.y = *(uint32_t*)&h1;
    l.x = *(uint32_t*)&l0; l.y = *(uint32_t*)&l1;
}
__device__ __forceinline__ void cpa16(uint32_t s, const void* g, int srcsz) {
    asm volatile("cp.async.cg.shared.global [%0], [%1], 16, %2;"
                 :: "r"(s), "l"(g), "r"(srcsz) : "memory");
}
__device__ __forceinline__ void cpa_commit() {
    asm volatile("cp.async.commit_group;" ::: "memory");
}
__device__ __forceinline__ void cpa_wait0() {
    asm volatile("cp.async.wait_group 0;" ::: "memory");
}

// ---------------- weight prep ----------------
__global__ void wsplit_kernel(const float4* __restrict__ src, uint32_t* __restrict__ dh,
                              uint32_t* __restrict__ dl, size_t n4) {
    size_t i = (size_t)blockIdx.x * blockDim.x + threadIdx.x;
    if (i < n4) {
        uint2 h, l;
        split4(src[i], h, l);
        dh[2 * i] = h.x; dh[2 * i + 1] = h.y;
        dl[2 * i] = l.x; dl[2 * i + 1] = l.y;
    }
}
__global__ void wsplit_f16_kernel(const float4* __restrict__ src, uint32_t* __restrict__ d,
                                  size_t n4) {
    size_t i = (size_t)blockIdx.x * blockDim.x + threadIdx.x;
    if (i < n4) {
        float4 f = src[i];
        __half2 h0 = __floats2half2_rn(f.x, f.y);
        __half2 h1 = __floats2half2_rn(f.z, f.w);
        d[2 * i] = *(uint32_t*)&h0;
        d[2 * i + 1] = *(uint32_t*)&h1;
    }
}

// ---------------- embedding + rmsnorm ----------------
__global__ void embed_rmsnorm_kernel(const int* __restrict__ ids,
                                     const float* __restrict__ wte,
                                     float* __restrict__ out) {
    __shared__ float red[32];
    int t = blockIdx.x;
    const float* row = wte + (size_t)ids[t] * HIDDEN;
    float v[4]; float ss = 0.0f;
    #pragma unroll
    for (int i = 0; i < 4; i++) { v[i] = row[threadIdx.x + i * 256]; ss += v[i] * v[i]; }
    ss = blockReduceSum(ss, red);
    float sc = rsqrtf(ss * (1.0f / HIDDEN) + EPSV);
    #pragma unroll
    for (int i = 0; i < 4; i++)
        out[(size_t)t * HIDDEN + threadIdx.x + i * 256] = v[i] * sc;
}

// ---------------- rmsnorm: fp32 in -> fp16 hi/lo planes ----------------
__global__ void rmsnorm_split_kernel(const float* __restrict__ in,
                                     __nv_bfloat16* __restrict__ oh,
                                     __nv_bfloat16* __restrict__ ol) {
    __shared__ float red[32];
    int t = blockIdx.x;
    const float* row = in + (size_t)t * HIDDEN;
    float v[4]; float ss = 0.0f;
    #pragma unroll
    for (int i = 0; i < 4; i++) {
        int idx = 2 * threadIdx.x + (i & 1) + (i >> 1) * 512;
        v[i] = row[idx];
        ss += v[i] * v[i];
    }
    ss = blockReduceSum(ss, red);
    float sc = rsqrtf(ss * (1.0f / HIDDEN) + EPSV);
    #pragma unroll
    for (int p = 0; p < 2; p++) {
        float a = v[2 * p] * sc, b = v[2 * p + 1] * sc;
        __half2 hh = __floats2half2_rn(a, b);
        __half2 ll = __floats2half2_rn(a - __half2float(hh.x),
                                       b - __half2float(hh.y));
        size_t off = (size_t)t * HIDDEN + 2 * threadIdx.x + p * 512;
        *(uint32_t*)((char*)oh + off * 2) = *(uint32_t*)&hh;
        *(uint32_t*)((char*)ol + off * 2) = *(uint32_t*)&ll;
    }
}

// ---------------- rope tables ----------------
__global__ void rope_init_kernel(float* __restrict__ ctab, float* __restrict__ stab) {
    int t = blockIdx.x, i = threadIdx.x;
    float invf = (float)pow(10000.0, -(double)(2 * i) / (double)HD);
    float ang = (float)t * invf;
    float s, c;
    sincosf(ang, &s, &c);
    ctab[t * 32 + i] = c;
    stab[t * 32 + i] = s;
}

// ---------------- per-token: qk rmsnorm+rope+split(bf16), v split. grid SEQ, 256 thr ----------------
__global__ void qknorm_rope_split_kernel(const float* __restrict__ qkv,
                                         const float* __restrict__ ctab,
                                         const float* __restrict__ stab,
                                         __nv_bfloat16* __restrict__ oh,
                                         __nv_bfloat16* __restrict__ ol) {
    int t = blockIdx.x, tid = threadIdx.x, lane = tid & 31, wid = tid >> 5;
    float cc = ctab[t * 32 + lane], ssn = stab[t * 32 + lane];
    #pragma unroll
    for (int task = wid; task < 32; task += 8) {
        int h = task & 15, wv = task >> 4;
        size_t base = (size_t)t * (3 * HIDDEN) + (size_t)wv * HIDDEN + h * HD;
        float2 x = *(const float2*)(qkv + base + 2 * lane);
        float ss = warpSum(x.x * x.x + x.y * x.y);
        float sc = rsqrtf(ss * (1.0f / HD) + EPSV);
        float x0 = x.x * sc, x1 = x.y * sc;
        float y0 = x1 * cc - x0 * ssn;
        float y1 = x1 * ssn + x0 * cc;
        __nv_bfloat162 hh = __floats2bfloat162_rn(y0, y1);
        __nv_bfloat162 ll = __floats2bfloat162_rn(y0 - __bfloat162float(hh.x),
                                                  y1 - __bfloat162float(hh.y));
        *(uint32_t*)((char*)oh + (base + 2 * lane) * 2) = *(uint32_t*)&hh;
        *(uint32_t*)((char*)ol + (base + 2 * lane) * 2) = *(uint32_t*)&ll;
    }
    size_t vb = (size_t)t * (3 * HIDDEN) + 2 * HIDDEN;
    float4 v = *(const float4*)(qkv + vb + tid * 4);
    uint2 h, l;
    split4(v, h, l);
    *(uint2*)((char*)oh + (vb + tid * 4) * 2) = h;
    *(uint2*)((char*)ol + (vb + tid * 4) * 2) = l;
}

// ================= fused flash attention (pre-split bf16, cp.async pipelined) =================
#define FRS       72
#define FT_BYTES  (64 * FRS * 2)
#define KV_STAGE  (4 * FT_BYTES)
#define FLASH_SMEM (2 * FT_BYTES + 2 * KV_STAGE)

__global__ void __launch_bounds__(128, 2)
flash_attn_kernel(const __nv_bfloat16* __restrict__ qh_g,
                  const __nv_bfloat16* __restrict__ ql_g,
                  __nv_bfloat16* __restrict__ outh, __nv_bfloat16* __restrict__ outl) {
    extern __shared__ char fsm[];
    uint32_t sb = smem_u32(fsm);
    uint32_t uQh = sb, uQl = sb + FT_BYTES;

    int tid = threadIdx.x, lane = tid & 31, wid = tid >> 5;
    int h = blockIdx.y;
    int qt = (int)gridDim.x - 1 - (int)blockIdx.x;
    int bm = qt * 64;

    int r = tid >> 1, c0 = (tid & 1) * 32;
    uint32_t soff = (uint32_t)(r * (FRS * 2) + c0 * 2);

    {
        const char* gQh = (const char*)(qh_g + (size_t)(bm + r) * (3 * HIDDEN) + h * HD + c0);
        const char* gQl = (const char*)(ql_g + (size_t)(bm + r) * (3 * HIDDEN) + h * HD + c0);
        #pragma unroll
        for (int g = 0; g < 4; g++) {
            cpa16(uQh + soff + g * 16, gQh + g * 16, 16);
            cpa16(uQl + soff + g * 16, gQl + g * 16, 16);
        }
        const char* gKh = (const char*)(qh_g + (size_t)r * (3 * HIDDEN) + HIDDEN + h * HD + c0);
        const char* gKl = (const char*)(ql_g + (size_t)r * (3 * HIDDEN) + HIDDEN + h * HD + c0);
        uint32_t st = sb + 2 * FT_BYTES;
        #pragma unroll
        for (int g = 0; g < 4; g++) {
            cpa16(st + soff + g * 16,                gKh + g * 16, 16);
            cpa16(st + FT_BYTES + soff + g * 16,     gKl + g * 16, 16);
            cpa16(st + 2 * FT_BYTES + soff + g * 16, gKh + HIDDEN * 2 + g * 16, 16);
            cpa16(st + 3 * FT_BYTES + soff + g * 16, gKl + HIDDEN * 2 + g * 16, 16);
        }
        cpa_commit();
    }

    uint32_t qh[4][4], ql[4][4];
    float o[8][4] = {};
    float m[2] = {-INFINITY, -INFINITY};
    float l[2] = {0.0f, 0.0f};

    for (int jt = 0; jt <= qt; jt++) {
        cpa_wait0();
        __syncthreads();

        if (jt == 0) {
            uint32_t qoff = (uint32_t)(((wid * 16 + (lane & 15)) * FRS + ((lane >> 4) & 1) * 8) * 2);
            #pragma unroll
            for (int ks = 0; ks < 4; ks++) {
                ldmx4(qh[ks], uQh + qoff + ks * 32);
                ldmx4(ql[ks], uQl + qoff + ks * 32);
            }
        }
        if (jt + 1 <= qt) {
            const char* gKh = (const char*)(qh_g + (size_t)((jt + 1) * 64 + r) * (3 * HIDDEN) + HIDDEN + h * HD + c0);
            const char* gKl = (const char*)(ql_g + (size_t)((jt + 1) * 64 + r) * (3 * HIDDEN) + HIDDEN + h * HD + c0);
            uint32_t st = sb + 2 * FT_BYTES + (uint32_t)((jt + 1) & 1) * KV_STAGE;
            #pragma unroll
            for (int g = 0; g < 4; g++) {
                cpa16(st + soff + g * 16,                gKh + g * 16, 16);
                cpa16(st + FT_BYTES + soff + g * 16,     gKl + g * 16, 16);
                cpa16(st + 2 * FT_BYTES + soff + g * 16, gKh + HIDDEN * 2 + g * 16, 16);
                cpa16(st + 3 * FT_BYTES + soff + g * 16, gKl + HIDDEN * 2 + g * 16, 16);
            }
            cpa_commit();
        }

        uint32_t stg = sb + 2 * FT_BYTES + (uint32_t)(jt & 1) * KV_STAGE;
        uint32_t uKh = stg, uKl = stg + FT_BYTES, uVh = stg + 2 * FT_BYTES, uVl = stg + 3 * FT_BYTES;

        float s[8][4] = {};
        uint32_t bbase = (uint32_t)(((((lane >> 4) & 1) * 8 + (lane & 7)) * FRS
                                     + ((lane >> 3) & 1) * 8) * 2);
        #pragma unroll
        for (int ks = 0; ks < 4; ks++) {
            #pragma unroll
            for (int nb = 0; nb < 4; nb++) {
                uint32_t kh[4], kl[4];
                uint32_t bo = bbase + (uint32_t)(nb * 16 * FRS * 2) + (uint32_t)(ks * 32);
                ldmx4(kh, uKh + bo);
                ldmx4(kl, uKl + bo);
                mma_bf16(s[nb * 2],     qh[ks], kh + 0);
                mma_bf16(s[nb * 2 + 1], qh[ks], kh + 2);
                mma_bf16(s[nb * 2],     qh[ks], kl + 0);
                mma_bf16(s[nb * 2 + 1], qh[ks], kl + 2);
                mma_bf16(s[nb * 2],     ql[ks], kh + 0);
                mma_bf16(s[nb * 2 + 1], ql[ks], kh + 2);
            }
        }
        #pragma unroll
        for (int nt = 0; nt < 8; nt++)
            #pragma unroll
            for (int c = 0; c < 4; c++) s[nt][c] *= 0.125f;

        if (jt == qt) {
            int q0 = wid * 16 + (lane >> 2);
            int q1 = q0 + 8;
            #pragma unroll
            for (int nt = 0; nt < 8; nt++) {
                int j0 = nt * 8 + (lane & 3) * 2;
                if (j0     > q0) s[nt][0] = -INFINITY;
                if (j0 + 1 > q0) s[nt][1] = -INFINITY;
                if (j0     > q1) s[nt][2] = -INFINITY;
                if (j0 + 1 > q1) s[nt][3] = -INFINITY;
            }
        }

        #pragma unroll
        for (int hh = 0; hh < 2; hh++) {
            float rm = -INFINITY;
            #pragma unroll
            for (int nt = 0; nt < 8; nt++)
                rm = fmaxf(rm, fmaxf(s[nt][2 * hh], s[nt][2 * hh + 1]));
            rm = fmaxf(rm, __shfl_xor_sync(0xffffffffu, rm, 1));
            rm = fmaxf(rm, __shfl_xor_sync(0xffffffffu, rm, 2));
            float mnew = fmaxf(m[hh], rm);
            float corr = __expf(m[hh] - mnew);
            float rs = 0.0f;
            #pragma unroll
            for (int nt = 0; nt < 8; nt++) {
                float p0 = __expf(s[nt][2 * hh]     - mnew);
                float p1 = __expf(s[nt][2 * hh + 1] - mnew);
                s[nt][2 * hh] = p0; s[nt][2 * hh + 1] = p1;
                rs += p0 + p1;
            }
            rs += __shfl_xor_sync(0xffffffffu, rs, 1);
            rs += __shfl_xor_sync(0xffffffffu, rs, 2);
            l[hh] = l[hh] * corr + rs;
            m[hh] = mnew;
            #pragma unroll
            for (int dt = 0; dt < 8; dt++) {
                o[dt][2 * hh] *= corr; o[dt][2 * hh + 1] *= corr;
            }
        }

        #pragma unroll
        for (int jks = 0; jks < 4; jks++) {
            float* ce = s[2 * jks];
            float* co = s[2 * jks + 1];
            uint32_t pa[4], pb[4];
            {
                __nv_bfloat162 h0 = __floats2bfloat162_rn(ce[0], ce[1]);
                __nv_bfloat162 h1 = __floats2bfloat162_rn(ce[2], ce[3]);
                __nv_bfloat162 h2 = __floats2bfloat162_rn(co[0], co[1]);
                __nv_bfloat162 h3 = __floats2bfloat162_rn(co[2], co[3]);
                pa[0] = *(uint32_t*)&h0; pa[1] = *(uint32_t*)&h1;
                pa[2] = *(uint32_t*)&h2; pa[3] = *(uint32_t*)&h3;
                __nv_bfloat162 e0 = __floats2bfloat162_rn(ce[0] - __bfloat162float(h0.x),
                                                          ce[1] - __bfloat162float(h0.y));
                __nv_bfloat162 e1 = __floats2bfloat162_rn(ce[2] - __bfloat162float(h1.x),
                                                          ce[3] - __bfloat162float(h1.y));
                __nv_bfloat162 e2 = __floats2bfloat162_rn(co[0] - __bfloat162float(h2.x),
                                                          co[1] - __bfloat162float(h2.y));
                __nv_bfloat162 e3 = __floats2bfloat162_rn(co[2] - __bfloat162float(h3.x),
                                                          co[3] - __bfloat162float(h3.y));
                pb[0] = *(uint32_t*)&e0; pb[1] = *(uint32_t*)&e1;
                pb[2] = *(uint32_t*)&e2; pb[3] = *(uint32_t*)&e3;
            }
            uint32_t vbase = (uint32_t)(((jks * 16 + (lane & 15)) * FRS
                                         + ((lane >> 4) & 1) * 8) * 2);
            #pragma unroll
            for (int db = 0; db < 4; db++) {
                uint32_t vh[4], vl[4];
                uint32_t vo = vbase + (uint32_t)(db * 32);
                ldmx4t(vh, uVh + vo);
                ldmx4t(vl, uVl + vo);
                mma_bf16(o[db * 2],     pa, vh + 0);
                mma_bf16(o[db * 2 + 1], pa, vh + 2);
                mma_bf16(o[db * 2],     pa, vl + 0);
                mma_bf16(o[db * 2 + 1], pa, vl + 2);
                mma_bf16(o[db * 2],     pb, vh + 0);
                mma_bf16(o[db * 2 + 1], pb, vh + 2);
            }
        }
    }

    float inv0 = 1.0f / l[0], inv1 = 1.0f / l[1];
    int row0 = bm + wid * 16 + (lane >> 2);
    #pragma unroll
    for (int dt = 0; dt < 8; dt++) {
        int col = h * HD + dt * 8 + (lane & 3) * 2;
        float a0 = o[dt][0] * inv0, b0 = o[dt][1] * inv0;
        float a1 = o[dt][2] * inv1, b1 = o[dt][3] * inv1;
        __nv_bfloat162 hh0 = __floats2bfloat162_rn(a0, b0);
        __nv_bfloat162 ll0 = __floats2bfloat162_rn(a0 - __bfloat162float(hh0.x),
                                                   b0 - __bfloat162float(hh0.y));
        __nv_bfloat162 hh1 = __floats2bfloat162_rn(a1, b1);
        __nv_bfloat162 ll1 = __floats2bfloat162_rn(a1 - __bfloat162float(hh1.x),
                                                   b1 - __bfloat162float(hh1.y));
        size_t off0 = (size_t)row0 * HIDDEN + col;
        size_t off1 = (size_t)(row0 + 8) * HIDDEN + col;
        *(uint32_t*)((char*)outh + off0 * 2) = *(uint32_t*)&hh0;
        *(uint32_t*)((char*)outl + off0 * 2) = *(uint32_t*)&ll0;
        *(uint32_t*)((char*)outh + off1 * 2) = *(uint32_t*)&hh1;
        *(uint32_t*)((char*)outl + off1 * 2) = *(uint32_t*)&ll1;
    }
}

// ================= bf16-split 3-pass GEMM (wo only) =================
#define RS 40

template <int EPI, int BM>
__global__ void __launch_bounds__(256, 2)
gemm_bf16_kernel(const __nv_bfloat16* __restrict__ Ah, const __nv_bfloat16* __restrict__ Al,
                 const __nv_bfloat16* __restrict__ Bh, const __nv_bfloat16* __restrict__ Bl,
                 float* __restrict__ C, const float* __restrict__ R,
                 int M, int N, int K) {
    constexpr int MT = (BM == 128) ? 4 : 2;
    constexpr int ABY = BM * RS * 2;
    constexpr int BBY = 128 * RS * 2;
    constexpr int STG = 2 * ABY + 2 * BBY;

    extern __shared__ char gsm[];
    int tid = threadIdx.x, lane = tid & 31, wid = tid >> 5;
    int wm = wid >> 2, wn = wid & 3;
    int bm = blockIdx.y * BM, bn = blockIdx.x * 128;

    uint32_t sb = smem_u32(gsm);

    int arow, acpa_n; uint32_t so_a; const char *gAh, *gAl;
    if (BM == 128) {
        arow = tid >> 1; int half = tid & 1; acpa_n = 2;
        so_a = (uint32_t)(arow * 80 + half * 32);
        gAh = (const char*)(Ah + (size_t)(bm + arow) * K + half * 16);
        gAl = (const char*)(Al + (size_t)(bm + arow) * K + half * 16);
    } else {
        arow = tid >> 2; int seg = tid & 3; acpa_n = 1;
        so_a = (uint32_t)(arow * 80 + seg * 16);
        gAh = (const char*)(Ah + (size_t)(bm + arow) * K + seg * 8);
        gAl = (const char*)(Al + (size_t)(bm + arow) * K + seg * 8);
    }
    int brow = tid >> 1, bhalf = tid & 1;
    int bgrow = bn + brow;
    bool bok = bgrow < N;
    int browc = bok ? bgrow : (N - 1);
    uint32_t so_b = (uint32_t)(brow * 80 + bhalf * 32);
    const char* gBh = (const char*)(Bh + (size_t)browc * K + bhalf * 16);
    const char* gBl = (const char*)(Bl + (size_t)browc * K + bhalf * 16);
    int bsz = bok ? 16 : 0;

    uint32_t aoff = (uint32_t)(((wm * (MT * 16) + (lane & 15)) * RS + ((lane >> 4) & 1) * 8) * 2);
    uint32_t boff = (uint32_t)(((wn * 32 + ((lane >> 4) & 1) * 8 + (lane & 7)) * RS
                                + ((lane >> 3) & 1) * 8) * 2);

    float acc[MT][4][4] = {};
    int nCh = K >> 5;

    {
        uint32_t s0 = sb;
        #pragma unroll
        for (int g = 0; g < 2; g++) {
            if (g < acpa_n) {
                cpa16(s0 + so_a + g * 16,       gAh + g * 16, 16);
                cpa16(s0 + ABY + so_a + g * 16, gAl + g * 16, 16);
            }
        }
        cpa16(s0 + 2 * ABY + so_b,            gBh, bsz);
        cpa16(s0 + 2 * ABY + so_b + 16,       gBh + 16, bsz);
        cpa16(s0 + 2 * ABY + BBY + so_b,      gBl, bsz);
        cpa16(s0 + 2 * ABY + BBY + so_b + 16, gBl + 16, bsz);
        cpa_commit();
    }

    for (int s = 0; s < nCh; s++) {
        cpa_wait0();
        __syncthreads();

        if (s + 1 < nCh) {
            uint32_t s1 = sb + (uint32_t)((s + 1) & 1) * STG;
            int kb = (s + 1) * 64;
            #pragma unroll
            for (int g = 0; g < 2; g++) {
                if (g < acpa_n) {
                    cpa16(s1 + so_a + g * 16,       gAh + kb + g * 16, 16);
                    cpa16(s1 + ABY + so_a + g * 16, gAl + kb + g * 16, 16);
                }
            }
            cpa16(s1 + 2 * ABY + so_b,            gBh + kb, bsz);
            cpa16(s1 + 2 * ABY + so_b + 16,       gBh + kb + 16, bsz);
            cpa16(s1 + 2 * ABY + BBY + so_b,      gBl + kb, bsz);
            cpa16(s1 + 2 * ABY + BBY + so_b + 16, gBl + kb + 16, bsz);
            cpa_commit();
        }

        uint32_t st = sb + (uint32_t)(s & 1) * STG;
        uint32_t uAh = st, uAl = st + ABY, uBh = st + 2 * ABY, uBl = st + 2 * ABY + BBY;
        #pragma unroll
        for (int ks = 0; ks < 2; ks++) {
            uint32_t k2 = (uint32_t)(ks * 32);
            uint32_t aH[MT][4], aL[MT][4], bH[2][4], bL[2][4];
            #pragma unroll
            for (int mt = 0; mt < MT; mt++) ldmx4(aH[mt], uAh + aoff + mt * (16 * RS * 2) + k2);
            #pragma unroll
            for (int np = 0; np < 2; np++) ldmx4(bH[np], uBh + boff + np * (16 * RS * 2) + k2);
            #pragma unroll
            for (int mt = 0; mt < MT; mt++)
                #pragma unroll
                for (int nt = 0; nt < 4; nt++)
                    mma_bf16(acc[mt][nt], aH[mt], &bH[nt >> 1][(nt & 1) * 2]);
            #pragma unroll
            for (int np = 0; np < 2; np++) ldmx4(bL[np], uBl + boff + np * (16 * RS * 2) + k2);
            #pragma unroll
            for (int mt = 0; mt < MT; mt++)
                #pragma unroll
                for (int nt = 0; nt < 4; nt++)
                    mma_bf16(acc[mt][nt], aH[mt], &bL[nt >> 1][(nt & 1) * 2]);
            #pragma unroll
            for (int mt = 0; mt < MT; mt++) ldmx4(aL[mt], uAl + aoff + mt * (16 * RS * 2) + k2);
            #pragma unroll
            for (int mt = 0; mt < MT; mt++)
                #pragma unroll
                for (int nt = 0; nt < 4; nt++)
                    mma_bf16(acc[mt][nt], aL[mt], &bH[nt >> 1][(nt & 1) * 2]);
        }
    }

    #pragma unroll
    for (int mt = 0; mt < MT; mt++) {
        int rw = bm + wm * (MT * 16) + mt * 16 + (lane >> 2);
        #pragma unroll
        for (int nt = 0; nt < 4; nt++) {
            int col = bn + wn * 32 + nt * 8 + (lane & 3) * 2;
            if (col < N) {
                float* c = acc[mt][nt];
                float v0 = c[0], v1 = c[1], v2 = c[2], v3 = c[3];
                if (EPI == 1) {
                    float2 r0 = *(const float2*)(R + (size_t)rw * N + col);
                    float2 r1 = *(const float2*)(R + (size_t)(rw + 8) * N + col);
                    v0 += r0.x; v1 += r0.y; v2 += r1.x; v3 += r1.y;
                }
                *(float2*)(C + (size_t)rw * N + col) = make_float2(v0, v1);
                *(float2*)(C + (size_t)(rw + 8) * N + col) = make_float2(v2, v3);
            }
        }
    }
}

#define GSMEM_128 (2 * (2 * 128 * RS * 2 + 2 * 128 * RS * 2))
#define GSMEM_64  (2 * (2 * 64 * RS * 2 + 2 * 128 * RS * 2))

// ================= fp16 2-pass GEMM: C = (Ah+Al) @ B^T, B single fp16 plane =================
// EPI 0: C = v (fp32)   EPI 1: C = R + v (fp32)   EPI 2: Oh/Ol = f16split(relu(v)^2)
template <int EPI, int BM>
__global__ void __launch_bounds__(256, 2)
gemm_f16_2p_kernel(const __half* __restrict__ Ah, const __half* __restrict__ Al,
                   const __half* __restrict__ Bh,
                   float* __restrict__ C, const float* __restrict__ R,
                   __half* __restrict__ Oh, __half* __restrict__ Ol,
                   int M, int N, int K) {
    constexpr int MT = (BM == 128) ? 4 : 2;
    constexpr int ABY = BM * RS * 2;
    constexpr int BBY = 128 * RS * 2;
    constexpr int STG = 2 * ABY + BBY;

    extern __shared__ char gsm[];
    int tid = threadIdx.x, lane = tid & 31, wid = tid >> 5;
    int wm = wid >> 2, wn = wid & 3;
    int bm = blockIdx.y * BM, bn = blockIdx.x * 128;

    uint32_t sb = smem_u32(gsm);

    int arow, acpa_n; uint32_t so_a; const char *gAh, *gAl;
    if (BM == 128) {
        arow = tid >> 1; int half = tid & 1; acpa_n = 2;
        so_a = (uint32_t)(arow * 80 + half * 32);
        gAh = (const char*)(Ah + (size_t)(bm + arow) * K + half * 16);
        gAl = (const char*)(Al + (size_t)(bm + arow) * K + half * 16);
    } else {
        arow = tid >> 2; int seg = tid & 3; acpa_n = 1;
        so_a = (uint32_t)(arow * 80 + seg * 16);
        gAh = (const char*)(Ah + (size_t)(bm + arow) * K + seg * 8);
        gAl = (const char*)(Al + (size_t)(bm + arow) * K + seg * 8);
    }
    int brow = tid >> 1, bhalf = tid & 1;
    int bgrow = bn + brow;
    bool bok = bgrow < N;
    int browc = bok ? bgrow : (N - 1);
    uint32_t so_b = (uint32_t)(brow * 80 + bhalf * 32);
    const char* gBh = (const char*)(Bh + (size_t)browc * K + bhalf * 16);
    int bsz = bok ? 16 : 0;

    uint32_t aoff = (uint32_t)(((wm * (MT * 16) + (lane & 15)) * RS + ((lane >> 4) & 1) * 8) * 2);
    uint32_t boff = (uint32_t)(((wn * 32 + ((lane >> 4) & 1) * 8 + (lane & 7)) * RS
                                + ((lane >> 3) & 1) * 8) * 2);

    float acc[MT][4][4] = {};
    int nCh = K >> 5;

    {
        uint32_t s0 = sb;
        #pragma unroll
        for (int g = 0; g < 2; g++) {
            if (g < acpa_n) {
                cpa16(s0 + so_a + g * 16,       gAh + g * 16, 16);
                cpa16(s0 + ABY + so_a + g * 16, gAl + g * 16, 16);
            }
        }
        cpa16(s0 + 2 * ABY + so_b,      gBh, bsz);
        cpa16(s0 + 2 * ABY + so_b + 16, gBh + 16, bsz);
        cpa_commit();
    }

    for (int s = 0; s < nCh; s++) {
        cpa_wait0();
        __syncthreads();

        if (s + 1 < nCh) {
            uint32_t s1 = sb + (uint32_t)((s + 1) & 1) * STG;
            int kb = (s + 1) * 64;
            #pragma unroll
            for (int g = 0; g < 2; g++) {
                if (g < acpa_n) {
                    cpa16(s1 + so_a + g * 16,       gAh + kb + g * 16, 16);
                    cpa16(s1 + ABY + so_a + g * 16, gAl + kb + g * 16, 16);
                }
            }
            cpa16(s1 + 2 * ABY + so_b,      gBh + kb, bsz);
            cpa16(s1 + 2 * ABY + so_b + 16, gBh + kb + 16, bsz);
            cpa_commit();
        }

        uint32_t st = sb + (uint32_t)(s & 1) * STG;
        uint32_t uAh = st, uAl = st + ABY, uB = st + 2 * ABY;
        #pragma unroll
        for (int ks = 0; ks < 2; ks++) {
            uint32_t k2 = (uint32_t)(ks * 32);
            uint32_t aH[MT][4], aL[MT][4], bH[2][4];
            #pragma unroll
            for (int mt = 0; mt < MT; mt++) ldmx4(aH[mt], uAh + aoff + mt * (16 * RS * 2) + k2);
            #pragma unroll
            for (int np = 0; np < 2; np++) ldmx4(bH[np], uB + boff + np * (16 * RS * 2) + k2);
            #pragma unroll
            for (int mt = 0; mt < MT; mt++)
                #pragma unroll
                for (int nt = 0; nt < 4; nt++)
                    mma_f16(acc[mt][nt], aH[mt], &bH[nt >> 1][(nt & 1) * 2]);
            #pragma unroll
            for (int mt = 0; mt < MT; mt++) ldmx4(aL[mt], uAl + aoff + mt * (16 * RS * 2) + k2);
            #pragma unroll
            for (int mt = 0; mt < MT; mt++)
                #pragma unroll
                for (int nt = 0; nt < 4; nt++)
                    mma_f16(acc[mt][nt], aL[mt], &bH[nt >> 1][(nt & 1) * 2]);
        }
    }

    #pragma unroll
    for (int mt = 0; mt < MT; mt++) {
        int rw = bm + wm * (MT * 16) + mt * 16 + (lane >> 2);
        #pragma unroll
        for (int nt = 0; nt < 4; nt++) {
            int col = bn + wn * 32 + nt * 8 + (lane & 3) * 2;
            if (col < N) {
                float* c = acc[mt][nt];
                float v0 = c[0], v1 = c[1], v2 = c[2], v3 = c[3];
                if (EPI == 1) {
                    float2 r0 = *(const float2*)(R + (size_t)rw * N + col);
                    float2 r1 = *(const float2*)(R + (size_t)(rw + 8) * N + col);
                    v0 += r0.x; v1 += r0.y; v2 += r1.x; v3 += r1.y;
                }
                if (EPI == 2) {
                    v0 = fmaxf(v0, 0.f); v0 *= v0;
                    v1 = fmaxf(v1, 0.f); v1 *= v1;
                    v2 = fmaxf(v2, 0.f); v2 *= v2;
                    v3 = fmaxf(v3, 0.f); v3 *= v3;
                    __half2 hh0 = __floats2half2_rn(v0, v1);
                    __half2 ll0 = __floats2half2_rn(v0 - __half2float(hh0.x),
                                                    v1 - __half2float(hh0.y));
                    __half2 hh1 = __floats2half2_rn(v2, v3);
                    __half2 ll1 = __floats2half2_rn(v2 - __half2float(hh1.x),
                                                    v3 - __half2float(hh1.y));
                    size_t o0 = (size_t)rw * N + col;
                    size_t o1 = (size_t)(rw + 8) * N + col;
                    *(uint32_t*)((char*)Oh + o0 * 2) = *(uint32_t*)&hh0;
                    *(uint32_t*)((char*)Ol + o0 * 2) = *(uint32_t*)&ll0;
                    *(uint32_t*)((char*)Oh + o1 * 2) = *(uint32_t*)&hh1;
                    *(uint32_t*)((char*)Ol + o1 * 2) = *(uint32_t*)&ll1;
                } else {
                    *(float2*)(C + (size_t)rw * N + col) = make_float2(v0, v1);
                    *(float2*)(C + (size_t)(rw + 8) * N + col) = make_float2(v2, v3);
                }
            }
        }
    }
}

#define GSMEMF_128 (2 * (2 * 128 * RS * 2 + 128 * RS * 2))   // 61440
#define GSMEMF_64  (2 * (2 * 64 * RS * 2 + 128 * RS * 2))    // 40960

// ---------------- host launcher ----------------
extern "C" void kernel_launch(void* const* d_in, const int* in_sizes, int n_in,
                              void* d_out, int out_size) {
    const int*   ids  = (const int*)d_in[0];
    const float* wte  = (const float*)d_in[1];
    const float* wqkv = (const float*)d_in[2];
    const float* wo   = (const float*)d_in[3];
    const float* w1   = (const float*)d_in[4];
    const float* w2   = (const float*)d_in[5];
    const float* lm   = (const float*)d_in[6];
    float* out = (float*)d_out;

    float *px, *pqkv, *pcos, *psin;
    __nv_bfloat16 *pwh, *pwl, *psh, *psl, *phh, *phl, *pah, *pal, *pmh, *pml;
    cudaGetSymbolAddress((void**)&px,   g_x);
    cudaGetSymbolAddress((void**)&pqkv, g_qkv);
    cudaGetSymbolAddress((void**)&pcos, g_cos);
    cudaGetSymbolAddress((void**)&psin, g_sin);
    cudaGetSymbolAddress((void**)&pwh,  g_wh);
    cudaGetSymbolAddress((void**)&pwl,  g_wl);
    cudaGetSymbolAddress((void**)&psh,  g_sh);
    cudaGetSymbolAddress((void**)&psl,  g_sl);
    cudaGetSymbolAddress((void**)&phh,  g_hh);
    cudaGetSymbolAddress((void**)&phl,  g_hl);
    cudaGetSymbolAddress((void**)&pah,  g_ah);
    cudaGetSymbolAddress((void**)&pal,  g_al);
    cudaGetSymbolAddress((void**)&pmh,  g_mh);
    cudaGetSymbolAddress((void**)&pml,  g_ml);

    cudaFuncSetAttribute(flash_attn_kernel,
                         cudaFuncAttributeMaxDynamicSharedMemorySize, FLASH_SMEM);
    cudaFuncSetAttribute(gemm_bf16_kernel<1, 64>,
                         cudaFuncAttributeMaxDynamicSharedMemorySize, GSMEM_64);
    cudaFuncSetAttribute(gemm_f16_2p_kernel<0, 128>,
                         cudaFuncAttributeMaxDynamicSharedMemorySize, GSMEMF_128);
    cudaFuncSetAttribute(gemm_f16_2p_kernel<2, 128>,
                         cudaFuncAttributeMaxDynamicSharedMemorySize, GSMEMF_128);
    cudaFuncSetAttribute(gemm_f16_2p_kernel<1, 64>,
                         cudaFuncAttributeMaxDynamicSharedMemorySize, GSMEMF_64);

    // ---- weight prep ----
    wsplit_f16_kernel<<<(unsigned)((25165824ULL / 4 + 255) / 256), 256>>>(
        (const float4*)wqkv, (uint32_t*)(pwh + OFF_WQKV), 25165824ULL / 4);
    wsplit_kernel<<<(unsigned)((8388608ULL / 4 + 255) / 256), 256>>>(
        (const float4*)wo, (uint32_t*)(pwh + OFF_WO), (uint32_t*)(pwl + OFF_WO), 8388608ULL / 4);
    wsplit_f16_kernel<<<(unsigned)((33554432ULL / 4 + 255) / 256), 256>>>(
        (const float4*)w1, (uint32_t*)(pwh + OFF_W1), 33554432ULL / 4);
    wsplit_f16_kernel<<<(unsigned)((33554432ULL / 4 + 255) / 256), 256>>>(
        (const float4*)w2, (uint32_t*)(pwh + OFF_W2), 33554432ULL / 4);
    wsplit_f16_kernel<<<(unsigned)((51478528ULL / 4 + 255) / 256), 256>>>(
        (const float4*)lm, (uint32_t*)(pwh + OFF_LM), 51478528ULL / 4);

    rope_init_kernel<<<SEQ, 32>>>(pcos, psin);
    embed_rmsnorm_kernel<<<SEQ, 256>>>(ids, wte, px);

    for (int l = 0; l < NL; l++) {
        __nv_bfloat16* wqkv_h = pwh + OFF_WQKV + (size_t)l * 3145728;   // fp16
        __nv_bfloat16* wo_h = pwh + OFF_WO + (size_t)l * 1048576;       // bf16 hi
        __nv_bfloat16* wo_l2 = pwl + OFF_WO + (size_t)l * 1048576;      // bf16 lo
        __nv_bfloat16* w1_h = pwh + OFF_W1 + (size_t)l * 4194304;       // fp16
        __nv_bfloat16* w2_h = pwh + OFF_W2 + (size_t)l * 4194304;       // fp16

        rmsnorm_split_kernel<<<SEQ, 256>>>(px, phh, phl);
        gemm_f16_2p_kernel<0, 128><<<dim3(24, 16), 256, GSMEMF_128>>>(
            (const __half*)phh, (const __half*)phl, (const __half*)wqkv_h,
            pqkv, nullptr, nullptr, nullptr, SEQ, 3 * HIDDEN, HIDDEN);
        qknorm_rope_split_kernel<<<SEQ, 256>>>(pqkv, pcos, psin, psh, psl);
        flash_attn_kernel<<<dim3(SEQ / 64, NH), 128, FLASH_SMEM>>>(psh, psl, pah, pal);
        gemm_bf16_kernel<1, 64><<<dim3(8, 32), 256, GSMEM_64>>>(
            pah, pal, wo_h, wo_l2, px, px, SEQ, HIDDEN, HIDDEN);

        rmsnorm_split_kernel<<<SEQ, 256>>>(px, phh, phl);
        gemm_f16_2p_kernel<2, 128><<<dim3(32, 16), 256, GSMEMF_128>>>(
            (const __half*)phh, (const __half*)phl, (const __half*)w1_h,
            nullptr, nullptr, (__half*)pmh, (__half*)pml, SEQ, FFN, HIDDEN);
        gemm_f16_2p_kernel<1, 64><<<dim3(8, 32), 256, GSMEMF_64>>>(
            (const __half*)pmh, (const __half*)pml, (const __half*)w2_h,
            px, px, nullptr, nullptr, SEQ, HIDDEN, FFN);
    }

    rmsnorm_split_kernel<<<SEQ, 256>>>(px, phh, phl);
    gemm_f16_2p_kernel<0, 128><<<dim3((VOCABSZ + 127) / 128, 16), 256, GSMEMF_128>>>(
        (const __half*)phh, (const __half*)phl, (const __half*)(pwh + OFF_LM),
        out, nullptr, nullptr, nullptr, SEQ, VOCABSZ, HIDDEN);
}

// round 12
// speedup vs baseline: 3.0540x; 1.1223x over previous
#include <cuda_runtime.h>
#include <cuda_bf16.h>
#include <cuda_fp16.h>
#include <math.h>
#include <stdint.h>

#define SEQ     2048
#define HIDDEN  1024
#define NH      16
#define HD      64
#define NL      8
#define VOCABSZ 50272
#define FFN     4096
#define EPSV    1e-5f

#define OFF_WQKV 0ULL
#define OFF_WO   25165824ULL
#define OFF_W1   33554432ULL
#define OFF_W2   67108864ULL
#define OFF_LM   100663296ULL
#define W_TOTAL  152141824ULL

// ---------------- scratch ----------------
__device__ float g_x  [(size_t)SEQ * HIDDEN];
__device__ float g_qkv[(size_t)SEQ * 3 * HIDDEN];
__device__ float g_cos[(size_t)SEQ * (HD / 2)];
__device__ float g_sin[(size_t)SEQ * (HD / 2)];
__device__ __half g_wh[W_TOTAL];                                      // all weights fp16
__device__ __half g_sh[(size_t)SEQ * 3 * HIDDEN];                     // q-hi, k, v (fp16)
__device__ __half g_sl[(size_t)SEQ * 3 * HIDDEN];                     // q-lo (fp16)
__device__ __half g_hh[(size_t)SEQ * HIDDEN], g_hl[(size_t)SEQ * HIDDEN];
__device__ __half g_ah[(size_t)SEQ * HIDDEN], g_al[(size_t)SEQ * HIDDEN];
__device__ __half g_mh[(size_t)SEQ * FFN],    g_ml[(size_t)SEQ * FFN];

// ---------------- helpers ----------------
__device__ __forceinline__ uint32_t smem_u32(const void* p) {
    uint32_t a;
    asm("{ .reg .u64 t; cvta.to.shared.u64 t, %1; cvt.u32.u64 %0, t; }" : "=r"(a) : "l"(p));
    return a;
}
__device__ __forceinline__ float warpSum(float v) {
    #pragma unroll
    for (int o = 16; o; o >>= 1) v += __shfl_xor_sync(0xffffffffu, v, o);
    return v;
}
__device__ __forceinline__ float blockReduceSum(float v, float* red) {
    int lane = threadIdx.x & 31, w = threadIdx.x >> 5;
    v = warpSum(v);
    if (lane == 0) red[w] = v;
    __syncthreads();
    if (w == 0) {
        float r = (lane < (int)(blockDim.x >> 5)) ? red[lane] : 0.0f;
        r = warpSum(r);
        if (lane == 0) red[0] = r;
    }
    __syncthreads();
    float out = red[0];
    __syncthreads();
    return out;
}
__device__ __forceinline__ void mma_f16(float* c, const uint32_t* a, const uint32_t* b) {
    asm volatile(
        "mma.sync.aligned.m16n8k16.row.col.f32.f16.f16.f32 "
        "{%0,%1,%2,%3}, {%4,%5,%6,%7}, {%8,%9}, {%0,%1,%2,%3};"
        : "+f"(c[0]), "+f"(c[1]), "+f"(c[2]), "+f"(c[3])
        : "r"(a[0]), "r"(a[1]), "r"(a[2]), "r"(a[3]), "r"(b[0]), "r"(b[1]));
}
__device__ __forceinline__ void ldmx4(uint32_t* d, uint32_t addr) {
    asm volatile("ldmatrix.sync.aligned.m8n8.x4.shared.b16 {%0,%1,%2,%3}, [%4];"
                 : "=r"(d[0]), "=r"(d[1]), "=r"(d[2]), "=r"(d[3]) : "r"(addr));
}
__device__ __forceinline__ void ldmx4t(uint32_t* d, uint32_t addr) {
    asm volatile("ldmatrix.sync.aligned.m8n8.x4.trans.shared.b16 {%0,%1,%2,%3}, [%4];"
                 : "=r"(d[0]), "=r"(d[1]), "=r"(d[2]), "=r"(d[3]) : "r"(addr));
}
__device__ __forceinline__ void cpa16(uint32_t s, const void* g, int srcsz) {
    asm volatile("cp.async.cg.shared.global [%0], [%1], 16, %2;"
                 :: "r"(s), "l"(g), "r"(srcsz) : "memory");
}
__device__ __forceinline__ void cpa_commit() {
    asm volatile("cp.async.commit_group;" ::: "memory");
}
__device__ __forceinline__ void cpa_wait0() {
    asm volatile("cp.async.wait_group 0;" ::: "memory");
}

// ---------------- weight prep: fp32 -> single fp16 plane ----------------
__global__ void wsplit_f16_kernel(const float4* __restrict__ src, uint32_t* __restrict__ d,
                                  size_t n4) {
    size_t i = (size_t)blockIdx.x * blockDim.x + threadIdx.x;
    if (i < n4) {
        float4 f = src[i];
        __half2 h0 = __floats2half2_rn(f.x, f.y);
        __half2 h1 = __floats2half2_rn(f.z, f.w);
        d[2 * i] = *(uint32_t*)&h0;
        d[2 * i + 1] = *(uint32_t*)&h1;
    }
}

// ---------------- embedding + rmsnorm ----------------
__global__ void embed_rmsnorm_kernel(const int* __restrict__ ids,
                                     const float* __restrict__ wte,
                                     float* __restrict__ out) {
    __shared__ float red[32];
    int t = blockIdx.x;
    const float* row = wte + (size_t)ids[t] * HIDDEN;
    float v[4]; float ss = 0.0f;
    #pragma unroll
    for (int i = 0; i < 4; i++) { v[i] = row[threadIdx.x + i * 256]; ss += v[i] * v[i]; }
    ss = blockReduceSum(ss, red);
    float sc = rsqrtf(ss * (1.0f / HIDDEN) + EPSV);
    #pragma unroll
    for (int i = 0; i < 4; i++)
        out[(size_t)t * HIDDEN + threadIdx.x + i * 256] = v[i] * sc;
}

// ---------------- rmsnorm: fp32 in -> fp16 hi/lo planes ----------------
__global__ void rmsnorm_split_kernel(const float* __restrict__ in,
                                     __half* __restrict__ oh,
                                     __half* __restrict__ ol) {
    __shared__ float red[32];
    int t = blockIdx.x;
    const float* row = in + (size_t)t * HIDDEN;
    float v[4]; float ss = 0.0f;
    #pragma unroll
    for (int i = 0; i < 4; i++) {
        int idx = 2 * threadIdx.x + (i & 1) + (i >> 1) * 512;
        v[i] = row[idx];
        ss += v[i] * v[i];
    }
    ss = blockReduceSum(ss, red);
    float sc = rsqrtf(ss * (1.0f / HIDDEN) + EPSV);
    #pragma unroll
    for (int p = 0; p < 2; p++) {
        float a = v[2 * p] * sc, b = v[2 * p + 1] * sc;
        __half2 hh = __floats2half2_rn(a, b);
        __half2 ll = __floats2half2_rn(a - __half2float(hh.x),
                                       b - __half2float(hh.y));
        size_t off = (size_t)t * HIDDEN + 2 * threadIdx.x + p * 512;
        *(uint32_t*)((char*)oh + off * 2) = *(uint32_t*)&hh;
        *(uint32_t*)((char*)ol + off * 2) = *(uint32_t*)&ll;
    }
}

// ---------------- rope tables ----------------
__global__ void rope_init_kernel(float* __restrict__ ctab, float* __restrict__ stab) {
    int t = blockIdx.x, i = threadIdx.x;
    float invf = (float)pow(10000.0, -(double)(2 * i) / (double)HD);
    float ang = (float)t * invf;
    float s, c;
    sincosf(ang, &s, &c);
    ctab[t * 32 + i] = c;
    stab[t * 32 + i] = s;
}

// ---------------- per-token: q -> fp16 hi/lo; k -> fp16; v -> fp16. grid SEQ, 256 thr ----------------
__global__ void qknorm_rope_split_kernel(const float* __restrict__ qkv,
                                         const float* __restrict__ ctab,
                                         const float* __restrict__ stab,
                                         __half* __restrict__ oh,
                                         __half* __restrict__ ol) {
    int t = blockIdx.x, tid = threadIdx.x, lane = tid & 31, wid = tid >> 5;
    float cc = ctab[t * 32 + lane], ssn = stab[t * 32 + lane];
    #pragma unroll
    for (int task = wid; task < 32; task += 8) {
        int h = task & 15, wv = task >> 4;
        size_t base = (size_t)t * (3 * HIDDEN) + (size_t)wv * HIDDEN + h * HD;
        float2 x = *(const float2*)(qkv + base + 2 * lane);
        float ss = warpSum(x.x * x.x + x.y * x.y);
        float sc = rsqrtf(ss * (1.0f / HD) + EPSV);
        float x0 = x.x * sc, x1 = x.y * sc;
        float y0 = x1 * cc - x0 * ssn;
        float y1 = x1 * ssn + x0 * cc;
        __half2 hh = __floats2half2_rn(y0, y1);
        *(uint32_t*)((char*)oh + (base + 2 * lane) * 2) = *(uint32_t*)&hh;
        if (wv == 0) {
            __half2 ll = __floats2half2_rn(y0 - __half2float(hh.x),
                                           y1 - __half2float(hh.y));
            *(uint32_t*)((char*)ol + (base + 2 * lane) * 2) = *(uint32_t*)&ll;
        }
    }
    // v: single fp16 plane
    size_t vb = (size_t)t * (3 * HIDDEN) + 2 * HIDDEN;
    float4 v = *(const float4*)(qkv + vb + tid * 4);
    __half2 h0 = __floats2half2_rn(v.x, v.y);
    __half2 h1 = __floats2half2_rn(v.z, v.w);
    uint2 pk = make_uint2(*(uint32_t*)&h0, *(uint32_t*)&h1);
    *(uint2*)((char*)oh + (vb + tid * 4) * 2) = pk;
}

// ================= fused flash attention (fp16, 2-pass, cp.async pipelined) =================
#define FRS       72
#define FT_BYTES  (64 * FRS * 2)              // 9216
#define KV_STAGE  (2 * FT_BYTES)              // K + V single planes
#define FLASH_SMEM (2 * FT_BYTES + 2 * KV_STAGE)   // 55296

__global__ void __launch_bounds__(128, 2)
flash_attn_kernel(const __half* __restrict__ qh_g,
                  const __half* __restrict__ ql_g,
                  __half* __restrict__ outh, __half* __restrict__ outl) {
    extern __shared__ char fsm[];
    uint32_t sb = smem_u32(fsm);
    uint32_t uQh = sb, uQl = sb + FT_BYTES;

    int tid = threadIdx.x, lane = tid & 31, wid = tid >> 5;
    int h = blockIdx.y;
    int qt = (int)gridDim.x - 1 - (int)blockIdx.x;
    int bm = qt * 64;

    int r = tid >> 1, c0 = (tid & 1) * 32;
    uint32_t soff = (uint32_t)(r * (FRS * 2) + c0 * 2);

    {
        const char* gQh = (const char*)(qh_g + (size_t)(bm + r) * (3 * HIDDEN) + h * HD + c0);
        const char* gQl = (const char*)(ql_g + (size_t)(bm + r) * (3 * HIDDEN) + h * HD + c0);
        #pragma unroll
        for (int g = 0; g < 4; g++) {
            cpa16(uQh + soff + g * 16, gQh + g * 16, 16);
            cpa16(uQl + soff + g * 16, gQl + g * 16, 16);
        }
        const char* gK = (const char*)(qh_g + (size_t)r * (3 * HIDDEN) + HIDDEN + h * HD + c0);
        uint32_t st = sb + 2 * FT_BYTES;
        #pragma unroll
        for (int g = 0; g < 4; g++) {
            cpa16(st + soff + g * 16,            gK + g * 16, 16);
            cpa16(st + FT_BYTES + soff + g * 16, gK + HIDDEN * 2 + g * 16, 16);
        }
        cpa_commit();
    }

    uint32_t qh[4][4], ql[4][4];
    float o[8][4] = {};
    float m[2] = {-INFINITY, -INFINITY};
    float l[2] = {0.0f, 0.0f};

    for (int jt = 0; jt <= qt; jt++) {
        cpa_wait0();
        __syncthreads();

        if (jt == 0) {
            uint32_t qoff = (uint32_t)(((wid * 16 + (lane & 15)) * FRS + ((lane >> 4) & 1) * 8) * 2);
            #pragma unroll
            for (int ks = 0; ks < 4; ks++) {
                ldmx4(qh[ks], uQh + qoff + ks * 32);
                ldmx4(ql[ks], uQl + qoff + ks * 32);
            }
        }
        if (jt + 1 <= qt) {
            const char* gK = (const char*)(qh_g + (size_t)((jt + 1) * 64 + r) * (3 * HIDDEN) + HIDDEN + h * HD + c0);
            uint32_t st = sb + 2 * FT_BYTES + (uint32_t)((jt + 1) & 1) * KV_STAGE;
            #pragma unroll
            for (int g = 0; g < 4; g++) {
                cpa16(st + soff + g * 16,            gK + g * 16, 16);
                cpa16(st + FT_BYTES + soff + g * 16, gK + HIDDEN * 2 + g * 16, 16);
            }
            cpa_commit();
        }

        uint32_t stg = sb + 2 * FT_BYTES + (uint32_t)(jt & 1) * KV_STAGE;
        uint32_t uK = stg, uV = stg + FT_BYTES;

        // ---- scores = (Qh + Ql) K^T ----
        float s[8][4] = {};
        uint32_t bbase = (uint32_t)(((((lane >> 4) & 1) * 8 + (lane & 7)) * FRS
                                     + ((lane >> 3) & 1) * 8) * 2);
        #pragma unroll
        for (int ks = 0; ks < 4; ks++) {
            #pragma unroll
            for (int nb = 0; nb < 4; nb++) {
                uint32_t kk[4];
                uint32_t bo = bbase + (uint32_t)(nb * 16 * FRS * 2) + (uint32_t)(ks * 32);
                ldmx4(kk, uK + bo);
                mma_f16(s[nb * 2],     qh[ks], kk + 0);
                mma_f16(s[nb * 2 + 1], qh[ks], kk + 2);
                mma_f16(s[nb * 2],     ql[ks], kk + 0);
                mma_f16(s[nb * 2 + 1], ql[ks], kk + 2);
            }
        }
        #pragma unroll
        for (int nt = 0; nt < 8; nt++)
            #pragma unroll
            for (int c = 0; c < 4; c++) s[nt][c] *= 0.125f;

        if (jt == qt) {
            int q0 = wid * 16 + (lane >> 2);
            int q1 = q0 + 8;
            #pragma unroll
            for (int nt = 0; nt < 8; nt++) {
                int j0 = nt * 8 + (lane & 3) * 2;
                if (j0     > q0) s[nt][0] = -INFINITY;
                if (j0 + 1 > q0) s[nt][1] = -INFINITY;
                if (j0     > q1) s[nt][2] = -INFINITY;
                if (j0 + 1 > q1) s[nt][3] = -INFINITY;
            }
        }

        #pragma unroll
        for (int hh = 0; hh < 2; hh++) {
            float rm = -INFINITY;
            #pragma unroll
            for (int nt = 0; nt < 8; nt++)
                rm = fmaxf(rm, fmaxf(s[nt][2 * hh], s[nt][2 * hh + 1]));
            rm = fmaxf(rm, __shfl_xor_sync(0xffffffffu, rm, 1));
            rm = fmaxf(rm, __shfl_xor_sync(0xffffffffu, rm, 2));
            float mnew = fmaxf(m[hh], rm);
            float corr = __expf(m[hh] - mnew);
            float rs = 0.0f;
            #pragma unroll
            for (int nt = 0; nt < 8; nt++) {
                float p0 = __expf(s[nt][2 * hh]     - mnew);
                float p1 = __expf(s[nt][2 * hh + 1] - mnew);
                s[nt][2 * hh] = p0; s[nt][2 * hh + 1] = p1;
                rs += p0 + p1;
            }
            rs += __shfl_xor_sync(0xffffffffu, rs, 1);
            rs += __shfl_xor_sync(0xffffffffu, rs, 2);
            l[hh] = l[hh] * corr + rs;
            m[hh] = mnew;
            #pragma unroll
            for (int dt = 0; dt < 8; dt++) {
                o[dt][2 * hh] *= corr; o[dt][2 * hh + 1] *= corr;
            }
        }

        // ---- O += (Ph + Pl) V ----
        #pragma unroll
        for (int jks = 0; jks < 4; jks++) {
            float* ce = s[2 * jks];
            float* co = s[2 * jks + 1];
            uint32_t pa[4], pb[4];
            {
                __half2 h0 = __floats2half2_rn(ce[0], ce[1]);
                __half2 h1 = __floats2half2_rn(ce[2], ce[3]);
                __half2 h2 = __floats2half2_rn(co[0], co[1]);
                __half2 h3 = __floats2half2_rn(co[2], co[3]);
                pa[0] = *(uint32_t*)&h0; pa[1] = *(uint32_t*)&h1;
                pa[2] = *(uint32_t*)&h2; pa[3] = *(uint32_t*)&h3;
                __half2 e0 = __floats2half2_rn(ce[0] - __half2float(h0.x),
                                               ce[1] - __half2float(h0.y));
                __half2 e1 = __floats2half2_rn(ce[2] - __half2float(h1.x),
                                               ce[3] - __half2float(h1.y));
                __half2 e2 = __floats2half2_rn(co[0] - __half2float(h2.x),
                                               co[1] - __half2float(h2.y));
                __half2 e3 = __floats2half2_rn(co[2] - __half2float(h3.x),
                                               co[3] - __half2float(h3.y));
                pb[0] = *(uint32_t*)&e0; pb[1] = *(uint32_t*)&e1;
                pb[2] = *(uint32_t*)&e2; pb[3] = *(uint32_t*)&e3;
            }
            uint32_t vbase = (uint32_t)(((jks * 16 + (lane & 15)) * FRS
                                         + ((lane >> 4) & 1) * 8) * 2);
            #pragma unroll
            for (int db = 0; db < 4; db++) {
                uint32_t vv[4];
                ldmx4t(vv, uV + vbase + (uint32_t)(db * 32));
                mma_f16(o[db * 2],     pa, vv + 0);
                mma_f16(o[db * 2 + 1], pa, vv + 2);
                mma_f16(o[db * 2],     pb, vv + 0);
                mma_f16(o[db * 2 + 1], pb, vv + 2);
            }
        }
    }

    float inv0 = 1.0f / l[0], inv1 = 1.0f / l[1];
    int row0 = bm + wid * 16 + (lane >> 2);
    #pragma unroll
    for (int dt = 0; dt < 8; dt++) {
        int col = h * HD + dt * 8 + (lane & 3) * 2;
        float a0 = o[dt][0] * inv0, b0 = o[dt][1] * inv0;
        float a1 = o[dt][2] * inv1, b1 = o[dt][3] * inv1;
        __half2 hh0 = __floats2half2_rn(a0, b0);
        __half2 ll0 = __floats2half2_rn(a0 - __half2float(hh0.x),
                                        b0 - __half2float(hh0.y));
        __half2 hh1 = __floats2half2_rn(a1, b1);
        __half2 ll1 = __floats2half2_rn(a1 - __half2float(hh1.x),
                                        b1 - __half2float(hh1.y));
        size_t off0 = (size_t)row0 * HIDDEN + col;
        size_t off1 = (size_t)(row0 + 8) * HIDDEN + col;
        *(uint32_t*)((char*)outh + off0 * 2) = *(uint32_t*)&hh0;
        *(uint32_t*)((char*)outl + off0 * 2) = *(uint32_t*)&ll0;
        *(uint32_t*)((char*)outh + off1 * 2) = *(uint32_t*)&hh1;
        *(uint32_t*)((char*)outl + off1 * 2) = *(uint32_t*)&ll1;
    }
}

// ================= fp16 2-pass GEMM: C = (Ah+Al) @ B^T, B single fp16 plane =================
// EPI 0: C = v (fp32)   EPI 1: C = R + v (fp32)   EPI 2: Oh/Ol = f16split(relu(v)^2)
#define RS 40

template <int EPI, int BM>
__global__ void __launch_bounds__(256, 2)
gemm_f16_2p_kernel(const __half* __restrict__ Ah, const __half* __restrict__ Al,
                   const __half* __restrict__ Bh,
                   float* __restrict__ C, const float* __restrict__ R,
                   __half* __restrict__ Oh, __half* __restrict__ Ol,
                   int M, int N, int K) {
    constexpr int MT = (BM == 128) ? 4 : 2;
    constexpr int ABY = BM * RS * 2;
    constexpr int BBY = 128 * RS * 2;
    constexpr int STG = 2 * ABY + BBY;

    extern __shared__ char gsm[];
    int tid = threadIdx.x, lane = tid & 31, wid = tid >> 5;
    int wm = wid >> 2, wn = wid & 3;
    int bm = blockIdx.y * BM, bn = blockIdx.x * 128;

    uint32_t sb = smem_u32(gsm);

    int arow, acpa_n; uint32_t so_a; const char *gAh, *gAl;
    if (BM == 128) {
        arow = tid >> 1; int half = tid & 1; acpa_n = 2;
        so_a = (uint32_t)(arow * 80 + half * 32);
        gAh = (const char*)(Ah + (size_t)(bm + arow) * K + half * 16);
        gAl = (const char*)(Al + (size_t)(bm + arow) * K + half * 16);
    } else {
        arow = tid >> 2; int seg = tid & 3; acpa_n = 1;
        so_a = (uint32_t)(arow * 80 + seg * 16);
        gAh = (const char*)(Ah + (size_t)(bm + arow) * K + seg * 8);
        gAl = (const char*)(Al + (size_t)(bm + arow) * K + seg * 8);
    }
    int brow = tid >> 1, bhalf = tid & 1;
    int bgrow = bn + brow;
    bool bok = bgrow < N;
    int browc = bok ? bgrow : (N - 1);
    uint32_t so_b = (uint32_t)(brow * 80 + bhalf * 32);
    const char* gBh = (const char*)(Bh + (size_t)browc * K + bhalf * 16);
    int bsz = bok ? 16 : 0;

    uint32_t aoff = (uint32_t)(((wm * (MT * 16) + (lane & 15)) * RS + ((lane >> 4) & 1) * 8) * 2);
    uint32_t boff = (uint32_t)(((wn * 32 + ((lane >> 4) & 1) * 8 + (lane & 7)) * RS
                                + ((lane >> 3) & 1) * 8) * 2);

    float acc[MT][4][4] = {};
    int nCh = K >> 5;

    {
        uint32_t s0 = sb;
        #pragma unroll
        for (int g = 0; g < 2; g++) {
            if (g < acpa_n) {
                cpa16(s0 + so_a + g * 16,       gAh + g * 16, 16);
                cpa16(s0 + ABY + so_a + g * 16, gAl + g * 16, 16);
            }
        }
        cpa16(s0 + 2 * ABY + so_b,      gBh, bsz);
        cpa16(s0 + 2 * ABY + so_b + 16, gBh + 16, bsz);
        cpa_commit();
    }

    for (int s = 0; s < nCh; s++) {
        cpa_wait0();
        __syncthreads();

        if (s + 1 < nCh) {
            uint32_t s1 = sb + (uint32_t)((s + 1) & 1) * STG;
            int kb = (s + 1) * 64;
            #pragma unroll
            for (int g = 0; g < 2; g++) {
                if (g < acpa_n) {
                    cpa16(s1 + so_a + g * 16,       gAh + kb + g * 16, 16);
                    cpa16(s1 + ABY + so_a + g * 16, gAl + kb + g * 16, 16);
                }
            }
            cpa16(s1 + 2 * ABY + so_b,      gBh + kb, bsz);
            cpa16(s1 + 2 * ABY + so_b + 16, gBh + kb + 16, bsz);
            cpa_commit();
        }

        uint32_t st = sb + (uint32_t)(s & 1) * STG;
        uint32_t uAh = st, uAl = st + ABY, uB = st + 2 * ABY;
        #pragma unroll
        for (int ks = 0; ks < 2; ks++) {
            uint32_t k2 = (uint32_t)(ks * 32);
            uint32_t aH[MT][4], aL[MT][4], bH[2][4];
            #pragma unroll
            for (int mt = 0; mt < MT; mt++) ldmx4(aH[mt], uAh + aoff + mt * (16 * RS * 2) + k2);
            #pragma unroll
            for (int np = 0; np < 2; np++) ldmx4(bH[np], uB + boff + np * (16 * RS * 2) + k2);
            #pragma unroll
            for (int mt = 0; mt < MT; mt++)
                #pragma unroll
                for (int nt = 0; nt < 4; nt++)
                    mma_f16(acc[mt][nt], aH[mt], &bH[nt >> 1][(nt & 1) * 2]);
            #pragma unroll
            for (int mt = 0; mt < MT; mt++) ldmx4(aL[mt], uAl + aoff + mt * (16 * RS * 2) + k2);
            #pragma unroll
            for (int mt = 0; mt < MT; mt++)
                #pragma unroll
                for (int nt = 0; nt < 4; nt++)
                    mma_f16(acc[mt][nt], aL[mt], &bH[nt >> 1][(nt & 1) * 2]);
        }
    }

    #pragma unroll
    for (int mt = 0; mt < MT; mt++) {
        int rw = bm + wm * (MT * 16) + mt * 16 + (lane >> 2);
        #pragma unroll
        for (int nt = 0; nt < 4; nt++) {
            int col = bn + wn * 32 + nt * 8 + (lane & 3) * 2;
            if (col < N) {
                float* c = acc[mt][nt];
                float v0 = c[0], v1 = c[1], v2 = c[2], v3 = c[3];
                if (EPI == 1) {
                    float2 r0 = *(const float2*)(R + (size_t)rw * N + col);
                    float2 r1 = *(const float2*)(R + (size_t)(rw + 8) * N + col);
                    v0 += r0.x; v1 += r0.y; v2 += r1.x; v3 += r1.y;
                }
                if (EPI == 2) {
                    v0 = fmaxf(v0, 0.f); v0 *= v0;
                    v1 = fmaxf(v1, 0.f); v1 *= v1;
                    v2 = fmaxf(v2, 0.f); v2 *= v2;
                    v3 = fmaxf(v3, 0.f); v3 *= v3;
                    __half2 hh0 = __floats2half2_rn(v0, v1);
                    __half2 ll0 = __floats2half2_rn(v0 - __half2float(hh0.x),
                                                    v1 - __half2float(hh0.y));
                    __half2 hh1 = __floats2half2_rn(v2, v3);
                    __half2 ll1 = __floats2half2_rn(v2 - __half2float(hh1.x),
                                                    v3 - __half2float(hh1.y));
                    size_t o0 = (size_t)rw * N + col;
                    size_t o1 = (size_t)(rw + 8) * N + col;
                    *(uint32_t*)((char*)Oh + o0 * 2) = *(uint32_t*)&hh0;
                    *(uint32_t*)((char*)Ol + o0 * 2) = *(uint32_t*)&ll0;
                    *(uint32_t*)((char*)Oh + o1 * 2) = *(uint32_t*)&hh1;
                    *(uint32_t*)((char*)Ol + o1 * 2) = *(uint32_t*)&ll1;
                } else {
                    *(float2*)(C + (size_t)rw * N + col) = make_float2(v0, v1);
                    *(float2*)(C + (size_t)(rw + 8) * N + col) = make_float2(v2, v3);
                }
            }
        }
    }
}

#define GSMEMF_128 (2 * (2 * 128 * RS * 2 + 128 * RS * 2))   // 61440
#define GSMEMF_64  (2 * (2 * 64 * RS * 2 + 128 * RS * 2))    // 40960

// ---------------- host launcher ----------------
extern "C" void kernel_launch(void* const* d_in, const int* in_sizes, int n_in,
                              void* d_out, int out_size) {
    const int*   ids  = (const int*)d_in[0];
    const float* wte  = (const float*)d_in[1];
    const float* wqkv = (const float*)d_in[2];
    const float* wo   = (const float*)d_in[3];
    const float* w1   = (const float*)d_in[4];
    const float* w2   = (const float*)d_in[5];
    const float* lm   = (const float*)d_in[6];
    float* out = (float*)d_out;

    float *px, *pqkv, *pcos, *psin;
    __half *pwh, *psh, *psl, *phh, *phl, *pah, *pal, *pmh, *pml;
    cudaGetSymbolAddress((void**)&px,   g_x);
    cudaGetSymbolAddress((void**)&pqkv, g_qkv);
    cudaGetSymbolAddress((void**)&pcos, g_cos);
    cudaGetSymbolAddress((void**)&psin, g_sin);
    cudaGetSymbolAddress((void**)&pwh,  g_wh);
    cudaGetSymbolAddress((void**)&psh,  g_sh);
    cudaGetSymbolAddress((void**)&psl,  g_sl);
    cudaGetSymbolAddress((void**)&phh,  g_hh);
    cudaGetSymbolAddress((void**)&phl,  g_hl);
    cudaGetSymbolAddress((void**)&pah,  g_ah);
    cudaGetSymbolAddress((void**)&pal,  g_al);
    cudaGetSymbolAddress((void**)&pmh,  g_mh);
    cudaGetSymbolAddress((void**)&pml,  g_ml);

    cudaFuncSetAttribute(flash_attn_kernel,
                         cudaFuncAttributeMaxDynamicSharedMemorySize, FLASH_SMEM);
    cudaFuncSetAttribute(gemm_f16_2p_kernel<0, 128>,
                         cudaFuncAttributeMaxDynamicSharedMemorySize, GSMEMF_128);
    cudaFuncSetAttribute(gemm_f16_2p_kernel<2, 128>,
                         cudaFuncAttributeMaxDynamicSharedMemorySize, GSMEMF_128);
    cudaFuncSetAttribute(gemm_f16_2p_kernel<1, 64>,
                         cudaFuncAttributeMaxDynamicSharedMemorySize, GSMEMF_64);

    // ---- weight prep (all fp16 single plane) ----
    wsplit_f16_kernel<<<(unsigned)((25165824ULL / 4 + 255) / 256), 256>>>(
        (const float4*)wqkv, (uint32_t*)(pwh + OFF_WQKV), 25165824ULL / 4);
    wsplit_f16_kernel<<<(unsigned)((8388608ULL / 4 + 255) / 256), 256>>>(
        (const float4*)wo, (uint32_t*)(pwh + OFF_WO), 8388608ULL / 4);
    wsplit_f16_kernel<<<(unsigned)((33554432ULL / 4 + 255) / 256), 256>>>(
        (const float4*)w1, (uint32_t*)(pwh + OFF_W1), 33554432ULL / 4);
    wsplit_f16_kernel<<<(unsigned)((33554432ULL / 4 + 255) / 256), 256>>>(
        (const float4*)w2, (uint32_t*)(pwh + OFF_W2), 33554432ULL / 4);
    wsplit_f16_kernel<<<(unsigned)((51478528ULL / 4 + 255) / 256), 256>>>(
        (const float4*)lm, (uint32_t*)(pwh + OFF_LM), 51478528ULL / 4);

    rope_init_kernel<<<SEQ, 32>>>(pcos, psin);
    embed_rmsnorm_kernel<<<SEQ, 256>>>(ids, wte, px);

    for (int l = 0; l < NL; l++) {
        __half* wqkv_h = pwh + OFF_WQKV + (size_t)l * 3145728;
        __half* wo_h   = pwh + OFF_WO + (size_t)l * 1048576;
        __half* w1_h   = pwh + OFF_W1 + (size_t)l * 4194304;
        __half* w2_h   = pwh + OFF_W2 + (size_t)l * 4194304;

        rmsnorm_split_kernel<<<SEQ, 256>>>(px, phh, phl);
        gemm_f16_2p_kernel<0, 128><<<dim3(24, 16), 256, GSMEMF_128>>>(
            phh, phl, wqkv_h, pqkv, nullptr, nullptr, nullptr, SEQ, 3 * HIDDEN, HIDDEN);
        qknorm_rope_split_kernel<<<SEQ, 256>>>(pqkv, pcos, psin, psh, psl);
        flash_attn_kernel<<<dim3(SEQ / 64, NH), 128, FLASH_SMEM>>>(psh, psl, pah, pal);
        gemm_f16_2p_kernel<1, 64><<<dim3(8, 32), 256, GSMEMF_64>>>(
            pah, pal, wo_h, px, px, nullptr, nullptr, SEQ, HIDDEN, HIDDEN);

        rmsnorm_split_kernel<<<SEQ, 256>>>(px, phh, phl);
        gemm_f16_2p_kernel<2, 128><<<dim3(32, 16), 256, GSMEMF_128>>>(
            phh, phl, w1_h, nullptr, nullptr, pmh, pml, SEQ, FFN, HIDDEN);
        gemm_f16_2p_kernel<1, 64><<<dim3(8, 32), 256, GSMEMF_64>>>(
            pmh, pml, w2_h, px, px, nullptr, nullptr, SEQ, HIDDEN, FFN);
    }

    rmsnorm_split_kernel<<<SEQ, 256>>>(px, phh, phl);
    gemm_f16_2p_kernel<0, 128><<<dim3((VOCABSZ + 127) / 128, 16), 256, GSMEMF_128>>>(
        phh, phl, pwh + OFF_LM, out, nullptr, nullptr, nullptr, SEQ, VOCABSZ, HIDDEN);
}

// round 13
// speedup vs baseline: 3.5692x; 1.1687x over previous
#include <cuda_runtime.h>
#include <cuda_bf16.h>
#include <cuda_fp16.h>
#include <math.h>
#include <stdint.h>

#define SEQ     2048
#define HIDDEN  1024
#define NH      16
#define HD      64
#define NL      8
#define VOCABSZ 50272
#define FFN     4096
#define EPSV    1e-5f

#define OFF_WQKV 0ULL
#define OFF_WO   25165824ULL
#define OFF_W1   33554432ULL
#define OFF_W2   67108864ULL
#define OFF_LM   100663296ULL
#define W_TOTAL  152141824ULL

// ---------------- scratch ----------------
__device__ float g_x  [(size_t)SEQ * HIDDEN];
__device__ float g_qkv[(size_t)SEQ * 3 * HIDDEN];
__device__ float g_cos[(size_t)SEQ * (HD / 2)];
__device__ float g_sin[(size_t)SEQ * (HD / 2)];
__device__ __half g_wh[W_TOTAL];                                      // all weights fp16
__device__ __half g_sh[(size_t)SEQ * 3 * HIDDEN];                     // q-hi, k, v (fp16)
__device__ __half g_sl[(size_t)SEQ * 3 * HIDDEN];                     // q-lo (fp16)
__device__ __half g_hh[(size_t)SEQ * HIDDEN], g_hl[(size_t)SEQ * HIDDEN];
__device__ __half g_ah[(size_t)SEQ * HIDDEN];                         // attn out (fp16)
__device__ __half g_mh[(size_t)SEQ * FFN],    g_ml[(size_t)SEQ * FFN];

// ---------------- helpers ----------------
__device__ __forceinline__ uint32_t smem_u32(const void* p) {
    uint32_t a;
    asm("{ .reg .u64 t; cvta.to.shared.u64 t, %1; cvt.u32.u64 %0, t; }" : "=r"(a) : "l"(p));
    return a;
}
__device__ __forceinline__ float warpSum(float v) {
    #pragma unroll
    for (int o = 16; o; o >>= 1) v += __shfl_xor_sync(0xffffffffu, v, o);
    return v;
}
__device__ __forceinline__ float blockReduceSum(float v, float* red) {
    int lane = threadIdx.x & 31, w = threadIdx.x >> 5;
    v = warpSum(v);
    if (lane == 0) red[w] = v;
    __syncthreads();
    if (w == 0) {
        float r = (lane < (int)(blockDim.x >> 5)) ? red[lane] : 0.0f;
        r = warpSum(r);
        if (lane == 0) red[0] = r;
    }
    __syncthreads();
    float out = red[0];
    __syncthreads();
    return out;
}
__device__ __forceinline__ void mma_f16(float* c, const uint32_t* a, const uint32_t* b) {
    asm volatile(
        "mma.sync.aligned.m16n8k16.row.col.f32.f16.f16.f32 "
        "{%0,%1,%2,%3}, {%4,%5,%6,%7}, {%8,%9}, {%0,%1,%2,%3};"
        : "+f"(c[0]), "+f"(c[1]), "+f"(c[2]), "+f"(c[3])
        : "r"(a[0]), "r"(a[1]), "r"(a[2]), "r"(a[3]), "r"(b[0]), "r"(b[1]));
}
__device__ __forceinline__ void ldmx4(uint32_t* d, uint32_t addr) {
    asm volatile("ldmatrix.sync.aligned.m8n8.x4.shared.b16 {%0,%1,%2,%3}, [%4];"
                 : "=r"(d[0]), "=r"(d[1]), "=r"(d[2]), "=r"(d[3]) : "r"(addr));
}
__device__ __forceinline__ void ldmx4t(uint32_t* d, uint32_t addr) {
    asm volatile("ldmatrix.sync.aligned.m8n8.x4.trans.shared.b16 {%0,%1,%2,%3}, [%4];"
                 : "=r"(d[0]), "=r"(d[1]), "=r"(d[2]), "=r"(d[3]) : "r"(addr));
}
__device__ __forceinline__ void cpa16(uint32_t s, const void* g, int srcsz) {
    asm volatile("cp.async.cg.shared.global [%0], [%1], 16, %2;"
                 :: "r"(s), "l"(g), "r"(srcsz) : "memory");
}
__device__ __forceinline__ void cpa_commit() {
    asm volatile("cp.async.commit_group;" ::: "memory");
}
__device__ __forceinline__ void cpa_wait0() {
    asm volatile("cp.async.wait_group 0;" ::: "memory");
}

// ---------------- weight prep: fp32 -> single fp16 plane ----------------
__global__ void wsplit_f16_kernel(const float4* __restrict__ src, uint32_t* __restrict__ d,
                                  size_t n4) {
    size_t i = (size_t)blockIdx.x * blockDim.x + threadIdx.x;
    if (i < n4) {
        float4 f = src[i];
        __half2 h0 = __floats2half2_rn(f.x, f.y);
        __half2 h1 = __floats2half2_rn(f.z, f.w);
        d[2 * i] = *(uint32_t*)&h0;
        d[2 * i + 1] = *(uint32_t*)&h1;
    }
}

// ---------------- embedding + rmsnorm ----------------
__global__ void embed_rmsnorm_kernel(const int* __restrict__ ids,
                                     const float* __restrict__ wte,
                                     float* __restrict__ out) {
    __shared__ float red[32];
    int t = blockIdx.x;
    const float* row = wte + (size_t)ids[t] * HIDDEN;
    float v[4]; float ss = 0.0f;
    #pragma unroll
    for (int i = 0; i < 4; i++) { v[i] = row[threadIdx.x + i * 256]; ss += v[i] * v[i]; }
    ss = blockReduceSum(ss, red);
    float sc = rsqrtf(ss * (1.0f / HIDDEN) + EPSV);
    #pragma unroll
    for (int i = 0; i < 4; i++)
        out[(size_t)t * HIDDEN + threadIdx.x + i * 256] = v[i] * sc;
}

// ---------------- rmsnorm: fp32 in -> fp16 planes (SPLIT: hi+lo, else hi only) ----------------
template <int SPLIT>
__global__ void rmsnorm_f16_kernel(const float* __restrict__ in,
                                   __half* __restrict__ oh,
                                   __half* __restrict__ ol) {
    __shared__ float red[32];
    int t = blockIdx.x;
    const float* row = in + (size_t)t * HIDDEN;
    float v[4]; float ss = 0.0f;
    #pragma unroll
    for (int i = 0; i < 4; i++) {
        int idx = 2 * threadIdx.x + (i & 1) + (i >> 1) * 512;
        v[i] = row[idx];
        ss += v[i] * v[i];
    }
    ss = blockReduceSum(ss, red);
    float sc = rsqrtf(ss * (1.0f / HIDDEN) + EPSV);
    #pragma unroll
    for (int p = 0; p < 2; p++) {
        float a = v[2 * p] * sc, b = v[2 * p + 1] * sc;
        __half2 hh = __floats2half2_rn(a, b);
        size_t off = (size_t)t * HIDDEN + 2 * threadIdx.x + p * 512;
        *(uint32_t*)((char*)oh + off * 2) = *(uint32_t*)&hh;
        if (SPLIT) {
            __half2 ll = __floats2half2_rn(a - __half2float(hh.x),
                                           b - __half2float(hh.y));
            *(uint32_t*)((char*)ol + off * 2) = *(uint32_t*)&ll;
        }
    }
}

// ---------------- rope tables ----------------
__global__ void rope_init_kernel(float* __restrict__ ctab, float* __restrict__ stab) {
    int t = blockIdx.x, i = threadIdx.x;
    float invf = (float)pow(10000.0, -(double)(2 * i) / (double)HD);
    float ang = (float)t * invf;
    float s, c;
    sincosf(ang, &s, &c);
    ctab[t * 32 + i] = c;
    stab[t * 32 + i] = s;
}

// ---------------- per-token: q -> fp16 hi/lo; k -> fp16; v -> fp16. grid SEQ, 256 thr ----------------
__global__ void qknorm_rope_split_kernel(const float* __restrict__ qkv,
                                         const float* __restrict__ ctab,
                                         const float* __restrict__ stab,
                                         __half* __restrict__ oh,
                                         __half* __restrict__ ol) {
    int t = blockIdx.x, tid = threadIdx.x, lane = tid & 31, wid = tid >> 5;
    float cc = ctab[t * 32 + lane], ssn = stab[t * 32 + lane];
    #pragma unroll
    for (int task = wid; task < 32; task += 8) {
        int h = task & 15, wv = task >> 4;
        size_t base = (size_t)t * (3 * HIDDEN) + (size_t)wv * HIDDEN + h * HD;
        float2 x = *(const float2*)(qkv + base + 2 * lane);
        float ss = warpSum(x.x * x.x + x.y * x.y);
        float sc = rsqrtf(ss * (1.0f / HD) + EPSV);
        float x0 = x.x * sc, x1 = x.y * sc;
        float y0 = x1 * cc - x0 * ssn;
        float y1 = x1 * ssn + x0 * cc;
        __half2 hh = __floats2half2_rn(y0, y1);
        *(uint32_t*)((char*)oh + (base + 2 * lane) * 2) = *(uint32_t*)&hh;
        if (wv == 0) {
            __half2 ll = __floats2half2_rn(y0 - __half2float(hh.x),
                                           y1 - __half2float(hh.y));
            *(uint32_t*)((char*)ol + (base + 2 * lane) * 2) = *(uint32_t*)&ll;
        }
    }
    // v: single fp16 plane
    size_t vb = (size_t)t * (3 * HIDDEN) + 2 * HIDDEN;
    float4 v = *(const float4*)(qkv + vb + tid * 4);
    __half2 h0 = __floats2half2_rn(v.x, v.y);
    __half2 h1 = __floats2half2_rn(v.z, v.w);
    uint2 pk = make_uint2(*(uint32_t*)&h0, *(uint32_t*)&h1);
    *(uint2*)((char*)oh + (vb + tid * 4) * 2) = pk;
}

// ================= fused flash attention (fp16, 2-pass, cp.async pipelined) =================
#define FRS       72
#define FT_BYTES  (64 * FRS * 2)              // 9216
#define KV_STAGE  (2 * FT_BYTES)              // K + V single planes
#define FLASH_SMEM (2 * FT_BYTES + 2 * KV_STAGE)   // 55296

__global__ void __launch_bounds__(128, 2)
flash_attn_kernel(const __half* __restrict__ qh_g,
                  const __half* __restrict__ ql_g,
                  __half* __restrict__ outh) {
    extern __shared__ char fsm[];
    uint32_t sb = smem_u32(fsm);
    uint32_t uQh = sb, uQl = sb + FT_BYTES;

    int tid = threadIdx.x, lane = tid & 31, wid = tid >> 5;
    int h = blockIdx.y;
    int qt = (int)gridDim.x - 1 - (int)blockIdx.x;
    int bm = qt * 64;

    int r = tid >> 1, c0 = (tid & 1) * 32;
    uint32_t soff = (uint32_t)(r * (FRS * 2) + c0 * 2);

    {
        const char* gQh = (const char*)(qh_g + (size_t)(bm + r) * (3 * HIDDEN) + h * HD + c0);
        const char* gQl = (const char*)(ql_g + (size_t)(bm + r) * (3 * HIDDEN) + h * HD + c0);
        #pragma unroll
        for (int g = 0; g < 4; g++) {
            cpa16(uQh + soff + g * 16, gQh + g * 16, 16);
            cpa16(uQl + soff + g * 16, gQl + g * 16, 16);
        }
        const char* gK = (const char*)(qh_g + (size_t)r * (3 * HIDDEN) + HIDDEN + h * HD + c0);
        uint32_t st = sb + 2 * FT_BYTES;
        #pragma unroll
        for (int g = 0; g < 4; g++) {
            cpa16(st + soff + g * 16,            gK + g * 16, 16);
            cpa16(st + FT_BYTES + soff + g * 16, gK + HIDDEN * 2 + g * 16, 16);
        }
        cpa_commit();
    }

    uint32_t qh[4][4], ql[4][4];
    float o[8][4] = {};
    float m[2] = {-INFINITY, -INFINITY};
    float l[2] = {0.0f, 0.0f};

    for (int jt = 0; jt <= qt; jt++) {
        cpa_wait0();
        __syncthreads();

        if (jt == 0) {
            uint32_t qoff = (uint32_t)(((wid * 16 + (lane & 15)) * FRS + ((lane >> 4) & 1) * 8) * 2);
            #pragma unroll
            for (int ks = 0; ks < 4; ks++) {
                ldmx4(qh[ks], uQh + qoff + ks * 32);
                ldmx4(ql[ks], uQl + qoff + ks * 32);
            }
        }
        if (jt + 1 <= qt) {
            const char* gK = (const char*)(qh_g + (size_t)((jt + 1) * 64 + r) * (3 * HIDDEN) + HIDDEN + h * HD + c0);
            uint32_t st = sb + 2 * FT_BYTES + (uint32_t)((jt + 1) & 1) * KV_STAGE;
            #pragma unroll
            for (int g = 0; g < 4; g++) {
                cpa16(st + soff + g * 16,            gK + g * 16, 16);
                cpa16(st + FT_BYTES + soff + g * 16, gK + HIDDEN * 2 + g * 16, 16);
            }
            cpa_commit();
        }

        uint32_t stg = sb + 2 * FT_BYTES + (uint32_t)(jt & 1) * KV_STAGE;
        uint32_t uK = stg, uV = stg + FT_BYTES;

        float s[8][4] = {};
        uint32_t bbase = (uint32_t)(((((lane >> 4) & 1) * 8 + (lane & 7)) * FRS
                                     + ((lane >> 3) & 1) * 8) * 2);
        #pragma unroll
        for (int ks = 0; ks < 4; ks++) {
            #pragma unroll
            for (int nb = 0; nb < 4; nb++) {
                uint32_t kk[4];
                uint32_t bo = bbase + (uint32_t)(nb * 16 * FRS * 2) + (uint32_t)(ks * 32);
                ldmx4(kk, uK + bo);
                mma_f16(s[nb * 2],     qh[ks], kk + 0);
                mma_f16(s[nb * 2 + 1], qh[ks], kk + 2);
                mma_f16(s[nb * 2],     ql[ks], kk + 0);
                mma_f16(s[nb * 2 + 1], ql[ks], kk + 2);
            }
        }
        #pragma unroll
        for (int nt = 0; nt < 8; nt++)
            #pragma unroll
            for (int c = 0; c < 4; c++) s[nt][c] *= 0.125f;

        if (jt == qt) {
            int q0 = wid * 16 + (lane >> 2);
            int q1 = q0 + 8;
            #pragma unroll
            for (int nt = 0; nt < 8; nt++) {
                int j0 = nt * 8 + (lane & 3) * 2;
                if (j0     > q0) s[nt][0] = -INFINITY;
                if (j0 + 1 > q0) s[nt][1] = -INFINITY;
                if (j0     > q1) s[nt][2] = -INFINITY;
                if (j0 + 1 > q1) s[nt][3] = -INFINITY;
            }
        }

        #pragma unroll
        for (int hh = 0; hh < 2; hh++) {
            float rm = -INFINITY;
            #pragma unroll
            for (int nt = 0; nt < 8; nt++)
                rm = fmaxf(rm, fmaxf(s[nt][2 * hh], s[nt][2 * hh + 1]));
            rm = fmaxf(rm, __shfl_xor_sync(0xffffffffu, rm, 1));
            rm = fmaxf(rm, __shfl_xor_sync(0xffffffffu, rm, 2));
            float mnew = fmaxf(m[hh], rm);
            float corr = __expf(m[hh] - mnew);
            float rs = 0.0f;
            #pragma unroll
            for (int nt = 0; nt < 8; nt++) {
                float p0 = __expf(s[nt][2 * hh]     - mnew);
                float p1 = __expf(s[nt][2 * hh + 1] - mnew);
                s[nt][2 * hh] = p0; s[nt][2 * hh + 1] = p1;
                rs += p0 + p1;
            }
            rs += __shfl_xor_sync(0xffffffffu, rs, 1);
            rs += __shfl_xor_sync(0xffffffffu, rs, 2);
            l[hh] = l[hh] * corr + rs;
            m[hh] = mnew;
            #pragma unroll
            for (int dt = 0; dt < 8; dt++) {
                o[dt][2 * hh] *= corr; o[dt][2 * hh + 1] *= corr;
            }
        }

        #pragma unroll
        for (int jks = 0; jks < 4; jks++) {
            float* ce = s[2 * jks];
            float* co = s[2 * jks + 1];
            uint32_t pa[4], pb[4];
            {
                __half2 h0 = __floats2half2_rn(ce[0], ce[1]);
                __half2 h1 = __floats2half2_rn(ce[2], ce[3]);
                __half2 h2 = __floats2half2_rn(co[0], co[1]);
                __half2 h3 = __floats2half2_rn(co[2], co[3]);
                pa[0] = *(uint32_t*)&h0; pa[1] = *(uint32_t*)&h1;
                pa[2] = *(uint32_t*)&h2; pa[3] = *(uint32_t*)&h3;
                __half2 e0 = __floats2half2_rn(ce[0] - __half2float(h0.x),
                                               ce[1] - __half2float(h0.y));
                __half2 e1 = __floats2half2_rn(ce[2] - __half2float(h1.x),
                                               ce[3] - __half2float(h1.y));
                __half2 e2 = __floats2half2_rn(co[0] - __half2float(h2.x),
                                               co[1] - __half2float(h2.y));
                __half2 e3 = __floats2half2_rn(co[2] - __half2float(h3.x),
                                               co[3] - __half2float(h3.y));
                pb[0] = *(uint32_t*)&e0; pb[1] = *(uint32_t*)&e1;
                pb[2] = *(uint32_t*)&e2; pb[3] = *(uint32_t*)&e3;
            }
            uint32_t vbase = (uint32_t)(((jks * 16 + (lane & 15)) * FRS
                                         + ((lane >> 4) & 1) * 8) * 2);
            #pragma unroll
            for (int db = 0; db < 4; db++) {
                uint32_t vv[4];
                ldmx4t(vv, uV + vbase + (uint32_t)(db * 32));
                mma_f16(o[db * 2],     pa, vv + 0);
                mma_f16(o[db * 2 + 1], pa, vv + 2);
                mma_f16(o[db * 2],     pb, vv + 0);
                mma_f16(o[db * 2 + 1], pb, vv + 2);
            }
        }
    }

    // ---- finalize: single fp16 plane ----
    float inv0 = 1.0f / l[0], inv1 = 1.0f / l[1];
    int row0 = bm + wid * 16 + (lane >> 2);
    #pragma unroll
    for (int dt = 0; dt < 8; dt++) {
        int col = h * HD + dt * 8 + (lane & 3) * 2;
        __half2 hh0 = __floats2half2_rn(o[dt][0] * inv0, o[dt][1] * inv0);
        __half2 hh1 = __floats2half2_rn(o[dt][2] * inv1, o[dt][3] * inv1);
        *(uint32_t*)((char*)outh + ((size_t)row0 * HIDDEN + col) * 2) = *(uint32_t*)&hh0;
        *(uint32_t*)((char*)outh + ((size_t)(row0 + 8) * HIDDEN + col) * 2) = *(uint32_t*)&hh1;
    }
}

// ================= fp16 GEMM: C = A @ B^T; NP=2 -> A = Ah+Al (2-pass), NP=1 -> A = Ah =================
// EPI 0: C = v (fp32)   EPI 1: C = R + v (fp32)   EPI 2: Oh/Ol = f16split(relu(v)^2)
#define RS 40

template <int EPI, int BM, int NP>
__global__ void __launch_bounds__(256, 2)
gemm_f16_kernel(const __half* __restrict__ Ah, const __half* __restrict__ Al,
                const __half* __restrict__ Bh,
                float* __restrict__ C, const float* __restrict__ R,
                __half* __restrict__ Oh, __half* __restrict__ Ol,
                int M, int N, int K) {
    constexpr int MT = (BM == 128) ? 4 : 2;
    constexpr int ABY = BM * RS * 2;
    constexpr int BBY = 128 * RS * 2;
    constexpr int STG = NP * ABY + BBY;

    extern __shared__ char gsm[];
    int tid = threadIdx.x, lane = tid & 31, wid = tid >> 5;
    int wm = wid >> 2, wn = wid & 3;
    int bm = blockIdx.y * BM, bn = blockIdx.x * 128;

    uint32_t sb = smem_u32(gsm);

    int arow, acpa_n; uint32_t so_a; const char *gAh, *gAl;
    if (BM == 128) {
        arow = tid >> 1; int half = tid & 1; acpa_n = 2;
        so_a = (uint32_t)(arow * 80 + half * 32);
        gAh = (const char*)(Ah + (size_t)(bm + arow) * K + half * 16);
        gAl = (const char*)(Al + (size_t)(bm + arow) * K + half * 16);
    } else {
        arow = tid >> 2; int seg = tid & 3; acpa_n = 1;
        so_a = (uint32_t)(arow * 80 + seg * 16);
        gAh = (const char*)(Ah + (size_t)(bm + arow) * K + seg * 8);
        gAl = (const char*)(Al + (size_t)(bm + arow) * K + seg * 8);
    }
    int brow = tid >> 1, bhalf = tid & 1;
    int bgrow = bn + brow;
    bool bok = bgrow < N;
    int browc = bok ? bgrow : (N - 1);
    uint32_t so_b = (uint32_t)(brow * 80 + bhalf * 32);
    const char* gBh = (const char*)(Bh + (size_t)browc * K + bhalf * 16);
    int bsz = bok ? 16 : 0;

    uint32_t aoff = (uint32_t)(((wm * (MT * 16) + (lane & 15)) * RS + ((lane >> 4) & 1) * 8) * 2);
    uint32_t boff = (uint32_t)(((wn * 32 + ((lane >> 4) & 1) * 8 + (lane & 7)) * RS
                                + ((lane >> 3) & 1) * 8) * 2);

    float acc[MT][4][4] = {};
    int nCh = K >> 5;

    {
        uint32_t s0 = sb;
        #pragma unroll
        for (int g = 0; g < 2; g++) {
            if (g < acpa_n) {
                cpa16(s0 + so_a + g * 16, gAh + g * 16, 16);
                if (NP == 2) cpa16(s0 + ABY + so_a + g * 16, gAl + g * 16, 16);
            }
        }
        cpa16(s0 + NP * ABY + so_b,      gBh, bsz);
        cpa16(s0 + NP * ABY + so_b + 16, gBh + 16, bsz);
        cpa_commit();
    }

    for (int s = 0; s < nCh; s++) {
        cpa_wait0();
        __syncthreads();

        if (s + 1 < nCh) {
            uint32_t s1 = sb + (uint32_t)((s + 1) & 1) * STG;
            int kb = (s + 1) * 64;
            #pragma unroll
            for (int g = 0; g < 2; g++) {
                if (g < acpa_n) {
                    cpa16(s1 + so_a + g * 16, gAh + kb + g * 16, 16);
                    if (NP == 2) cpa16(s1 + ABY + so_a + g * 16, gAl + kb + g * 16, 16);
                }
            }
            cpa16(s1 + NP * ABY + so_b,      gBh + kb, bsz);
            cpa16(s1 + NP * ABY + so_b + 16, gBh + kb + 16, bsz);
            cpa_commit();
        }

        uint32_t st = sb + (uint32_t)(s & 1) * STG;
        uint32_t uAh = st, uAl = st + ABY, uB = st + NP * ABY;
        #pragma unroll
        for (int ks = 0; ks < 2; ks++) {
            uint32_t k2 = (uint32_t)(ks * 32);
            uint32_t aH[MT][4], bH[2][4];
            #pragma unroll
            for (int mt = 0; mt < MT; mt++) ldmx4(aH[mt], uAh + aoff + mt * (16 * RS * 2) + k2);
            #pragma unroll
            for (int np = 0; np < 2; np++) ldmx4(bH[np], uB + boff + np * (16 * RS * 2) + k2);
            #pragma unroll
            for (int mt = 0; mt < MT; mt++)
                #pragma unroll
                for (int nt = 0; nt < 4; nt++)
                    mma_f16(acc[mt][nt], aH[mt], &bH[nt >> 1][(nt & 1) * 2]);
            if (NP == 2) {
                uint32_t aL[MT][4];
                #pragma unroll
                for (int mt = 0; mt < MT; mt++) ldmx4(aL[mt], uAl + aoff + mt * (16 * RS * 2) + k2);
                #pragma unroll
                for (int mt = 0; mt < MT; mt++)
                    #pragma unroll
                    for (int nt = 0; nt < 4; nt++)
                        mma_f16(acc[mt][nt], aL[mt], &bH[nt >> 1][(nt & 1) * 2]);
            }
        }
    }

    #pragma unroll
    for (int mt = 0; mt < MT; mt++) {
        int rw = bm + wm * (MT * 16) + mt * 16 + (lane >> 2);
        #pragma unroll
        for (int nt = 0; nt < 4; nt++) {
            int col = bn + wn * 32 + nt * 8 + (lane & 3) * 2;
            if (col < N) {
                float* c = acc[mt][nt];
                float v0 = c[0], v1 = c[1], v2 = c[2], v3 = c[3];
                if (EPI == 1) {
                    float2 r0 = *(const float2*)(R + (size_t)rw * N + col);
                    float2 r1 = *(const float2*)(R + (size_t)(rw + 8) * N + col);
                    v0 += r0.x; v1 += r0.y; v2 += r1.x; v3 += r1.y;
                }
                if (EPI == 2) {
                    v0 = fmaxf(v0, 0.f); v0 *= v0;
                    v1 = fmaxf(v1, 0.f); v1 *= v1;
                    v2 = fmaxf(v2, 0.f); v2 *= v2;
                    v3 = fmaxf(v3, 0.f); v3 *= v3;
                    __half2 hh0 = __floats2half2_rn(v0, v1);
                    __half2 ll0 = __floats2half2_rn(v0 - __half2float(hh0.x),
                                                    v1 - __half2float(hh0.y));
                    __half2 hh1 = __floats2half2_rn(v2, v3);
                    __half2 ll1 = __floats2half2_rn(v2 - __half2float(hh1.x),
                                                    v3 - __half2float(hh1.y));
                    size_t o0 = (size_t)rw * N + col;
                    size_t o1 = (size_t)(rw + 8) * N + col;
                    *(uint32_t*)((char*)Oh + o0 * 2) = *(uint32_t*)&hh0;
                    *(uint32_t*)((char*)Ol + o0 * 2) = *(uint32_t*)&ll0;
                    *(uint32_t*)((char*)Oh + o1 * 2) = *(uint32_t*)&hh1;
                    *(uint32_t*)((char*)Ol + o1 * 2) = *(uint32_t*)&ll1;
                } else {
                    *(float2*)(C + (size_t)rw * N + col) = make_float2(v0, v1);
                    *(float2*)(C + (size_t)(rw + 8) * N + col) = make_float2(v2, v3);
                }
            }
        }
    }
}

#define GS_128_2 (2 * (2 * 128 * RS * 2 + 128 * RS * 2))   // 61440
#define GS_64_2  (2 * (2 * 64 * RS * 2 + 128 * RS * 2))    // 40960
#define GS_128_1 (2 * (128 * RS * 2 + 128 * RS * 2))       // 40960
#define GS_64_1  (2 * (64 * RS * 2 + 128 * RS * 2))        // 30720

// ---------------- host launcher ----------------
extern "C" void kernel_launch(void* const* d_in, const int* in_sizes, int n_in,
                              void* d_out, int out_size) {
    const int*   ids  = (const int*)d_in[0];
    const float* wte  = (const float*)d_in[1];
    const float* wqkv = (const float*)d_in[2];
    const float* wo   = (const float*)d_in[3];
    const float* w1   = (const float*)d_in[4];
    const float* w2   = (const float*)d_in[5];
    const float* lm   = (const float*)d_in[6];
    float* out = (float*)d_out;

    float *px, *pqkv, *pcos, *psin;
    __half *pwh, *psh, *psl, *phh, *phl, *pah, *pmh, *pml;
    cudaGetSymbolAddress((void**)&px,   g_x);
    cudaGetSymbolAddress((void**)&pqkv, g_qkv);
    cudaGetSymbolAddress((void**)&pcos, g_cos);
    cudaGetSymbolAddress((void**)&psin, g_sin);
    cudaGetSymbolAddress((void**)&pwh,  g_wh);
    cudaGetSymbolAddress((void**)&psh,  g_sh);
    cudaGetSymbolAddress((void**)&psl,  g_sl);
    cudaGetSymbolAddress((void**)&phh,  g_hh);
    cudaGetSymbolAddress((void**)&phl,  g_hl);
    cudaGetSymbolAddress((void**)&pah,  g_ah);
    cudaGetSymbolAddress((void**)&pmh,  g_mh);
    cudaGetSymbolAddress((void**)&pml,  g_ml);

    cudaFuncSetAttribute(flash_attn_kernel,
                         cudaFuncAttributeMaxDynamicSharedMemorySize, FLASH_SMEM);
    cudaFuncSetAttribute(gemm_f16_kernel<0, 128, 1>,
                         cudaFuncAttributeMaxDynamicSharedMemorySize, GS_128_1);
    cudaFuncSetAttribute(gemm_f16_kernel<1, 64, 1>,
                         cudaFuncAttributeMaxDynamicSharedMemorySize, GS_64_1);
    cudaFuncSetAttribute(gemm_f16_kernel<2, 128, 2>,
                         cudaFuncAttributeMaxDynamicSharedMemorySize, GS_128_2);
    cudaFuncSetAttribute(gemm_f16_kernel<1, 64, 2>,
                         cudaFuncAttributeMaxDynamicSharedMemorySize, GS_64_2);

    // ---- weight prep (all fp16 single plane) ----
    wsplit_f16_kernel<<<(unsigned)((25165824ULL / 4 + 255) / 256), 256>>>(
        (const float4*)wqkv, (uint32_t*)(pwh + OFF_WQKV), 25165824ULL / 4);
    wsplit_f16_kernel<<<(unsigned)((8388608ULL / 4 + 255) / 256), 256>>>(
        (const float4*)wo, (uint32_t*)(pwh + OFF_WO), 8388608ULL / 4);
    wsplit_f16_kernel<<<(unsigned)((33554432ULL / 4 + 255) / 256), 256>>>(
        (const float4*)w1, (uint32_t*)(pwh + OFF_W1), 33554432ULL / 4);
    wsplit_f16_kernel<<<(unsigned)((33554432ULL / 4 + 255) / 256), 256>>>(
        (const float4*)w2, (uint32_t*)(pwh + OFF_W2), 33554432ULL / 4);
    wsplit_f16_kernel<<<(unsigned)((51478528ULL / 4 + 255) / 256), 256>>>(
        (const float4*)lm, (uint32_t*)(pwh + OFF_LM), 51478528ULL / 4);

    rope_init_kernel<<<SEQ, 32>>>(pcos, psin);
    embed_rmsnorm_kernel<<<SEQ, 256>>>(ids, wte, px);

    for (int l = 0; l < NL; l++) {
        __half* wqkv_h = pwh + OFF_WQKV + (size_t)l * 3145728;
        __half* wo_h   = pwh + OFF_WO + (size_t)l * 1048576;
        __half* w1_h   = pwh + OFF_W1 + (size_t)l * 4194304;
        __half* w2_h   = pwh + OFF_W2 + (size_t)l * 4194304;

        // attention block: 1-pass qkv, 2-pass flash, 1-pass wo
        rmsnorm_f16_kernel<0><<<SEQ, 256>>>(px, phh, nullptr);
        gemm_f16_kernel<0, 128, 1><<<dim3(24, 16), 256, GS_128_1>>>(
            phh, nullptr, wqkv_h, pqkv, nullptr, nullptr, nullptr, SEQ, 3 * HIDDEN, HIDDEN);
        qknorm_rope_split_kernel<<<SEQ, 256>>>(pqkv, pcos, psin, psh, psl);
        flash_attn_kernel<<<dim3(SEQ / 64, NH), 128, FLASH_SMEM>>>(psh, psl, pah);
        gemm_f16_kernel<1, 64, 1><<<dim3(8, 32), 256, GS_64_1>>>(
            pah, nullptr, wo_h, px, px, nullptr, nullptr, SEQ, HIDDEN, HIDDEN);

        // FFN block: 2-pass w1, 2-pass w2
        rmsnorm_f16_kernel<1><<<SEQ, 256>>>(px, phh, phl);
        gemm_f16_kernel<2, 128, 2><<<dim3(32, 16), 256, GS_128_2>>>(
            phh, phl, w1_h, nullptr, nullptr, pmh, pml, SEQ, FFN, HIDDEN);
        gemm_f16_kernel<1, 64, 2><<<dim3(8, 32), 256, GS_64_2>>>(
            pmh, pml, w2_h, px, px, nullptr, nullptr, SEQ, HIDDEN, FFN);
    }

    // lm head: 1-pass
    rmsnorm_f16_kernel<0><<<SEQ, 256>>>(px, phh, nullptr);
    gemm_f16_kernel<0, 128, 1><<<dim3((VOCABSZ + 127) / 128, 16), 256, GS_128_1>>>(
        phh, nullptr, pwh + OFF_LM, out, nullptr, nullptr, nullptr, SEQ, VOCABSZ, HIDDEN);
}

// round 15
// speedup vs baseline: 4.4378x; 1.2434x over previous
#include <cuda_runtime.h>
#include <cuda_bf16.h>
#include <cuda_fp16.h>
#include <math.h>
#include <stdint.h>

#define SEQ     2048
#define HIDDEN  1024
#define NH      16
#define HD      64
#define NL      8
#define VOCABSZ 50272
#define FFN     4096
#define EPSV    1e-5f

#define OFF_WQKV 0ULL
#define OFF_WO   25165824ULL
#define OFF_W1   33554432ULL
#define OFF_W2   67108864ULL
#define OFF_LM   100663296ULL
#define W_TOTAL  152141824ULL

// ---------------- scratch ----------------
__device__ float g_x  [(size_t)SEQ * HIDDEN];
__device__ float g_qkv[(size_t)SEQ * 3 * HIDDEN];
__device__ float g_cos[(size_t)SEQ * (HD / 2)];
__device__ float g_sin[(size_t)SEQ * (HD / 2)];
__device__ __half g_wh[W_TOTAL];                    // all weights fp16
__device__ __half g_sh[(size_t)SEQ * 3 * HIDDEN];   // q, k, v (fp16)
__device__ __half g_hh[(size_t)SEQ * HIDDEN];       // normed activations (fp16)
__device__ __half g_ah[(size_t)SEQ * HIDDEN];       // attn out (fp16)
__device__ __half g_mh[(size_t)SEQ * FFN];          // ffn mid (fp16)

// ---------------- helpers ----------------
__device__ __forceinline__ uint32_t smem_u32(const void* p) {
    uint32_t a;
    asm("{ .reg .u64 t; cvta.to.shared.u64 t, %1; cvt.u32.u64 %0, t; }" : "=r"(a) : "l"(p));
    return a;
}
__device__ __forceinline__ float warpSum(float v) {
    #pragma unroll
    for (int o = 16; o; o >>= 1) v += __shfl_xor_sync(0xffffffffu, v, o);
    return v;
}
__device__ __forceinline__ float blockReduceSum(float v, float* red) {
    int lane = threadIdx.x & 31, w = threadIdx.x >> 5;
    v = warpSum(v);
    if (lane == 0) red[w] = v;
    __syncthreads();
    if (w == 0) {
        float r = (lane < (int)(blockDim.x >> 5)) ? red[lane] : 0.0f;
        r = warpSum(r);
        if (lane == 0) red[0] = r;
    }
    __syncthreads();
    float out = red[0];
    __syncthreads();
    return out;
}
__device__ __forceinline__ void mma_f16(float* c, const uint32_t* a, const uint32_t* b) {
    asm volatile(
        "mma.sync.aligned.m16n8k16.row.col.f32.f16.f16.f32 "
        "{%0,%1,%2,%3}, {%4,%5,%6,%7}, {%8,%9}, {%0,%1,%2,%3};"
        : "+f"(c[0]), "+f"(c[1]), "+f"(c[2]), "+f"(c[3])
        : "r"(a[0]), "r"(a[1]), "r"(a[2]), "r"(a[3]), "r"(b[0]), "r"(b[1]));
}
__device__ __forceinline__ void ldmx4(uint32_t* d, uint32_t addr) {
    asm volatile("ldmatrix.sync.aligned.m8n8.x4.shared.b16 {%0,%1,%2,%3}, [%4];"
                 : "=r"(d[0]), "=r"(d[1]), "=r"(d[2]), "=r"(d[3]) : "r"(addr));
}
__device__ __forceinline__ void ldmx4t(uint32_t* d, uint32_t addr) {
    asm volatile("ldmatrix.sync.aligned.m8n8.x4.trans.shared.b16 {%0,%1,%2,%3}, [%4];"
                 : "=r"(d[0]), "=r"(d[1]), "=r"(d[2]), "=r"(d[3]) : "r"(addr));
}
__device__ __forceinline__ void cpa16(uint32_t s, const void* g, int srcsz) {
    asm volatile("cp.async.cg.shared.global [%0], [%1], 16, %2;"
                 :: "r"(s), "l"(g), "r"(srcsz) : "memory");
}
__device__ __forceinline__ void cpa_commit() {
    asm volatile("cp.async.commit_group;" ::: "memory");
}
__device__ __forceinline__ void cpa_wait0() {
    asm volatile("cp.async.wait_group 0;" ::: "memory");
}

// ---------------- weight prep: fp32 -> fp16 ----------------
__global__ void wsplit_f16_kernel(const float4* __restrict__ src, uint32_t* __restrict__ d,
                                  size_t n4) {
    size_t i = (size_t)blockIdx.x * blockDim.x + threadIdx.x;
    if (i < n4) {
        float4 f = src[i];
        __half2 h0 = __floats2half2_rn(f.x, f.y);
        __half2 h1 = __floats2half2_rn(f.z, f.w);
        d[2 * i] = *(uint32_t*)&h0;
        d[2 * i + 1] = *(uint32_t*)&h1;
    }
}

// ---------------- embedding + rmsnorm ----------------
__global__ void embed_rmsnorm_kernel(const int* __restrict__ ids,
                                     const float* __restrict__ wte,
                                     float* __restrict__ out) {
    __shared__ float red[32];
    int t = blockIdx.x;
    const float* row = wte + (size_t)ids[t] * HIDDEN;
    float v[4]; float ss = 0.0f;
    #pragma unroll
    for (int i = 0; i < 4; i++) { v[i] = row[threadIdx.x + i * 256]; ss += v[i] * v[i]; }
    ss = blockReduceSum(ss, red);
    float sc = rsqrtf(ss * (1.0f / HIDDEN) + EPSV);
    #pragma unroll
    for (int i = 0; i < 4; i++)
        out[(size_t)t * HIDDEN + threadIdx.x + i * 256] = v[i] * sc;
}

// ---------------- rmsnorm: fp32 in -> fp16 plane ----------------
__global__ void rmsnorm_f16_kernel(const float* __restrict__ in,
                                   __half* __restrict__ oh) {
    __shared__ float red[32];
    int t = blockIdx.x;
    const float* row = in + (size_t)t * HIDDEN;
    float v[4]; float ss = 0.0f;
    #pragma unroll
    for (int i = 0; i < 4; i++) {
        int idx = 2 * threadIdx.x + (i & 1) + (i >> 1) * 512;
        v[i] = row[idx];
        ss += v[i] * v[i];
    }
    ss = blockReduceSum(ss, red);
    float sc = rsqrtf(ss * (1.0f / HIDDEN) + EPSV);
    #pragma unroll
    for (int p = 0; p < 2; p++) {
        __half2 hh = __floats2half2_rn(v[2 * p] * sc, v[2 * p + 1] * sc);
        size_t off = (size_t)t * HIDDEN + 2 * threadIdx.x + p * 512;
        *(uint32_t*)((char*)oh + off * 2) = *(uint32_t*)&hh;
    }
}

// ---------------- rope tables ----------------
__global__ void rope_init_kernel(float* __restrict__ ctab, float* __restrict__ stab) {
    int t = blockIdx.x, i = threadIdx.x;
    float invf = (float)pow(10000.0, -(double)(2 * i) / (double)HD);
    float ang = (float)t * invf;
    float s, c;
    sincosf(ang, &s, &c);
    ctab[t * 32 + i] = c;
    stab[t * 32 + i] = s;
}

// ---------------- per-token: q,k rmsnorm+rope -> fp16; v -> fp16. grid SEQ, 256 thr ----------------
__global__ void qknorm_rope_kernel(const float* __restrict__ qkv,
                                   const float* __restrict__ ctab,
                                   const float* __restrict__ stab,
                                   __half* __restrict__ oh) {
    int t = blockIdx.x, tid = threadIdx.x, lane = tid & 31, wid = tid >> 5;
    float cc = ctab[t * 32 + lane], ssn = stab[t * 32 + lane];
    #pragma unroll
    for (int task = wid; task < 32; task += 8) {
        int h = task & 15, wv = task >> 4;
        size_t base = (size_t)t * (3 * HIDDEN) + (size_t)wv * HIDDEN + h * HD;
        float2 x = *(const float2*)(qkv + base + 2 * lane);
        float ss = warpSum(x.x * x.x + x.y * x.y);
        float sc = rsqrtf(ss * (1.0f / HD) + EPSV);
        float x0 = x.x * sc, x1 = x.y * sc;
        float y0 = x1 * cc - x0 * ssn;
        float y1 = x1 * ssn + x0 * cc;
        __half2 hh = __floats2half2_rn(y0, y1);
        *(uint32_t*)((char*)oh + (base + 2 * lane) * 2) = *(uint32_t*)&hh;
    }
    // v: fp16
    size_t vb = (size_t)t * (3 * HIDDEN) + 2 * HIDDEN;
    float4 v = *(const float4*)(qkv + vb + tid * 4);
    __half2 h0 = __floats2half2_rn(v.x, v.y);
    __half2 h1 = __floats2half2_rn(v.z, v.w);
    *(uint2*)((char*)oh + (vb + tid * 4) * 2) = make_uint2(*(uint32_t*)&h0, *(uint32_t*)&h1);
}

// ================= fused flash attention (pure fp16, cp.async pipelined) =================
#define FRS       72
#define FT_BYTES  (64 * FRS * 2)              // 9216
#define KV_STAGE  (2 * FT_BYTES)
#define FLASH_SMEM (FT_BYTES + 2 * KV_STAGE)  // 46080

__global__ void __launch_bounds__(128, 2)
flash_attn_kernel(const __half* __restrict__ qkv_g, __half* __restrict__ outh) {
    extern __shared__ char fsm[];
    uint32_t sb = smem_u32(fsm);
    uint32_t uQ = sb;

    int tid = threadIdx.x, lane = tid & 31, wid = tid >> 5;
    int h = blockIdx.y;
    int qt = (int)gridDim.x - 1 - (int)blockIdx.x;
    int bm = qt * 64;

    int r = tid >> 1, c0 = (tid & 1) * 32;
    uint32_t soff = (uint32_t)(r * (FRS * 2) + c0 * 2);

    {
        const char* gQ = (const char*)(qkv_g + (size_t)(bm + r) * (3 * HIDDEN) + h * HD + c0);
        #pragma unroll
        for (int g = 0; g < 4; g++)
            cpa16(uQ + soff + g * 16, gQ + g * 16, 16);
        const char* gK = (const char*)(qkv_g + (size_t)r * (3 * HIDDEN) + HIDDEN + h * HD + c0);
        uint32_t st = sb + FT_BYTES;
        #pragma unroll
        for (int g = 0; g < 4; g++) {
            cpa16(st + soff + g * 16,            gK + g * 16, 16);
            cpa16(st + FT_BYTES + soff + g * 16, gK + HIDDEN * 2 + g * 16, 16);
        }
        cpa_commit();
    }

    uint32_t qh[4][4];
    float o[8][4] = {};
    float m[2] = {-INFINITY, -INFINITY};
    float l[2] = {0.0f, 0.0f};

    for (int jt = 0; jt <= qt; jt++) {
        cpa_wait0();
        __syncthreads();

        if (jt == 0) {
            uint32_t qoff = (uint32_t)(((wid * 16 + (lane & 15)) * FRS + ((lane >> 4) & 1) * 8) * 2);
            #pragma unroll
            for (int ks = 0; ks < 4; ks++)
                ldmx4(qh[ks], uQ + qoff + ks * 32);
        }
        if (jt + 1 <= qt) {
            const char* gK = (const char*)(qkv_g + (size_t)((jt + 1) * 64 + r) * (3 * HIDDEN) + HIDDEN + h * HD + c0);
            uint32_t st = sb + FT_BYTES + (uint32_t)((jt + 1) & 1) * KV_STAGE;
            #pragma unroll
            for (int g = 0; g < 4; g++) {
                cpa16(st + soff + g * 16,            gK + g * 16, 16);
                cpa16(st + FT_BYTES + soff + g * 16, gK + HIDDEN * 2 + g * 16, 16);
            }
            cpa_commit();
        }

        uint32_t stg = sb + FT_BYTES + (uint32_t)(jt & 1) * KV_STAGE;
        uint32_t uK = stg, uV = stg + FT_BYTES;

        // ---- scores = Q K^T ----
        float s[8][4] = {};
        uint32_t bbase = (uint32_t)(((((lane >> 4) & 1) * 8 + (lane & 7)) * FRS
                                     + ((lane >> 3) & 1) * 8) * 2);
        #pragma unroll
        for (int ks = 0; ks < 4; ks++) {
            #pragma unroll
            for (int nb = 0; nb < 4; nb++) {
                uint32_t kk[4];
                uint32_t bo = bbase + (uint32_t)(nb * 16 * FRS * 2) + (uint32_t)(ks * 32);
                ldmx4(kk, uK + bo);
                mma_f16(s[nb * 2],     qh[ks], kk + 0);
                mma_f16(s[nb * 2 + 1], qh[ks], kk + 2);
            }
        }
        #pragma unroll
        for (int nt = 0; nt < 8; nt++)
            #pragma unroll
            for (int c = 0; c < 4; c++) s[nt][c] *= 0.125f;

        if (jt == qt) {
            int q0 = wid * 16 + (lane >> 2);
            int q1 = q0 + 8;
            #pragma unroll
            for (int nt = 0; nt < 8; nt++) {
                int j0 = nt * 8 + (lane & 3) * 2;
                if (j0     > q0) s[nt][0] = -INFINITY;
                if (j0 + 1 > q0) s[nt][1] = -INFINITY;
                if (j0     > q1) s[nt][2] = -INFINITY;
                if (j0 + 1 > q1) s[nt][3] = -INFINITY;
            }
        }

        #pragma unroll
        for (int hh = 0; hh < 2; hh++) {
            float rm = -INFINITY;
            #pragma unroll
            for (int nt = 0; nt < 8; nt++)
                rm = fmaxf(rm, fmaxf(s[nt][2 * hh], s[nt][2 * hh + 1]));
            rm = fmaxf(rm, __shfl_xor_sync(0xffffffffu, rm, 1));
            rm = fmaxf(rm, __shfl_xor_sync(0xffffffffu, rm, 2));
            float mnew = fmaxf(m[hh], rm);
            float corr = __expf(m[hh] - mnew);
            float rs = 0.0f;
            #pragma unroll
            for (int nt = 0; nt < 8; nt++) {
                float p0 = __expf(s[nt][2 * hh]     - mnew);
                float p1 = __expf(s[nt][2 * hh + 1] - mnew);
                s[nt][2 * hh] = p0; s[nt][2 * hh + 1] = p1;
                rs += p0 + p1;
            }
            rs += __shfl_xor_sync(0xffffffffu, rs, 1);
            rs += __shfl_xor_sync(0xffffffffu, rs, 2);
            l[hh] = l[hh] * corr + rs;
            m[hh] = mnew;
            #pragma unroll
            for (int dt = 0; dt < 8; dt++) {
                o[dt][2 * hh] *= corr; o[dt][2 * hh + 1] *= corr;
            }
        }

        // ---- O += P V ----
        #pragma unroll
        for (int jks = 0; jks < 4; jks++) {
            float* ce = s[2 * jks];
            float* co = s[2 * jks + 1];
            uint32_t pa[4];
            {
                __half2 h0 = __floats2half2_rn(ce[0], ce[1]);
                __half2 h1 = __floats2half2_rn(ce[2], ce[3]);
                __half2 h2 = __floats2half2_rn(co[0], co[1]);
                __half2 h3 = __floats2half2_rn(co[2], co[3]);
                pa[0] = *(uint32_t*)&h0; pa[1] = *(uint32_t*)&h1;
                pa[2] = *(uint32_t*)&h2; pa[3] = *(uint32_t*)&h3;
            }
            uint32_t vbase = (uint32_t)(((jks * 16 + (lane & 15)) * FRS
                                         + ((lane >> 4) & 1) * 8) * 2);
            #pragma unroll
            for (int db = 0; db < 4; db++) {
                uint32_t vv[4];
                ldmx4t(vv, uV + vbase + (uint32_t)(db * 32));
                mma_f16(o[db * 2],     pa, vv + 0);
                mma_f16(o[db * 2 + 1], pa, vv + 2);
            }
        }
    }

    float inv0 = 1.0f / l[0], inv1 = 1.0f / l[1];
    int row0 = bm + wid * 16 + (lane >> 2);
    #pragma unroll
    for (int dt = 0; dt < 8; dt++) {
        int col = h * HD + dt * 8 + (lane & 3) * 2;
        __half2 hh0 = __floats2half2_rn(o[dt][0] * inv0, o[dt][1] * inv0);
        __half2 hh1 = __floats2half2_rn(o[dt][2] * inv1, o[dt][3] * inv1);
        *(uint32_t*)((char*)outh + ((size_t)row0 * HIDDEN + col) * 2) = *(uint32_t*)&hh0;
        *(uint32_t*)((char*)outh + ((size_t)(row0 + 8) * HIDDEN + col) * 2) = *(uint32_t*)&hh1;
    }
}

// ================= fp16 1-pass GEMM: C = A @ B^T =================
// EPI 0: C = v (fp32)   EPI 1: C = R + v (fp32)   EPI 2: Oh = f16(relu(v)^2)
#define RS 40

template <int EPI, int BM>
__global__ void __launch_bounds__(256, 2)
gemm_f16_kernel(const __half* __restrict__ Ah, const __half* __restrict__ Bh,
                float* __restrict__ C, const float* __restrict__ R,
                __half* __restrict__ Oh,
                int M, int N, int K) {
    constexpr int MT = (BM == 128) ? 4 : 2;
    constexpr int ABY = BM * RS * 2;
    constexpr int BBY = 128 * RS * 2;
    constexpr int STG = ABY + BBY;

    extern __shared__ char gsm[];
    int tid = threadIdx.x, lane = tid & 31, wid = tid >> 5;
    int wm = wid >> 2, wn = wid & 3;
    int bm = blockIdx.y * BM, bn = blockIdx.x * 128;

    uint32_t sb = smem_u32(gsm);

    int arow, acpa_n; uint32_t so_a; const char* gAh;
    if (BM == 128) {
        arow = tid >> 1; int half = tid & 1; acpa_n = 2;
        so_a = (uint32_t)(arow * 80 + half * 32);
        gAh = (const char*)(Ah + (size_t)(bm + arow) * K + half * 16);
    } else {
        arow = tid >> 2; int seg = tid & 3; acpa_n = 1;
        so_a = (uint32_t)(arow * 80 + seg * 16);
        gAh = (const char*)(Ah + (size_t)(bm + arow) * K + seg * 8);
    }
    int brow = tid >> 1, bhalf = tid & 1;
    int bgrow = bn + brow;
    bool bok = bgrow < N;
    int browc = bok ? bgrow : (N - 1);
    uint32_t so_b = (uint32_t)(brow * 80 + bhalf * 32);
    const char* gBh = (const char*)(Bh + (size_t)browc * K + bhalf * 16);
    int bsz = bok ? 16 : 0;

    uint32_t aoff = (uint32_t)(((wm * (MT * 16) + (lane & 15)) * RS + ((lane >> 4) & 1) * 8) * 2);
    uint32_t boff = (uint32_t)(((wn * 32 + ((lane >> 4) & 1) * 8 + (lane & 7)) * RS
                                + ((lane >> 3) & 1) * 8) * 2);

    float acc[MT][4][4] = {};
    int nCh = K >> 5;

    {
        uint32_t s0 = sb;
        #pragma unroll
        for (int g = 0; g < 2; g++)
            if (g < acpa_n) cpa16(s0 + so_a + g * 16, gAh + g * 16, 16);
        cpa16(s0 + ABY + so_b,      gBh, bsz);
        cpa16(s0 + ABY + so_b + 16, gBh + 16, bsz);
        cpa_commit();
    }

    for (int s = 0; s < nCh; s++) {
        cpa_wait0();
        __syncthreads();

        if (s + 1 < nCh) {
            uint32_t s1 = sb + (uint32_t)((s + 1) & 1) * STG;
            int kb = (s + 1) * 64;
            #pragma unroll
            for (int g = 0; g < 2; g++)
                if (g < acpa_n) cpa16(s1 + so_a + g * 16, gAh + kb + g * 16, 16);
            cpa16(s1 + ABY + so_b,      gBh + kb, bsz);
            cpa16(s1 + ABY + so_b + 16, gBh + kb + 16, bsz);
            cpa_commit();
        }

        uint32_t st = sb + (uint32_t)(s & 1) * STG;
        uint32_t uAh = st, uB = st + ABY;
        #pragma unroll
        for (int ks = 0; ks < 2; ks++) {
            uint32_t k2 = (uint32_t)(ks * 32);
            uint32_t aH[MT][4], bH[2][4];
            #pragma unroll
            for (int mt = 0; mt < MT; mt++) ldmx4(aH[mt], uAh + aoff + mt * (16 * RS * 2) + k2);
            #pragma unroll
            for (int np = 0; np < 2; np++) ldmx4(bH[np], uB + boff + np * (16 * RS * 2) + k2);
            #pragma unroll
            for (int mt = 0; mt < MT; mt++)
                #pragma unroll
                for (int nt = 0; nt < 4; nt++)
                    mma_f16(acc[mt][nt], aH[mt], &bH[nt >> 1][(nt & 1) * 2]);
        }
    }

    #pragma unroll
    for (int mt = 0; mt < MT; mt++) {
        int rw = bm + wm * (MT * 16) + mt * 16 + (lane >> 2);
        #pragma unroll
        for (int nt = 0; nt < 4; nt++) {
            int col = bn + wn * 32 + nt * 8 + (lane & 3) * 2;
            if (col < N) {
                float* c = acc[mt][nt];
                float v0 = c[0], v1 = c[1], v2 = c[2], v3 = c[3];
                if (EPI == 1) {
                    float2 r0 = *(const float2*)(R + (size_t)rw * N + col);
                    float2 r1 = *(const float2*)(R + (size_t)(rw + 8) * N + col);
                    v0 += r0.x; v1 += r0.y; v2 += r1.x; v3 += r1.y;
                }
                if (EPI == 2) {
                    v0 = fmaxf(v0, 0.f); v0 *= v0;
                    v1 = fmaxf(v1, 0.f); v1 *= v1;
                    v2 = fmaxf(v2, 0.f); v2 *= v2;
                    v3 = fmaxf(v3, 0.f); v3 *= v3;
                    __half2 hh0 = __floats2half2_rn(v0, v1);
                    __half2 hh1 = __floats2half2_rn(v2, v3);
                    *(uint32_t*)((char*)Oh + ((size_t)rw * N + col) * 2) = *(uint32_t*)&hh0;
                    *(uint32_t*)((char*)Oh + ((size_t)(rw + 8) * N + col) * 2) = *(uint32_t*)&hh1;
                } else {
                    *(float2*)(C + (size_t)rw * N + col) = make_float2(v0, v1);
                    *(float2*)(C + (size_t)(rw + 8) * N + col) = make_float2(v2, v3);
                }
            }
        }
    }
}

#define GS_128 (2 * (128 * RS * 2 + 128 * RS * 2))   // 40960
#define GS_64  (2 * (64 * RS * 2 + 128 * RS * 2))    // 30720

// ---------------- host launcher ----------------
extern "C" void kernel_launch(void* const* d_in, const int* in_sizes, int n_in,
                              void* d_out, int out_size) {
    const int*   ids  = (const int*)d_in[0];
    const float* wte  = (const float*)d_in[1];
    const float* wqkv = (const float*)d_in[2];
    const float* wo   = (const float*)d_in[3];
    const float* w1   = (const float*)d_in[4];
    const float* w2   = (const float*)d_in[5];
    const float* lm   = (const float*)d_in[6];
    float* out = (float*)d_out;

    float *px, *pqkv, *pcos, *psin;
    __half *pwh, *psh, *phh, *pah, *pmh;
    cudaGetSymbolAddress((void**)&px,   g_x);
    cudaGetSymbolAddress((void**)&pqkv, g_qkv);
    cudaGetSymbolAddress((void**)&pcos, g_cos);
    cudaGetSymbolAddress((void**)&psin, g_sin);
    cudaGetSymbolAddress((void**)&pwh,  g_wh);
    cudaGetSymbolAddress((void**)&psh,  g_sh);
    cudaGetSymbolAddress((void**)&phh,  g_hh);
    cudaGetSymbolAddress((void**)&pah,  g_ah);
    cudaGetSymbolAddress((void**)&pmh,  g_mh);

    cudaFuncSetAttribute(flash_attn_kernel,
                         cudaFuncAttributeMaxDynamicSharedMemorySize, FLASH_SMEM);
    cudaFuncSetAttribute(gemm_f16_kernel<0, 128>,
                         cudaFuncAttributeMaxDynamicSharedMemorySize, GS_128);
    cudaFuncSetAttribute(gemm_f16_kernel<2, 128>,
                         cudaFuncAttributeMaxDynamicSharedMemorySize, GS_128);
    cudaFuncSetAttribute(gemm_f16_kernel<1, 64>,
                         cudaFuncAttributeMaxDynamicSharedMemorySize, GS_64);

    // ---- weight prep ----
    wsplit_f16_kernel<<<(unsigned)((25165824ULL / 4 + 255) / 256), 256>>>(
        (const float4*)wqkv, (uint32_t*)(pwh + OFF_WQKV), 25165824ULL / 4);
    wsplit_f16_kernel<<<(unsigned)((8388608ULL / 4 + 255) / 256), 256>>>(
        (const float4*)wo, (uint32_t*)(pwh + OFF_WO), 8388608ULL / 4);
    wsplit_f16_kernel<<<(unsigned)((33554432ULL / 4 + 255) / 256), 256>>>(
        (const float4*)w1, (uint32_t*)(pwh + OFF_W1), 33554432ULL / 4);
    wsplit_f16_kernel<<<(unsigned)((33554432ULL / 4 + 255) / 256), 256>>>(
        (const float4*)w2, (uint32_t*)(pwh + OFF_W2), 33554432ULL / 4);
    wsplit_f16_kernel<<<(unsigned)((51478528ULL / 4 + 255) / 256), 256>>>(
        (const float4*)lm, (uint32_t*)(pwh + OFF_LM), 51478528ULL / 4);

    rope_init_kernel<<<SEQ, 32>>>(pcos, psin);
    embed_rmsnorm_kernel<<<SEQ, 256>>>(ids, wte, px);

    for (int l = 0; l < NL; l++) {
        __half* wqkv_h = pwh + OFF_WQKV + (size_t)l * 3145728;
        __half* wo_h   = pwh + OFF_WO + (size_t)l * 1048576;
        __half* w1_h   = pwh + OFF_W1 + (size_t)l * 4194304;
        __half* w2_h   = pwh + OFF_W2 + (size_t)l * 4194304;

        rmsnorm_f16_kernel<<<SEQ, 256>>>(px, phh);
        gemm_f16_kernel<0, 128><<<dim3(24, 16), 256, GS_128>>>(
            phh, wqkv_h, pqkv, nullptr, nullptr, SEQ, 3 * HIDDEN, HIDDEN);
        qknorm_rope_kernel<<<SEQ, 256>>>(pqkv, pcos, psin, psh);
        flash_attn_kernel<<<dim3(SEQ / 64, NH), 128, FLASH_SMEM>>>(psh, pah);
        gemm_f16_kernel<1, 64><<<dim3(8, 32), 256, GS_64>>>(
            pah, wo_h, px, px, nullptr, SEQ, HIDDEN, HIDDEN);

        rmsnorm_f16_kernel<<<SEQ, 256>>>(px, phh);
        gemm_f16_kernel<2, 128><<<dim3(32, 16), 256, GS_128>>>(
            phh, w1_h, nullptr, nullptr, pmh, SEQ, FFN, HIDDEN);
        gemm_f16_kernel<1, 64><<<dim3(8, 32), 256, GS_64>>>(
            pmh, w2_h, px, px, nullptr, SEQ, HIDDEN, FFN);
    }

    rmsnorm_f16_kernel<<<SEQ, 256>>>(px, phh);
    gemm_f16_kernel<0, 128><<<dim3((VOCABSZ + 127) / 128, 16), 256, GS_128>>>(
        phh, pwh + OFF_LM, out, nullptr, nullptr, SEQ, VOCABSZ, HIDDEN);
}